// round 7
// baseline (speedup 1.0000x reference)
#include <cuda_runtime.h>
#include <cuda_fp16.h>
#include <math.h>
#include <stdint.h>

// Problem constants
#define B_  8
#define T_  512
#define D_  512
#define H_  8
#define FF_ 2048
#define L_  6
#define CS_ 16
#define LC_ 4
#define DK_ 64
#define NCHUNK_ (T_ / CS_)          // 32
#define WMAX_ ((LC_ + 1) * CS_)     // 80
#define QKVN_ (3 * D_)              // 1536
#define PALLN_ (L_ * D_)            // 3072

// ---------------- scratch (device globals; no allocation) ----------------
__device__ float  g_x   [B_*T_*D_];
__device__ float  g_qkv [B_*T_*QKVN_];
__device__ float  g_o   [B_*T_*D_];
__device__ float  g_ff  [B_*T_*FF_];
__device__ float  g_pall[T_*PALLN_];
__device__ float  g_bqkv[L_*QKVN_];
__device__ float2 g_st  [B_*T_];

// transposed + split weights: Wt[n][k]
__device__ __half g_wqkvh[L_*QKVN_*D_], g_wqkvl[L_*QKVN_*D_];
__device__ __half g_woh[L_*D_*D_],  g_wol[L_*D_*D_];
__device__ __half g_wph[L_*D_*D_],  g_wpl[L_*D_*D_];
__device__ __half g_w1h[L_*D_*FF_], g_w1l[L_*D_*FF_];
__device__ __half g_w2h[L_*FF_*D_], g_w2l[L_*FF_*D_];

// ---------------- PTX helpers (family-portable: sm_80+ ISA only) ----------
__device__ __forceinline__ uint32_t s2u(const void* p) {
    uint32_t a;
    asm("{ .reg .u64 t; cvta.to.shared.u64 t, %1; cvt.u32.u64 %0, t; }" : "=r"(a) : "l"(p));
    return a;
}

#define CPA16(sa, g) \
    asm volatile("cp.async.cg.shared.global [%0], [%1], 16;" :: "r"(sa), "l"(g) : "memory")
#define CPCOMMIT() asm volatile("cp.async.commit_group;" ::: "memory")
#define CPWAIT(n)  asm volatile("cp.async.wait_group %0;" :: "n"(n) : "memory")

#define LDSM4(d0, d1, d2, d3, a) \
    asm volatile("ldmatrix.sync.aligned.m8n8.x4.shared.b16 {%0,%1,%2,%3}, [%4];" \
        : "=r"(d0), "=r"(d1), "=r"(d2), "=r"(d3) : "r"(a))

#define MMA16816(c, a, b0, b1) \
    asm volatile("mma.sync.aligned.m16n8k16.row.col.f32.f16.f16.f32 " \
        "{%0,%1,%2,%3}, {%4,%5,%6,%7}, {%8,%9}, {%0,%1,%2,%3};" \
        : "+f"((c)[0]), "+f"((c)[1]), "+f"((c)[2]), "+f"((c)[3]) \
        : "r"((a)[0]), "r"((a)[1]), "r"((a)[2]), "r"((a)[3]), "r"(b0), "r"(b1))

__device__ __forceinline__ void split_h(float v, __half& hi, __half& lo) {
    hi = __float2half_rn(v);
    lo = __float2half_rn(v - __half2float(hi));
}
__device__ __forceinline__ uint32_t pack2(__half a, __half b) {
    __half2 t = __halves2half2(a, b);
    return *reinterpret_cast<uint32_t*>(&t);
}
__device__ __forceinline__ float4 ld4h(const __half* p) {
    uint2 u = *(const uint2*)p;
    __half2 a = *reinterpret_cast<__half2*>(&u.x);
    __half2 b = *reinterpret_cast<__half2*>(&u.y);
    float2 fa = __half22float2(a), fb = __half22float2(b);
    return make_float4(fa.x, fa.y, fb.x, fb.y);
}
__device__ __forceinline__ float dot4(float4 a, float4 b) {
    return a.x * b.x + a.y * b.y + a.z * b.z + a.w * b.w;
}

// ---------------- elementwise scale: x = xs * sqrt(D) ----------------
__global__ void scale_kernel(const float* __restrict__ xs, float s) {
    int i = blockIdx.x * blockDim.x + threadIdx.x;
    g_x[i] = xs[i] * s;
}

// ---------------- bias concat for fused QKV ----------------
__global__ void bcat_kernel(const float* __restrict__ bq, const float* __restrict__ bk,
                            const float* __restrict__ bv) {
    int i = blockIdx.x * blockDim.x + threadIdx.x;   // L*1536
    int l = i / QKVN_, c = i % QKVN_;
    float v = (c < D_) ? bq[l * D_ + c]
            : (c < 2 * D_) ? bk[l * D_ + c - D_]
            : bv[l * D_ + c - 2 * D_];
    g_bqkv[i] = v;
}

// ---------------- merged QKV weight transpose+split ----------------
// grid (16, 16, 3*L): z -> which (q/k/v) and layer
__global__ void wtransqkv_kernel(const float* __restrict__ Wq,
                                 const float* __restrict__ Wk,
                                 const float* __restrict__ Wv,
                                 __half* __restrict__ Th, __half* __restrict__ Tl) {
    __shared__ float sm[32][33];
    int z = blockIdx.z;
    int which = z / L_, l = z % L_;
    const size_t DD = (size_t)D_ * D_;
    const float* Wl = (which == 0 ? Wq : which == 1 ? Wk : Wv) + (size_t)l * DD;
    size_t dOff = (size_t)l * QKVN_ * D_ + (size_t)which * DD;
    __half* Thl = Th + dOff;
    __half* Tll = Tl + dOff;
    int n0 = blockIdx.x * 32, k0 = blockIdx.y * 32;
    int tx = threadIdx.x, ty = threadIdx.y;
    #pragma unroll
    for (int j = 0; j < 4; j++)
        sm[ty + j * 8][tx] = Wl[(size_t)(k0 + ty + j * 8) * D_ + n0 + tx];
    __syncthreads();
    #pragma unroll
    for (int j = 0; j < 4; j++) {
        int n = ty + j * 8;
        float v = sm[tx][n];
        __half h, l2;
        split_h(v, h, l2);
        size_t o = (size_t)(n0 + n) * D_ + k0 + tx;
        Thl[o] = h; Tll[o] = l2;
    }
}

// ---------------- generic weight transpose + split ----------------
__global__ void wtrans_kernel(const float* __restrict__ W,
                              __half* __restrict__ Th, __half* __restrict__ Tl,
                              int K, int N, size_t srcLS, size_t dstLS) {
    __shared__ float sm[32][33];
    const float* Wl = W + (size_t)blockIdx.z * srcLS;
    __half* Thl = Th + (size_t)blockIdx.z * dstLS;
    __half* Tll = Tl + (size_t)blockIdx.z * dstLS;
    int n0 = blockIdx.x * 32, k0 = blockIdx.y * 32;
    int tx = threadIdx.x, ty = threadIdx.y;
    #pragma unroll
    for (int j = 0; j < 4; j++)
        sm[ty + j * 8][tx] = Wl[(size_t)(k0 + ty + j * 8) * N + n0 + tx];
    __syncthreads();
    #pragma unroll
    for (int j = 0; j < 4; j++) {
        int n = ty + j * 8;
        float v = sm[tx][n];
        __half h, l;
        split_h(v, h, l);
        size_t o = (size_t)(n0 + n) * K + k0 + tx;
        Thl[o] = h; Tll[o] = l;
    }
}

// ---------------- LayerNorm stats / final LN ----------------
__device__ __forceinline__ void ln_stats(const float* x, int tid, float& v0, float& v1,
                                         float& mean, float& inv, float* sh_s, float* sh_ss) {
    v0 = x[tid]; v1 = x[tid + 256];
    float s = v0 + v1, ss = v0 * v0 + v1 * v1;
    int lane = tid & 31, warp = tid >> 5;
    #pragma unroll
    for (int off = 16; off; off >>= 1) {
        s  += __shfl_xor_sync(0xffffffffu, s,  off);
        ss += __shfl_xor_sync(0xffffffffu, ss, off);
    }
    if (lane == 0) { sh_s[warp] = s; sh_ss[warp] = ss; }
    __syncthreads();
    if (warp == 0) {
        float a = (lane < 8) ? sh_s[lane]  : 0.0f;
        float b = (lane < 8) ? sh_ss[lane] : 0.0f;
        #pragma unroll
        for (int off = 4; off; off >>= 1) {
            a += __shfl_xor_sync(0xffffffffu, a, off);
            b += __shfl_xor_sync(0xffffffffu, b, off);
        }
        if (lane == 0) { sh_s[0] = a; sh_ss[0] = b; }
    }
    __syncthreads();
    mean = sh_s[0] * (1.0f / D_);
    float var = sh_ss[0] * (1.0f / D_) - mean * mean;
    inv = rsqrtf(var + 1e-5f);
}

__global__ void lnstats_kernel(const float* __restrict__ in, float2* __restrict__ st) {
    __shared__ float sh_s[8], sh_ss[8];
    int row = blockIdx.x, tid = threadIdx.x;
    float v0, v1, mean, inv;
    ln_stats(in + (size_t)row * D_, tid, v0, v1, mean, inv, sh_s, sh_ss);
    if (tid == 0) st[row] = make_float2(mean, inv);
}

__global__ void ln_kernel(const float* __restrict__ in, float* __restrict__ out,
                          const float* __restrict__ gam, const float* __restrict__ bet) {
    __shared__ float sh_s[8], sh_ss[8];
    int row = blockIdx.x, tid = threadIdx.x;
    const float* x = in + (size_t)row * D_;
    float v0, v1, mean, inv;
    ln_stats(x, tid, v0, v1, mean, inv, sh_s, sh_ss);
    float* y = out + (size_t)row * D_;
    y[tid]       = (v0 - mean) * inv * gam[tid]       + bet[tid];
    y[tid + 256] = (v1 - mean) * inv * gam[tid + 256] + bet[tid + 256];
}

// ---------------- HMMA fp16x3 GEMM, fp32-A, fused LN, templated BM ---------
// BM in {128, 64}; BN = 128; BK = 32. 8 warps: 2 warp-rows x 4 warp-cols,
// warp tile (BM/2) x 32. 2-stage pipeline, 2 CTAs/SM.
template<int BM>
__global__ void __launch_bounds__(256, 2)
gemm_f32a(const float* __restrict__ A, const float2* __restrict__ stats,
          const float* __restrict__ gam, const float* __restrict__ bet,
          const __half* __restrict__ Bh, const __half* __restrict__ Bl,
          const float* __restrict__ bias, const float* __restrict__ res,
          float* __restrict__ outF, int N, int K, int relu) {
    constexpr int MI   = BM / 32;            // m-frags per warp (4 or 2)
    constexpr int NA   = BM / 64;            // loader iterations (2 or 1)
    constexpr int ABYT = BM * 64;            // bytes of one A array (hi or lo)
    constexpr int STGB = BM * 128 + 16384;   // stage bytes
    extern __shared__ char smem[];
    uint32_t sb = s2u(smem);
    int tid = threadIdx.x, lane = tid & 31, wid = tid >> 5;
    int wm = wid >> 2, wn = wid & 3;
    int rowBase = blockIdx.y * BM, colBase = blockIdx.x * 128;
    int sub = lane & 7, grp = lane >> 3;

    float acc[MI][4][4];
    #pragma unroll
    for (int i = 0; i < MI; i++)
        #pragma unroll
        for (int j = 0; j < 4; j++)
            #pragma unroll
            for (int c = 0; c < 4; c++) acc[i][j][c] = 0.0f;

    const int NC = K >> 5;

    float aR[NA][8];
    float2 stR[NA];
    #pragma unroll
    for (int i = 0; i < NA; i++) {
        int id = tid + (i << 8);
        int row = id >> 2;
        stR[i] = stats ? stats[rowBase + row] : make_float2(0.0f, 1.0f);
    }

    auto ldgA = [&](int c) {
        int k0 = c << 5;
        #pragma unroll
        for (int i = 0; i < NA; i++) {
            int id = tid + (i << 8);
            int row = id >> 2, ch = id & 3;
            const float* g = A + (size_t)(rowBase + row) * K + k0 + ch * 8;
            float4 u = *(const float4*)g;
            float4 v = *(const float4*)(g + 4);
            aR[i][0] = u.x; aR[i][1] = u.y; aR[i][2] = u.z; aR[i][3] = u.w;
            aR[i][4] = v.x; aR[i][5] = v.y; aR[i][6] = v.z; aR[i][7] = v.w;
        }
    };

    auto stsA = [&](int c, int buf) {
        int k0 = c << 5;
        #pragma unroll
        for (int i = 0; i < NA; i++) {
            int id = tid + (i << 8);
            int row = id >> 2, ch = id & 3;
            float y[8];
            if (gam) {
                float mean = stR[i].x, inv = stR[i].y;
                const float* gg = gam + k0 + ch * 8;
                const float* bb = bet + k0 + ch * 8;
                float4 g0 = *(const float4*)gg, g1 = *(const float4*)(gg + 4);
                float4 b0 = *(const float4*)bb, b1 = *(const float4*)(bb + 4);
                y[0] = (aR[i][0] - mean) * inv * g0.x + b0.x;
                y[1] = (aR[i][1] - mean) * inv * g0.y + b0.y;
                y[2] = (aR[i][2] - mean) * inv * g0.z + b0.z;
                y[3] = (aR[i][3] - mean) * inv * g0.w + b0.w;
                y[4] = (aR[i][4] - mean) * inv * g1.x + b1.x;
                y[5] = (aR[i][5] - mean) * inv * g1.y + b1.y;
                y[6] = (aR[i][6] - mean) * inv * g1.z + b1.z;
                y[7] = (aR[i][7] - mean) * inv * g1.w + b1.w;
            } else {
                #pragma unroll
                for (int j = 0; j < 8; j++) y[j] = aR[i][j];
            }
            __half h[8], l[8];
            #pragma unroll
            for (int j = 0; j < 8; j++) split_h(y[j], h[j], l[j]);
            int phys = ch ^ ((row >> 1) & 3);
            uint32_t rel = (uint32_t)(buf * STGB) + row * 64 + phys * 16;
            uint4 wh, wl;
            wh.x = pack2(h[0], h[1]); wh.y = pack2(h[2], h[3]);
            wh.z = pack2(h[4], h[5]); wh.w = pack2(h[6], h[7]);
            wl.x = pack2(l[0], l[1]); wl.y = pack2(l[2], l[3]);
            wl.z = pack2(l[4], l[5]); wl.w = pack2(l[6], l[7]);
            *(uint4*)(smem + rel)                  = wh;
            *(uint4*)(smem + rel + (uint32_t)ABYT) = wl;
        }
    };

    auto loadB = [&](int c, int buf) {
        uint32_t sbase = sb + buf * STGB + (uint32_t)(2 * ABYT);
        int k0 = c << 5;
        #pragma unroll
        for (int i = 0; i < 2; i++) {
            int id = tid + (i << 8);
            int row = id >> 2, ch = id & 3;
            int phys = ch ^ ((row >> 1) & 3);
            uint32_t so = sbase + row * 64 + phys * 16;
            CPA16(so,          Bh + (size_t)(colBase + row) * K + k0 + ch * 8);
            CPA16(so + 8192u,  Bl + (size_t)(colBase + row) * K + k0 + ch * 8);
        }
    };

    auto compute = [&](int buf) {
        uint32_t base = sb + buf * STGB;
        uint32_t bbase = base + (uint32_t)(2 * ABYT);
        #pragma unroll
        for (int ks = 0; ks < 2; ks++) {
            uint32_t ahf[MI][4], alf[MI][4], bhf[4][2], blf[4][2];
            #pragma unroll
            for (int mi = 0; mi < MI; mi++) {
                int row = wm * (BM / 2) + mi * 16 + sub + (grp & 1) * 8;
                int ci = 2 * ks + (grp >> 1);
                uint32_t ad = base + row * 64 + ((ci ^ ((row >> 1) & 3)) * 16);
                LDSM4(ahf[mi][0], ahf[mi][1], ahf[mi][2], ahf[mi][3], ad);
                LDSM4(alf[mi][0], alf[mi][1], alf[mi][2], alf[mi][3], ad + (uint32_t)ABYT);
            }
            #pragma unroll
            for (int g = 0; g < 2; g++) {
                int row = wn * 32 + g * 16 + sub + (grp & 1) * 8;
                int ci = 2 * ks + (grp >> 1);
                uint32_t ad = bbase + row * 64 + ((ci ^ ((row >> 1) & 3)) * 16);
                uint32_t r0, r1, r2, r3;
                LDSM4(r0, r1, r2, r3, ad);
                bhf[2*g][0] = r0; bhf[2*g+1][0] = r1; bhf[2*g][1] = r2; bhf[2*g+1][1] = r3;
                LDSM4(r0, r1, r2, r3, ad + 8192u);
                blf[2*g][0] = r0; blf[2*g+1][0] = r1; blf[2*g][1] = r2; blf[2*g+1][1] = r3;
            }
            #pragma unroll
            for (int mi = 0; mi < MI; mi++)
                #pragma unroll
                for (int nj = 0; nj < 4; nj++)
                    MMA16816(acc[mi][nj], ahf[mi], bhf[nj][0], bhf[nj][1]);
            #pragma unroll
            for (int mi = 0; mi < MI; mi++)
                #pragma unroll
                for (int nj = 0; nj < 4; nj++)
                    MMA16816(acc[mi][nj], ahf[mi], blf[nj][0], blf[nj][1]);
            #pragma unroll
            for (int mi = 0; mi < MI; mi++)
                #pragma unroll
                for (int nj = 0; nj < 4; nj++)
                    MMA16816(acc[mi][nj], alf[mi], bhf[nj][0], bhf[nj][1]);
        }
    };

    // prologue
    ldgA(0);
    stsA(0, 0);
    loadB(0, 0);
    CPCOMMIT();
    #pragma unroll 1
    for (int c = 0; c < NC; c++) {
        if (c + 1 < NC) ldgA(c + 1);       // LDG in flight over the B-wait
        CPWAIT(0);
        __syncthreads();
        if (c + 1 < NC) loadB(c + 1, (c + 1) & 1);
        CPCOMMIT();
        if (c + 1 < NC) stsA(c + 1, (c + 1) & 1);
        compute(c & 1);
    }

    // --- epilogue (fp32 out) ---
    #pragma unroll
    for (int mi = 0; mi < MI; mi++) {
        #pragma unroll
        for (int nj = 0; nj < 4; nj++) {
            int r = rowBase + wm * (BM / 2) + mi * 16 + (lane >> 2);
            int c = colBase + wn * 32 + nj * 8 + ((lane & 3) << 1);
            #pragma unroll
            for (int half_ : {0, 1}) {
                int rr = r + half_ * 8;
                float v0 = acc[mi][nj][half_ * 2 + 0];
                float v1 = acc[mi][nj][half_ * 2 + 1];
                if (bias) { v0 += bias[c]; v1 += bias[c + 1]; }
                if (res) {
                    float2 rv = *(const float2*)(res + (size_t)rr * N + c);
                    v0 += rv.x; v1 += rv.y;
                }
                if (relu) { v0 = fmaxf(v0, 0.0f); v1 = fmaxf(v1, 0.0f); }
                *(float2*)(outF + (size_t)rr * N + c) = make_float2(v0, v1);
            }
        }
    }
}

// ---------------- Chunked local attention (fp16 scores path, fp32 out) -----
__global__ void attn_kernel(const float* __restrict__ qkv, const float* __restrict__ p,
                            const float* __restrict__ pbu, const float* __restrict__ pbv,
                            float* __restrict__ o) {
    int ci = blockIdx.x, h = blockIdx.y, b = blockIdx.z;
    int s0 = max((ci - LC_) * CS_, 0);
    int s1 = (ci + 1) * CS_;
    int W = s1 - s0;
    int t0 = ci * CS_;
    int tid = threadIdx.x;                    // 256 threads

    extern __shared__ char asmem[];
    __half* Ks = (__half*)asmem;              // WMAX*64 halves
    __half* Ps = Ks + WMAX_ * 64;
    __half* QU = Ps + WMAX_ * 64;             // 16*64
    __half* QV = QU + 16 * 64;
    float* Vs = (float*)(QV + 16 * 64);       // WMAX*64 floats
    float* SC = Vs + WMAX_ * 64;              // 16*WMAX

    for (int idx = tid; idx < W * 64; idx += 256) {
        int s = idx >> 6, d = idx & 63;
        size_t gi = (size_t)((b * T_) + s0 + s) * QKVN_ + h * DK_ + d;
        Ks[idx] = __float2half(qkv[gi + D_]);
        Vs[idx] = qkv[gi + 2 * D_];
        Ps[idx] = __float2half(p[(size_t)(s0 + s) * PALLN_ + h * DK_ + d]);
    }
    for (int idx = tid; idx < 16 * 64; idx += 256) {
        int qi = idx >> 6, d = idx & 63;
        float qv_ = qkv[(size_t)((b * T_) + t0 + qi) * QKVN_ + h * DK_ + d];
        QU[idx] = __float2half(qv_ + pbu[h * DK_ + d]);
        QV[idx] = __float2half(qv_ + pbv[h * DK_ + d]);
    }
    __syncthreads();

    const float scale = 0.125f;
    int Wh = W >> 1;
    for (int it = tid; it < 8 * Wh; it += 256) {
        int qi = (it / Wh) * 2, s = (it % Wh) * 2;
        float a00 = 0, a01 = 0, a10 = 0, a11 = 0;
        #pragma unroll 4
        for (int d = 0; d < 64; d += 4) {
            float4 qu0 = ld4h(&QU[qi * 64 + d]);
            float4 qu1 = ld4h(&QU[(qi + 1) * 64 + d]);
            float4 qv0 = ld4h(&QV[qi * 64 + d]);
            float4 qv1 = ld4h(&QV[(qi + 1) * 64 + d]);
            float4 k0 = ld4h(&Ks[s * 64 + d]);
            float4 k1 = ld4h(&Ks[(s + 1) * 64 + d]);
            float4 p0 = ld4h(&Ps[s * 64 + d]);
            float4 p1 = ld4h(&Ps[(s + 1) * 64 + d]);
            a00 += dot4(qu0, k0) + dot4(qv0, p0);
            a01 += dot4(qu0, k1) + dot4(qv0, p1);
            a10 += dot4(qu1, k0) + dot4(qv1, p0);
            a11 += dot4(qu1, k1) + dot4(qv1, p1);
        }
        SC[qi * WMAX_ + s]           = a00 * scale;
        SC[qi * WMAX_ + s + 1]       = a01 * scale;
        SC[(qi + 1) * WMAX_ + s]     = a10 * scale;
        SC[(qi + 1) * WMAX_ + s + 1] = a11 * scale;
    }
    __syncthreads();

    int warp = tid >> 5, lane = tid & 31;
    for (int qi = warp; qi < 16; qi += 8) {
        float m = -1e30f;
        for (int s = lane; s < W; s += 32) m = fmaxf(m, SC[qi * WMAX_ + s]);
        #pragma unroll
        for (int off = 16; off; off >>= 1) m = fmaxf(m, __shfl_xor_sync(0xffffffffu, m, off));
        float sum = 0.0f;
        for (int s = lane; s < W; s += 32) {
            float e = expf(SC[qi * WMAX_ + s] - m);
            SC[qi * WMAX_ + s] = e;
            sum += e;
        }
        #pragma unroll
        for (int off = 16; off; off >>= 1) sum += __shfl_xor_sync(0xffffffffu, sum, off);
        float inv = 1.0f / sum;
        for (int s = lane; s < W; s += 32) SC[qi * WMAX_ + s] *= inv;
    }
    __syncthreads();

    {
        int it = tid;                       // 8 * 32 = 256
        int qi = (it >> 5) * 2, d = (it & 31) * 2;
        float a00 = 0, a01 = 0, a10 = 0, a11 = 0;
        for (int s = 0; s < W; s++) {
            float2 vv = *(const float2*)&Vs[s * 64 + d];
            float c0 = SC[qi * WMAX_ + s];
            float c1 = SC[(qi + 1) * WMAX_ + s];
            a00 += c0 * vv.x; a01 += c0 * vv.y;
            a10 += c1 * vv.x; a11 += c1 * vv.y;
        }
        size_t o0 = (size_t)((b * T_) + t0 + qi) * D_ + h * DK_ + d;
        *(float2*)(o + o0)      = make_float2(a00, a01);
        *(float2*)(o + o0 + D_) = make_float2(a10, a11);
    }
}

static const int ATTN_SMEM = (WMAX_*64*2 + 16*64*2) * 2 + (WMAX_*64 + 16*WMAX_) * 4; // 50176
static const int GEMM_SMEM128 = 2 * (128 * 128 + 16384);   // 65536
static const int GEMM_SMEM64  = 2 * (64 * 128 + 16384);    // 49152

extern "C" void kernel_launch(void* const* d_in, const int* in_sizes, int n_in,
                              void* d_out, int out_size) {
    (void)in_sizes; (void)n_in; (void)out_size;
    const float* xs    = (const float*)d_in[0];
    const float* pos   = (const float*)d_in[1];
    // d_in[2] = mask: unused (window computed analytically)
    const float* Wq    = (const float*)d_in[3];
    const float* bq    = (const float*)d_in[4];
    const float* Wk    = (const float*)d_in[5];
    const float* bk    = (const float*)d_in[6];
    const float* Wv    = (const float*)d_in[7];
    const float* bv    = (const float*)d_in[8];
    const float* Wo    = (const float*)d_in[9];
    const float* bo    = (const float*)d_in[10];
    const float* Wp    = (const float*)d_in[11];
    const float* pbu   = (const float*)d_in[12];
    const float* pbv   = (const float*)d_in[13];
    const float* ln1s  = (const float*)d_in[14];
    const float* ln1b  = (const float*)d_in[15];
    const float* ln2s  = (const float*)d_in[16];
    const float* ln2b  = (const float*)d_in[17];
    const float* W1    = (const float*)d_in[18];
    const float* b1    = (const float*)d_in[19];
    const float* W2    = (const float*)d_in[20];
    const float* b2    = (const float*)d_in[21];
    const float* lnfs  = (const float*)d_in[22];
    const float* lnfb  = (const float*)d_in[23];

    cudaFuncSetAttribute(attn_kernel,    cudaFuncAttributeMaxDynamicSharedMemorySize, ATTN_SMEM);
    cudaFuncSetAttribute(gemm_f32a<128>, cudaFuncAttributeMaxDynamicSharedMemorySize, GEMM_SMEM128);
    cudaFuncSetAttribute(gemm_f32a<64>,  cudaFuncAttributeMaxDynamicSharedMemorySize, GEMM_SMEM64);

    void* a;
    #define SYM(p, s) cudaGetSymbolAddress(&a, s); auto* p = (decltype(&s[0]))a;
    SYM(px, g_x)  SYM(pqkv, g_qkv)  SYM(po, g_o)  SYM(pff, g_ff)
    SYM(ppall, g_pall)  SYM(pbqkv, g_bqkv)  SYM(pst, g_st)
    SYM(pwqkvh, g_wqkvh) SYM(pwqkvl, g_wqkvl)
    SYM(pwoh, g_woh) SYM(pwol, g_wol)
    SYM(pwph, g_wph) SYM(pwpl, g_wpl)
    SYM(pw1h, g_w1h) SYM(pw1l, g_w1l)
    SYM(pw2h, g_w2h) SYM(pw2l, g_w2l)
    #undef SYM

    const int M = B_ * T_;  // 4096
    const size_t DD = (size_t)D_ * D_;          // 262144
    const size_t QKVLS = (size_t)QKVN_ * D_;    // 786432
    dim3 wtb(32, 8);

    // Launch order chosen so launch #6 (ncu -s 5 -c 1) is the fused QKV GEMM.
    scale_kernel<<<(B_*T_*D_) / 256, 256>>>(xs, sqrtf((float)D_));                       // 1
    bcat_kernel<<<(L_*QKVN_) / 256, 256>>>(bq, bk, bv);                                  // 2
    wtransqkv_kernel<<<dim3(16, 16, 3 * L_), wtb>>>(Wq, Wk, Wv, pwqkvh, pwqkvl);         // 3
    lnstats_kernel<<<M, 256>>>(px, pst);                                                 // 4
    wtrans_kernel<<<dim3(D_/32, D_/32, L_), wtb>>>(Wo, pwoh, pwol, D_, D_, DD, DD);      // 5
    // 6: the big fused QKV GEMM for layer 0 (captured by ncu)
    gemm_f32a<128><<<dim3(QKVN_/128, M/128), 256, GEMM_SMEM128>>>(px, pst,
        ln1s, ln1b, pwqkvh, pwqkvl, pbqkv, nullptr, pqkv, QKVN_, D_, 0);
    // remaining prep (needed before attention / FF of layer 0)
    wtrans_kernel<<<dim3(D_/32,  D_/32,  L_), wtb>>>(Wp, pwph, pwpl, D_,  D_,  DD, DD);
    wtrans_kernel<<<dim3(FF_/32, D_/32,  L_), wtb>>>(W1, pw1h, pw1l, D_,  FF_, (size_t)D_*FF_, (size_t)D_*FF_);
    wtrans_kernel<<<dim3(D_/32,  FF_/32, L_), wtb>>>(W2, pw2h, pw2l, FF_, D_,  (size_t)FF_*D_, (size_t)FF_*D_);
    gemm_f32a<64><<<dim3(PALLN_/128, T_/64), 256, GEMM_SMEM64>>>(pos, nullptr, nullptr, nullptr,
        pwph, pwpl, nullptr, nullptr, ppall, PALLN_, D_, 0);

    for (int l = 0; l < L_; l++) {
        size_t wdf = (size_t)l * D_ * FF_;

        if (l > 0) {
            lnstats_kernel<<<M, 256>>>(px, pst);
            gemm_f32a<128><<<dim3(QKVN_/128, M/128), 256, GEMM_SMEM128>>>(px, pst,
                ln1s + l*D_, ln1b + l*D_,
                pwqkvh + l * QKVLS, pwqkvl + l * QKVLS,
                pbqkv + l * QKVN_, nullptr, pqkv, QKVN_, D_, 0);
        }

        // attention -> o fp32
        attn_kernel<<<dim3(NCHUNK_, H_, B_), 256, ATTN_SMEM>>>(
            pqkv, ppall + l * D_, pbu + l * H_ * DK_, pbv + l * H_ * DK_, po);

        // x = x + o @ Wo + bo   (BM=64: 256 CTAs)
        gemm_f32a<64><<<dim3(D_/128, M/64), 256, GEMM_SMEM64>>>(po, nullptr, nullptr, nullptr,
            pwoh + l * DD, pwol + l * DD,
            bo + l*D_, px, px, D_, D_, 0);

        // row stats for LN2
        lnstats_kernel<<<M, 256>>>(px, pst);

        // ff = relu(LN2(x) @ W1 + b1)
        gemm_f32a<128><<<dim3(FF_/128, M/128), 256, GEMM_SMEM128>>>(px, pst,
            ln2s + l*D_, ln2b + l*D_,
            pw1h + wdf, pw1l + wdf,
            b1 + l*FF_, nullptr, pff, FF_, D_, 1);

        // x = x + ff @ W2 + b2  (BM=64: 256 CTAs)
        gemm_f32a<64><<<dim3(D_/128, M/64), 256, GEMM_SMEM64>>>(pff, nullptr, nullptr, nullptr,
            pw2h + wdf, pw2l + wdf,
            b2 + l*D_, px, px, D_, FF_, 0);
    }

    // out = LNf(x)  (fp32)
    ln_kernel<<<M, 256>>>(px, (float*)d_out, lnfs, lnfb);
}

// round 8
// speedup vs baseline: 1.4829x; 1.4829x over previous
#include <cuda_runtime.h>
#include <cuda_fp16.h>
#include <math.h>
#include <stdint.h>

// Problem constants
#define B_  8
#define T_  512
#define D_  512
#define H_  8
#define FF_ 2048
#define L_  6
#define CS_ 16
#define LC_ 4
#define DK_ 64
#define NCHUNK_ (T_ / CS_)          // 32
#define WMAX_ ((LC_ + 1) * CS_)     // 80
#define QKVN_ (3 * D_)              // 1536
#define PALLN_ (L_ * D_)            // 3072

// ---------------- scratch (device globals; no allocation) ----------------
__device__ float  g_x   [B_*T_*D_];
__device__ float  g_qkv [B_*T_*QKVN_];
__device__ float  g_o   [B_*T_*D_];
__device__ float  g_ff  [B_*T_*FF_];
__device__ float  g_pall[T_*PALLN_];
__device__ float  g_bqkv[L_*QKVN_];
__device__ float2 g_st  [B_*T_];

// transposed + split weights: Wt[n][k]
__device__ __half g_wqkvh[L_*QKVN_*D_], g_wqkvl[L_*QKVN_*D_];
__device__ __half g_woh[L_*D_*D_],  g_wol[L_*D_*D_];
__device__ __half g_wph[L_*D_*D_],  g_wpl[L_*D_*D_];
__device__ __half g_w1h[L_*D_*FF_], g_w1l[L_*D_*FF_];
__device__ __half g_w2h[L_*FF_*D_], g_w2l[L_*FF_*D_];

// ---------------- PTX helpers (family-portable: sm_80+ ISA only) ----------
__device__ __forceinline__ uint32_t s2u(const void* p) {
    uint32_t a;
    asm("{ .reg .u64 t; cvta.to.shared.u64 t, %1; cvt.u32.u64 %0, t; }" : "=r"(a) : "l"(p));
    return a;
}

#define CPA16(sa, g) \
    asm volatile("cp.async.cg.shared.global [%0], [%1], 16;" :: "r"(sa), "l"(g) : "memory")
#define CPCOMMIT() asm volatile("cp.async.commit_group;" ::: "memory")
#define CPWAIT(n)  asm volatile("cp.async.wait_group %0;" :: "n"(n) : "memory")

#define LDSM4(d0, d1, d2, d3, a) \
    asm volatile("ldmatrix.sync.aligned.m8n8.x4.shared.b16 {%0,%1,%2,%3}, [%4];" \
        : "=r"(d0), "=r"(d1), "=r"(d2), "=r"(d3) : "r"(a))

#define MMA16816(c, a, b0, b1) \
    asm volatile("mma.sync.aligned.m16n8k16.row.col.f32.f16.f16.f32 " \
        "{%0,%1,%2,%3}, {%4,%5,%6,%7}, {%8,%9}, {%0,%1,%2,%3};" \
        : "+f"((c)[0]), "+f"((c)[1]), "+f"((c)[2]), "+f"((c)[3]) \
        : "r"((a)[0]), "r"((a)[1]), "r"((a)[2]), "r"((a)[3]), "r"(b0), "r"(b1))

__device__ __forceinline__ void split_h(float v, __half& hi, __half& lo) {
    hi = __float2half_rn(v);
    lo = __float2half_rn(v - __half2float(hi));
}
__device__ __forceinline__ uint32_t pack2(__half a, __half b) {
    __half2 t = __halves2half2(a, b);
    return *reinterpret_cast<uint32_t*>(&t);
}
__device__ __forceinline__ float4 ld4h(const __half* p) {
    uint2 u = *(const uint2*)p;
    __half2 a = *reinterpret_cast<__half2*>(&u.x);
    __half2 b = *reinterpret_cast<__half2*>(&u.y);
    float2 fa = __half22float2(a), fb = __half22float2(b);
    return make_float4(fa.x, fa.y, fb.x, fb.y);
}
__device__ __forceinline__ float dot4(float4 a, float4 b) {
    return a.x * b.x + a.y * b.y + a.z * b.z + a.w * b.w;
}

// ---------------- elementwise scale: x = xs * sqrt(D) ----------------
__global__ void scale_kernel(const float* __restrict__ xs, float s) {
    int i = blockIdx.x * blockDim.x + threadIdx.x;
    g_x[i] = xs[i] * s;
}

// ---------------- bias concat for fused QKV ----------------
__global__ void bcat_kernel(const float* __restrict__ bq, const float* __restrict__ bk,
                            const float* __restrict__ bv) {
    int i = blockIdx.x * blockDim.x + threadIdx.x;   // L*1536
    int l = i / QKVN_, c = i % QKVN_;
    float v = (c < D_) ? bq[l * D_ + c]
            : (c < 2 * D_) ? bk[l * D_ + c - D_]
            : bv[l * D_ + c - 2 * D_];
    g_bqkv[i] = v;
}

// ---------------- merged QKV weight transpose+split ----------------
__global__ void wtransqkv_kernel(const float* __restrict__ Wq,
                                 const float* __restrict__ Wk,
                                 const float* __restrict__ Wv,
                                 __half* __restrict__ Th, __half* __restrict__ Tl) {
    __shared__ float sm[32][33];
    int z = blockIdx.z;
    int which = z / L_, l = z % L_;
    const size_t DD = (size_t)D_ * D_;
    const float* Wl = (which == 0 ? Wq : which == 1 ? Wk : Wv) + (size_t)l * DD;
    size_t dOff = (size_t)l * QKVN_ * D_ + (size_t)which * DD;
    __half* Thl = Th + dOff;
    __half* Tll = Tl + dOff;
    int n0 = blockIdx.x * 32, k0 = blockIdx.y * 32;
    int tx = threadIdx.x, ty = threadIdx.y;
    #pragma unroll
    for (int j = 0; j < 4; j++)
        sm[ty + j * 8][tx] = Wl[(size_t)(k0 + ty + j * 8) * D_ + n0 + tx];
    __syncthreads();
    #pragma unroll
    for (int j = 0; j < 4; j++) {
        int n = ty + j * 8;
        float v = sm[tx][n];
        __half h, l2;
        split_h(v, h, l2);
        size_t o = (size_t)(n0 + n) * D_ + k0 + tx;
        Thl[o] = h; Tll[o] = l2;
    }
}

// ---------------- generic weight transpose + split ----------------
__global__ void wtrans_kernel(const float* __restrict__ W,
                              __half* __restrict__ Th, __half* __restrict__ Tl,
                              int K, int N, size_t srcLS, size_t dstLS) {
    __shared__ float sm[32][33];
    const float* Wl = W + (size_t)blockIdx.z * srcLS;
    __half* Thl = Th + (size_t)blockIdx.z * dstLS;
    __half* Tll = Tl + (size_t)blockIdx.z * dstLS;
    int n0 = blockIdx.x * 32, k0 = blockIdx.y * 32;
    int tx = threadIdx.x, ty = threadIdx.y;
    #pragma unroll
    for (int j = 0; j < 4; j++)
        sm[ty + j * 8][tx] = Wl[(size_t)(k0 + ty + j * 8) * N + n0 + tx];
    __syncthreads();
    #pragma unroll
    for (int j = 0; j < 4; j++) {
        int n = ty + j * 8;
        float v = sm[tx][n];
        __half h, l;
        split_h(v, h, l);
        size_t o = (size_t)(n0 + n) * K + k0 + tx;
        Thl[o] = h; Tll[o] = l;
    }
}

// ---------------- LN stats: one warp per row, float4 loads ----------------
__global__ void lnstats_kernel(const float* __restrict__ in, float2* __restrict__ st) {
    int warp = threadIdx.x >> 5, lane = threadIdx.x & 31;
    int row = blockIdx.x * 8 + warp;
    const float4* x = (const float4*)(in + (size_t)row * D_);
    float s = 0.0f, ss = 0.0f;
    #pragma unroll
    for (int j = 0; j < 4; j++) {
        float4 v = x[lane + j * 32];
        s  += v.x + v.y + v.z + v.w;
        ss += v.x * v.x + v.y * v.y + v.z * v.z + v.w * v.w;
    }
    #pragma unroll
    for (int off = 16; off; off >>= 1) {
        s  += __shfl_xor_sync(0xffffffffu, s,  off);
        ss += __shfl_xor_sync(0xffffffffu, ss, off);
    }
    if (lane == 0) {
        float mean = s * (1.0f / D_);
        float var  = ss * (1.0f / D_) - mean * mean;
        st[row] = make_float2(mean, rsqrtf(var + 1e-5f));
    }
}

// ---------------- final LN ----------------
__global__ void ln_kernel(const float* __restrict__ in, float* __restrict__ out,
                          const float* __restrict__ gam, const float* __restrict__ bet) {
    __shared__ float sh_s[8], sh_ss[8];
    int row = blockIdx.x, tid = threadIdx.x;
    const float* x = in + (size_t)row * D_;
    float v0 = x[tid], v1 = x[tid + 256];
    float s = v0 + v1, ss = v0 * v0 + v1 * v1;
    int lane = tid & 31, warp = tid >> 5;
    #pragma unroll
    for (int off = 16; off; off >>= 1) {
        s  += __shfl_xor_sync(0xffffffffu, s,  off);
        ss += __shfl_xor_sync(0xffffffffu, ss, off);
    }
    if (lane == 0) { sh_s[warp] = s; sh_ss[warp] = ss; }
    __syncthreads();
    if (warp == 0) {
        float a = (lane < 8) ? sh_s[lane]  : 0.0f;
        float b = (lane < 8) ? sh_ss[lane] : 0.0f;
        #pragma unroll
        for (int off = 4; off; off >>= 1) {
            a += __shfl_xor_sync(0xffffffffu, a, off);
            b += __shfl_xor_sync(0xffffffffu, b, off);
        }
        if (lane == 0) { sh_s[0] = a; sh_ss[0] = b; }
    }
    __syncthreads();
    float mean = sh_s[0] * (1.0f / D_);
    float var  = sh_ss[0] * (1.0f / D_) - mean * mean;
    float inv  = rsqrtf(var + 1e-5f);
    float* y = out + (size_t)row * D_;
    y[tid]       = (v0 - mean) * inv * gam[tid]       + bet[tid];
    y[tid + 256] = (v1 - mean) * inv * gam[tid + 256] + bet[tid + 256];
}

// ---------------- HMMA fp16x3 GEMM, fp32-A, fused LN --------------------
// BM=128, BN=128, BK=32; 8 warps (2x4), warp tile 64x32.
// 3-stage cp.async pipeline (wait_group 1) + 2 CTAs/SM (96KB smem each).
#define STAGE_BYTES 32768
#define NSTG 3
__global__ void __launch_bounds__(256, 2)
gemm_f32a(const float* __restrict__ A, const float2* __restrict__ stats,
          const float* __restrict__ gam, const float* __restrict__ bet,
          const __half* __restrict__ Bh, const __half* __restrict__ Bl,
          const float* __restrict__ bias, const float* __restrict__ res,
          float* __restrict__ outF, int N, int K, int relu) {
    extern __shared__ char smem[];
    uint32_t sb = s2u(smem);
    int tid = threadIdx.x, lane = tid & 31, wid = tid >> 5;
    int wm = wid >> 2, wn = wid & 3;
    int rowBase = blockIdx.y * 128, colBase = blockIdx.x * 128;
    int sub = lane & 7, grp = lane >> 3;

    float acc[4][4][4];
    #pragma unroll
    for (int i = 0; i < 4; i++)
        #pragma unroll
        for (int j = 0; j < 4; j++)
            #pragma unroll
            for (int c = 0; c < 4; c++) acc[i][j][c] = 0.0f;

    const int NC = K >> 5;

    float aR[2][8];
    float2 stR[2];
    #pragma unroll
    for (int i = 0; i < 2; i++) {
        int id = tid + (i << 8);
        int row = id >> 2;
        stR[i] = stats ? stats[rowBase + row] : make_float2(0.0f, 1.0f);
    }

    auto ldgA = [&](int c) {
        int k0 = c << 5;
        #pragma unroll
        for (int i = 0; i < 2; i++) {
            int id = tid + (i << 8);
            int row = id >> 2, ch = id & 3;
            const float* g = A + (size_t)(rowBase + row) * K + k0 + ch * 8;
            float4 u = *(const float4*)g;
            float4 v = *(const float4*)(g + 4);
            aR[i][0] = u.x; aR[i][1] = u.y; aR[i][2] = u.z; aR[i][3] = u.w;
            aR[i][4] = v.x; aR[i][5] = v.y; aR[i][6] = v.z; aR[i][7] = v.w;
        }
    };

    auto stsA = [&](int c, int buf) {
        int k0 = c << 5;
        #pragma unroll
        for (int i = 0; i < 2; i++) {
            int id = tid + (i << 8);
            int row = id >> 2, ch = id & 3;
            float y[8];
            if (gam) {
                float mean = stR[i].x, inv = stR[i].y;
                const float* gg = gam + k0 + ch * 8;
                const float* bb = bet + k0 + ch * 8;
                float4 g0 = *(const float4*)gg, g1 = *(const float4*)(gg + 4);
                float4 b0 = *(const float4*)bb, b1 = *(const float4*)(bb + 4);
                y[0] = (aR[i][0] - mean) * inv * g0.x + b0.x;
                y[1] = (aR[i][1] - mean) * inv * g0.y + b0.y;
                y[2] = (aR[i][2] - mean) * inv * g0.z + b0.z;
                y[3] = (aR[i][3] - mean) * inv * g0.w + b0.w;
                y[4] = (aR[i][4] - mean) * inv * g1.x + b1.x;
                y[5] = (aR[i][5] - mean) * inv * g1.y + b1.y;
                y[6] = (aR[i][6] - mean) * inv * g1.z + b1.z;
                y[7] = (aR[i][7] - mean) * inv * g1.w + b1.w;
            } else {
                #pragma unroll
                for (int j = 0; j < 8; j++) y[j] = aR[i][j];
            }
            __half h[8], l[8];
            #pragma unroll
            for (int j = 0; j < 8; j++) split_h(y[j], h[j], l[j]);
            int phys = ch ^ ((row >> 1) & 3);
            uint32_t rel = (uint32_t)(buf * STAGE_BYTES) + row * 64 + phys * 16;
            uint4 wh, wl;
            wh.x = pack2(h[0], h[1]); wh.y = pack2(h[2], h[3]);
            wh.z = pack2(h[4], h[5]); wh.w = pack2(h[6], h[7]);
            wl.x = pack2(l[0], l[1]); wl.y = pack2(l[2], l[3]);
            wl.z = pack2(l[4], l[5]); wl.w = pack2(l[6], l[7]);
            *(uint4*)(smem + rel)         = wh;
            *(uint4*)(smem + rel + 8192u) = wl;
        }
    };

    auto loadB = [&](int c, int buf) {
        uint32_t sbase = sb + buf * STAGE_BYTES + 16384u;
        int k0 = c << 5;
        #pragma unroll
        for (int i = 0; i < 2; i++) {
            int id = tid + (i << 8);
            int row = id >> 2, ch = id & 3;
            int phys = ch ^ ((row >> 1) & 3);
            uint32_t so = sbase + row * 64 + phys * 16;
            CPA16(so,          Bh + (size_t)(colBase + row) * K + k0 + ch * 8);
            CPA16(so + 8192u,  Bl + (size_t)(colBase + row) * K + k0 + ch * 8);
        }
    };

    auto compute = [&](int buf) {
        uint32_t base = sb + buf * STAGE_BYTES;
        #pragma unroll
        for (int ks = 0; ks < 2; ks++) {
            uint32_t ahf[4][4], alf[4][4], bhf[4][2], blf[4][2];
            #pragma unroll
            for (int mi = 0; mi < 4; mi++) {
                int row = wm * 64 + mi * 16 + sub + (grp & 1) * 8;
                int ci = 2 * ks + (grp >> 1);
                uint32_t ad = base + row * 64 + ((ci ^ ((row >> 1) & 3)) * 16);
                LDSM4(ahf[mi][0], ahf[mi][1], ahf[mi][2], ahf[mi][3], ad);
                LDSM4(alf[mi][0], alf[mi][1], alf[mi][2], alf[mi][3], ad + 8192u);
            }
            #pragma unroll
            for (int g = 0; g < 2; g++) {
                int row = wn * 32 + g * 16 + sub + (grp & 1) * 8;
                int ci = 2 * ks + (grp >> 1);
                uint32_t ad = base + 16384u + row * 64 + ((ci ^ ((row >> 1) & 3)) * 16);
                uint32_t r0, r1, r2, r3;
                LDSM4(r0, r1, r2, r3, ad);
                bhf[2*g][0] = r0; bhf[2*g+1][0] = r1; bhf[2*g][1] = r2; bhf[2*g+1][1] = r3;
                LDSM4(r0, r1, r2, r3, ad + 8192u);
                blf[2*g][0] = r0; blf[2*g+1][0] = r1; blf[2*g][1] = r2; blf[2*g+1][1] = r3;
            }
            #pragma unroll
            for (int mi = 0; mi < 4; mi++)
                #pragma unroll
                for (int nj = 0; nj < 4; nj++)
                    MMA16816(acc[mi][nj], ahf[mi], bhf[nj][0], bhf[nj][1]);
            #pragma unroll
            for (int mi = 0; mi < 4; mi++)
                #pragma unroll
                for (int nj = 0; nj < 4; nj++)
                    MMA16816(acc[mi][nj], ahf[mi], blf[nj][0], blf[nj][1]);
            #pragma unroll
            for (int mi = 0; mi < 4; mi++)
                #pragma unroll
                for (int nj = 0; nj < 4; nj++)
                    MMA16816(acc[mi][nj], alf[mi], bhf[nj][0], bhf[nj][1]);
        }
    };

    // prologue: stages 0 and 1
    ldgA(0); stsA(0, 0); loadB(0, 0); CPCOMMIT();
    if (NC > 1) { ldgA(1); stsA(1, 1); loadB(1, 1); }
    CPCOMMIT();
    #pragma unroll 1
    for (int c = 0; c < NC; c++) {
        int nxt = c + 2;
        int nb = nxt % NSTG;
        if (nxt < NC) ldgA(nxt);           // LDG in flight over the wait
        CPWAIT(1);                          // stage c complete (c+1 may fly)
        __syncthreads();
        if (nxt < NC) loadB(nxt, nb);
        CPCOMMIT();
        if (nxt < NC) stsA(nxt, nb);
        compute(c % NSTG);
    }

    // --- epilogue (fp32 out) ---
    #pragma unroll
    for (int mi = 0; mi < 4; mi++) {
        #pragma unroll
        for (int nj = 0; nj < 4; nj++) {
            int r = rowBase + wm * 64 + mi * 16 + (lane >> 2);
            int c = colBase + wn * 32 + nj * 8 + ((lane & 3) << 1);
            #pragma unroll
            for (int half_ : {0, 1}) {
                int rr = r + half_ * 8;
                float v0 = acc[mi][nj][half_ * 2 + 0];
                float v1 = acc[mi][nj][half_ * 2 + 1];
                if (bias) { v0 += bias[c]; v1 += bias[c + 1]; }
                if (res) {
                    float2 rv = *(const float2*)(res + (size_t)rr * N + c);
                    v0 += rv.x; v1 += rv.y;
                }
                if (relu) { v0 = fmaxf(v0, 0.0f); v1 = fmaxf(v1, 0.0f); }
                *(float2*)(outF + (size_t)rr * N + c) = make_float2(v0, v1);
            }
        }
    }
}

// ---------------- Chunked local attention (fp16 scores path, fp32 out) -----
__global__ void attn_kernel(const float* __restrict__ qkv, const float* __restrict__ p,
                            const float* __restrict__ pbu, const float* __restrict__ pbv,
                            float* __restrict__ o) {
    int ci = blockIdx.x, h = blockIdx.y, b = blockIdx.z;
    int s0 = max((ci - LC_) * CS_, 0);
    int s1 = (ci + 1) * CS_;
    int W = s1 - s0;
    int t0 = ci * CS_;
    int tid = threadIdx.x;                    // 256 threads

    extern __shared__ char asmem[];
    __half* Ks = (__half*)asmem;              // WMAX*64 halves
    __half* Ps = Ks + WMAX_ * 64;
    __half* QU = Ps + WMAX_ * 64;             // 16*64
    __half* QV = QU + 16 * 64;
    float* Vs = (float*)(QV + 16 * 64);       // WMAX*64 floats
    float* SC = Vs + WMAX_ * 64;              // 16*WMAX

    for (int idx = tid; idx < W * 64; idx += 256) {
        int s = idx >> 6, d = idx & 63;
        size_t gi = (size_t)((b * T_) + s0 + s) * QKVN_ + h * DK_ + d;
        Ks[idx] = __float2half(qkv[gi + D_]);
        Vs[idx] = qkv[gi + 2 * D_];
        Ps[idx] = __float2half(p[(size_t)(s0 + s) * PALLN_ + h * DK_ + d]);
    }
    for (int idx = tid; idx < 16 * 64; idx += 256) {
        int qi = idx >> 6, d = idx & 63;
        float qv_ = qkv[(size_t)((b * T_) + t0 + qi) * QKVN_ + h * DK_ + d];
        QU[idx] = __float2half(qv_ + pbu[h * DK_ + d]);
        QV[idx] = __float2half(qv_ + pbv[h * DK_ + d]);
    }
    __syncthreads();

    const float scale = 0.125f;
    int Wh = W >> 1;
    for (int it = tid; it < 8 * Wh; it += 256) {
        int qi = (it / Wh) * 2, s = (it % Wh) * 2;
        float a00 = 0, a01 = 0, a10 = 0, a11 = 0;
        #pragma unroll 4
        for (int d = 0; d < 64; d += 4) {
            float4 qu0 = ld4h(&QU[qi * 64 + d]);
            float4 qu1 = ld4h(&QU[(qi + 1) * 64 + d]);
            float4 qv0 = ld4h(&QV[qi * 64 + d]);
            float4 qv1 = ld4h(&QV[(qi + 1) * 64 + d]);
            float4 k0 = ld4h(&Ks[s * 64 + d]);
            float4 k1 = ld4h(&Ks[(s + 1) * 64 + d]);
            float4 p0 = ld4h(&Ps[s * 64 + d]);
            float4 p1 = ld4h(&Ps[(s + 1) * 64 + d]);
            a00 += dot4(qu0, k0) + dot4(qv0, p0);
            a01 += dot4(qu0, k1) + dot4(qv0, p1);
            a10 += dot4(qu1, k0) + dot4(qv1, p0);
            a11 += dot4(qu1, k1) + dot4(qv1, p1);
        }
        SC[qi * WMAX_ + s]           = a00 * scale;
        SC[qi * WMAX_ + s + 1]       = a01 * scale;
        SC[(qi + 1) * WMAX_ + s]     = a10 * scale;
        SC[(qi + 1) * WMAX_ + s + 1] = a11 * scale;
    }
    __syncthreads();

    int warp = tid >> 5, lane = tid & 31;
    for (int qi = warp; qi < 16; qi += 8) {
        float m = -1e30f;
        for (int s = lane; s < W; s += 32) m = fmaxf(m, SC[qi * WMAX_ + s]);
        #pragma unroll
        for (int off = 16; off; off >>= 1) m = fmaxf(m, __shfl_xor_sync(0xffffffffu, m, off));
        float sum = 0.0f;
        for (int s = lane; s < W; s += 32) {
            float e = expf(SC[qi * WMAX_ + s] - m);
            SC[qi * WMAX_ + s] = e;
            sum += e;
        }
        #pragma unroll
        for (int off = 16; off; off >>= 1) sum += __shfl_xor_sync(0xffffffffu, sum, off);
        float inv = 1.0f / sum;
        for (int s = lane; s < W; s += 32) SC[qi * WMAX_ + s] *= inv;
    }
    __syncthreads();

    {
        int it = tid;                       // 8 * 32 = 256
        int qi = (it >> 5) * 2, d = (it & 31) * 2;
        float a00 = 0, a01 = 0, a10 = 0, a11 = 0;
        for (int s = 0; s < W; s++) {
            float2 vv = *(const float2*)&Vs[s * 64 + d];
            float c0 = SC[qi * WMAX_ + s];
            float c1 = SC[(qi + 1) * WMAX_ + s];
            a00 += c0 * vv.x; a01 += c0 * vv.y;
            a10 += c1 * vv.x; a11 += c1 * vv.y;
        }
        size_t o0 = (size_t)((b * T_) + t0 + qi) * D_ + h * DK_ + d;
        *(float2*)(o + o0)      = make_float2(a00, a01);
        *(float2*)(o + o0 + D_) = make_float2(a10, a11);
    }
}

static const int ATTN_SMEM = (WMAX_*64*2 + 16*64*2) * 2 + (WMAX_*64 + 16*WMAX_) * 4; // 50176
static const int GEMM_SMEM = NSTG * STAGE_BYTES;   // 98304

extern "C" void kernel_launch(void* const* d_in, const int* in_sizes, int n_in,
                              void* d_out, int out_size) {
    (void)in_sizes; (void)n_in; (void)out_size;
    const float* xs    = (const float*)d_in[0];
    const float* pos   = (const float*)d_in[1];
    // d_in[2] = mask: unused (window computed analytically)
    const float* Wq    = (const float*)d_in[3];
    const float* bq    = (const float*)d_in[4];
    const float* Wk    = (const float*)d_in[5];
    const float* bk    = (const float*)d_in[6];
    const float* Wv    = (const float*)d_in[7];
    const float* bv    = (const float*)d_in[8];
    const float* Wo    = (const float*)d_in[9];
    const float* bo    = (const float*)d_in[10];
    const float* Wp    = (const float*)d_in[11];
    const float* pbu   = (const float*)d_in[12];
    const float* pbv   = (const float*)d_in[13];
    const float* ln1s  = (const float*)d_in[14];
    const float* ln1b  = (const float*)d_in[15];
    const float* ln2s  = (const float*)d_in[16];
    const float* ln2b  = (const float*)d_in[17];
    const float* W1    = (const float*)d_in[18];
    const float* b1    = (const float*)d_in[19];
    const float* W2    = (const float*)d_in[20];
    const float* b2    = (const float*)d_in[21];
    const float* lnfs  = (const float*)d_in[22];
    const float* lnfb  = (const float*)d_in[23];

    cudaFuncSetAttribute(attn_kernel, cudaFuncAttributeMaxDynamicSharedMemorySize, ATTN_SMEM);
    cudaFuncSetAttribute(gemm_f32a,   cudaFuncAttributeMaxDynamicSharedMemorySize, GEMM_SMEM);

    void* a;
    #define SYM(p, s) cudaGetSymbolAddress(&a, s); auto* p = (decltype(&s[0]))a;
    SYM(px, g_x)  SYM(pqkv, g_qkv)  SYM(po, g_o)  SYM(pff, g_ff)
    SYM(ppall, g_pall)  SYM(pbqkv, g_bqkv)  SYM(pst, g_st)
    SYM(pwqkvh, g_wqkvh) SYM(pwqkvl, g_wqkvl)
    SYM(pwoh, g_woh) SYM(pwol, g_wol)
    SYM(pwph, g_wph) SYM(pwpl, g_wpl)
    SYM(pw1h, g_w1h) SYM(pw1l, g_w1l)
    SYM(pw2h, g_w2h) SYM(pw2l, g_w2l)
    #undef SYM

    const int M = B_ * T_;  // 4096
    const size_t DD = (size_t)D_ * D_;          // 262144
    const size_t QKVLS = (size_t)QKVN_ * D_;    // 786432
    dim3 wtb(32, 8);

    scale_kernel<<<(B_*T_*D_) / 256, 256>>>(xs, sqrtf((float)D_));
    bcat_kernel<<<(L_*QKVN_) / 256, 256>>>(bq, bk, bv);
    wtransqkv_kernel<<<dim3(16, 16, 3 * L_), wtb>>>(Wq, Wk, Wv, pwqkvh, pwqkvl);
    lnstats_kernel<<<M / 8, 256>>>(px, pst);
    wtrans_kernel<<<dim3(D_/32, D_/32, L_), wtb>>>(Wo, pwoh, pwol, D_, D_, DD, DD);
    // layer-0 fused QKV GEMM early (profiling target position)
    gemm_f32a<<<dim3(QKVN_/128, M/128), 256, GEMM_SMEM>>>(px, pst,
        ln1s, ln1b, pwqkvh, pwqkvl, pbqkv, nullptr, pqkv, QKVN_, D_, 0);
    // remaining prep
    wtrans_kernel<<<dim3(D_/32,  D_/32,  L_), wtb>>>(Wp, pwph, pwpl, D_,  D_,  DD, DD);
    wtrans_kernel<<<dim3(FF_/32, D_/32,  L_), wtb>>>(W1, pw1h, pw1l, D_,  FF_, (size_t)D_*FF_, (size_t)D_*FF_);
    wtrans_kernel<<<dim3(D_/32,  FF_/32, L_), wtb>>>(W2, pw2h, pw2l, FF_, D_,  (size_t)FF_*D_, (size_t)FF_*D_);
    gemm_f32a<<<dim3(PALLN_/128, T_/128), 256, GEMM_SMEM>>>(pos, nullptr, nullptr, nullptr,
        pwph, pwpl, nullptr, nullptr, ppall, PALLN_, D_, 0);

    for (int l = 0; l < L_; l++) {
        size_t wdf = (size_t)l * D_ * FF_;

        if (l > 0) {
            lnstats_kernel<<<M / 8, 256>>>(px, pst);
            gemm_f32a<<<dim3(QKVN_/128, M/128), 256, GEMM_SMEM>>>(px, pst,
                ln1s + l*D_, ln1b + l*D_,
                pwqkvh + l * QKVLS, pwqkvl + l * QKVLS,
                pbqkv + l * QKVN_, nullptr, pqkv, QKVN_, D_, 0);
        }

        // attention -> o fp32
        attn_kernel<<<dim3(NCHUNK_, H_, B_), 256, ATTN_SMEM>>>(
            pqkv, ppall + l * D_, pbu + l * H_ * DK_, pbv + l * H_ * DK_, po);

        // x = x + o @ Wo + bo
        gemm_f32a<<<dim3(D_/128, M/128), 256, GEMM_SMEM>>>(po, nullptr, nullptr, nullptr,
            pwoh + l * DD, pwol + l * DD,
            bo + l*D_, px, px, D_, D_, 0);

        // row stats for LN2
        lnstats_kernel<<<M / 8, 256>>>(px, pst);

        // ff = relu(LN2(x) @ W1 + b1)
        gemm_f32a<<<dim3(FF_/128, M/128), 256, GEMM_SMEM>>>(px, pst,
            ln2s + l*D_, ln2b + l*D_,
            pw1h + wdf, pw1l + wdf,
            b1 + l*FF_, nullptr, pff, FF_, D_, 1);

        // x = x + ff @ W2 + b2
        gemm_f32a<<<dim3(D_/128, M/128), 256, GEMM_SMEM>>>(pff, nullptr, nullptr, nullptr,
            pw2h + wdf, pw2l + wdf,
            b2 + l*D_, px, px, D_, FF_, 0);
    }

    // out = LNf(x)  (fp32)
    ln_kernel<<<M, 256>>>(px, (float*)d_out, lnfs, lnfb);
}

// round 9
// speedup vs baseline: 1.8133x; 1.2228x over previous
#include <cuda_runtime.h>
#include <cuda_fp16.h>
#include <math.h>
#include <stdint.h>

// Problem constants
#define B_  8
#define T_  512
#define D_  512
#define H_  8
#define FF_ 2048
#define L_  6
#define CS_ 16
#define LC_ 4
#define DK_ 64
#define NCHUNK_ (T_ / CS_)          // 32
#define WMAX_ ((LC_ + 1) * CS_)     // 80
#define QKVN_ (3 * D_)              // 1536
#define PALLN_ (L_ * D_)            // 3072

// ---------------- scratch (device globals; no allocation) ----------------
__device__ float  g_x   [B_*T_*D_];
__device__ float  g_qkv [B_*T_*QKVN_];
__device__ float  g_o   [B_*T_*D_];
__device__ float  g_ff  [B_*T_*FF_];
__device__ float  g_pall[T_*PALLN_];
__device__ float  g_bqkv[L_*QKVN_];
__device__ float2 g_st  [B_*T_];

// transposed + split weights: Wt[n][k]
__device__ __half g_wqkvh[L_*QKVN_*D_], g_wqkvl[L_*QKVN_*D_];
__device__ __half g_woh[L_*D_*D_],  g_wol[L_*D_*D_];
__device__ __half g_wph[L_*D_*D_],  g_wpl[L_*D_*D_];
__device__ __half g_w1h[L_*D_*FF_], g_w1l[L_*D_*FF_];
__device__ __half g_w2h[L_*FF_*D_], g_w2l[L_*FF_*D_];

// ---------------- PTX helpers (family-portable: sm_80+ ISA only) ----------
__device__ __forceinline__ uint32_t s2u(const void* p) {
    uint32_t a;
    asm("{ .reg .u64 t; cvta.to.shared.u64 t, %1; cvt.u32.u64 %0, t; }" : "=r"(a) : "l"(p));
    return a;
}

#define CPA16(sa, g) \
    asm volatile("cp.async.cg.shared.global [%0], [%1], 16;" :: "r"(sa), "l"(g) : "memory")
#define CPCOMMIT() asm volatile("cp.async.commit_group;" ::: "memory")
#define CPWAIT(n)  asm volatile("cp.async.wait_group %0;" :: "n"(n) : "memory")

#define LDSM4(d0, d1, d2, d3, a) \
    asm volatile("ldmatrix.sync.aligned.m8n8.x4.shared.b16 {%0,%1,%2,%3}, [%4];" \
        : "=r"(d0), "=r"(d1), "=r"(d2), "=r"(d3) : "r"(a))

#define MMA16816(c, a, b0, b1) \
    asm volatile("mma.sync.aligned.m16n8k16.row.col.f32.f16.f16.f32 " \
        "{%0,%1,%2,%3}, {%4,%5,%6,%7}, {%8,%9}, {%0,%1,%2,%3};" \
        : "+f"((c)[0]), "+f"((c)[1]), "+f"((c)[2]), "+f"((c)[3]) \
        : "r"((a)[0]), "r"((a)[1]), "r"((a)[2]), "r"((a)[3]), "r"(b0), "r"(b1))

__device__ __forceinline__ void split_h(float v, __half& hi, __half& lo) {
    hi = __float2half_rn(v);
    lo = __float2half_rn(v - __half2float(hi));
}
__device__ __forceinline__ uint32_t pack2(__half a, __half b) {
    __half2 t = __halves2half2(a, b);
    return *reinterpret_cast<uint32_t*>(&t);
}
__device__ __forceinline__ float4 ld4h(const __half* p) {
    uint2 u = *(const uint2*)p;
    __half2 a = *reinterpret_cast<__half2*>(&u.x);
    __half2 b = *reinterpret_cast<__half2*>(&u.y);
    float2 fa = __half22float2(a), fb = __half22float2(b);
    return make_float4(fa.x, fa.y, fb.x, fb.y);
}
__device__ __forceinline__ float dot4(float4 a, float4 b) {
    return a.x * b.x + a.y * b.y + a.z * b.z + a.w * b.w;
}

// ---------------- elementwise scale: x = xs * sqrt(D) ----------------
__global__ void scale_kernel(const float* __restrict__ xs, float s) {
    int i = blockIdx.x * blockDim.x + threadIdx.x;
    g_x[i] = xs[i] * s;
}

// ---------------- bias concat for fused QKV ----------------
__global__ void bcat_kernel(const float* __restrict__ bq, const float* __restrict__ bk,
                            const float* __restrict__ bv) {
    int i = blockIdx.x * blockDim.x + threadIdx.x;   // L*1536
    int l = i / QKVN_, c = i % QKVN_;
    float v = (c < D_) ? bq[l * D_ + c]
            : (c < 2 * D_) ? bk[l * D_ + c - D_]
            : bv[l * D_ + c - 2 * D_];
    g_bqkv[i] = v;
}

// ---------------- merged QKV weight transpose+split ----------------
__global__ void wtransqkv_kernel(const float* __restrict__ Wq,
                                 const float* __restrict__ Wk,
                                 const float* __restrict__ Wv,
                                 __half* __restrict__ Th, __half* __restrict__ Tl) {
    __shared__ float sm[32][33];
    int z = blockIdx.z;
    int which = z / L_, l = z % L_;
    const size_t DD = (size_t)D_ * D_;
    const float* Wl = (which == 0 ? Wq : which == 1 ? Wk : Wv) + (size_t)l * DD;
    size_t dOff = (size_t)l * QKVN_ * D_ + (size_t)which * DD;
    __half* Thl = Th + dOff;
    __half* Tll = Tl + dOff;
    int n0 = blockIdx.x * 32, k0 = blockIdx.y * 32;
    int tx = threadIdx.x, ty = threadIdx.y;
    #pragma unroll
    for (int j = 0; j < 4; j++)
        sm[ty + j * 8][tx] = Wl[(size_t)(k0 + ty + j * 8) * D_ + n0 + tx];
    __syncthreads();
    #pragma unroll
    for (int j = 0; j < 4; j++) {
        int n = ty + j * 8;
        float v = sm[tx][n];
        __half h, l2;
        split_h(v, h, l2);
        size_t o = (size_t)(n0 + n) * D_ + k0 + tx;
        Thl[o] = h; Tll[o] = l2;
    }
}

// ---------------- generic weight transpose + split ----------------
__global__ void wtrans_kernel(const float* __restrict__ W,
                              __half* __restrict__ Th, __half* __restrict__ Tl,
                              int K, int N, size_t srcLS, size_t dstLS) {
    __shared__ float sm[32][33];
    const float* Wl = W + (size_t)blockIdx.z * srcLS;
    __half* Thl = Th + (size_t)blockIdx.z * dstLS;
    __half* Tll = Tl + (size_t)blockIdx.z * dstLS;
    int n0 = blockIdx.x * 32, k0 = blockIdx.y * 32;
    int tx = threadIdx.x, ty = threadIdx.y;
    #pragma unroll
    for (int j = 0; j < 4; j++)
        sm[ty + j * 8][tx] = Wl[(size_t)(k0 + ty + j * 8) * N + n0 + tx];
    __syncthreads();
    #pragma unroll
    for (int j = 0; j < 4; j++) {
        int n = ty + j * 8;
        float v = sm[tx][n];
        __half h, l;
        split_h(v, h, l);
        size_t o = (size_t)(n0 + n) * K + k0 + tx;
        Thl[o] = h; Tll[o] = l;
    }
}

// ---------------- LN stats: one warp per row, float4 loads ----------------
__global__ void lnstats_kernel(const float* __restrict__ in, float2* __restrict__ st) {
    int warp = threadIdx.x >> 5, lane = threadIdx.x & 31;
    int row = blockIdx.x * 8 + warp;
    const float4* x = (const float4*)(in + (size_t)row * D_);
    float s = 0.0f, ss = 0.0f;
    #pragma unroll
    for (int j = 0; j < 4; j++) {
        float4 v = x[lane + j * 32];
        s  += v.x + v.y + v.z + v.w;
        ss += v.x * v.x + v.y * v.y + v.z * v.z + v.w * v.w;
    }
    #pragma unroll
    for (int off = 16; off; off >>= 1) {
        s  += __shfl_xor_sync(0xffffffffu, s,  off);
        ss += __shfl_xor_sync(0xffffffffu, ss, off);
    }
    if (lane == 0) {
        float mean = s * (1.0f / D_);
        float var  = ss * (1.0f / D_) - mean * mean;
        st[row] = make_float2(mean, rsqrtf(var + 1e-5f));
    }
}

// ---------------- final LN ----------------
__global__ void ln_kernel(const float* __restrict__ in, float* __restrict__ out,
                          const float* __restrict__ gam, const float* __restrict__ bet) {
    __shared__ float sh_s[8], sh_ss[8];
    int row = blockIdx.x, tid = threadIdx.x;
    const float* x = in + (size_t)row * D_;
    float v0 = x[tid], v1 = x[tid + 256];
    float s = v0 + v1, ss = v0 * v0 + v1 * v1;
    int lane = tid & 31, warp = tid >> 5;
    #pragma unroll
    for (int off = 16; off; off >>= 1) {
        s  += __shfl_xor_sync(0xffffffffu, s,  off);
        ss += __shfl_xor_sync(0xffffffffu, ss, off);
    }
    if (lane == 0) { sh_s[warp] = s; sh_ss[warp] = ss; }
    __syncthreads();
    if (warp == 0) {
        float a = (lane < 8) ? sh_s[lane]  : 0.0f;
        float b = (lane < 8) ? sh_ss[lane] : 0.0f;
        #pragma unroll
        for (int off = 4; off; off >>= 1) {
            a += __shfl_xor_sync(0xffffffffu, a, off);
            b += __shfl_xor_sync(0xffffffffu, b, off);
        }
        if (lane == 0) { sh_s[0] = a; sh_ss[0] = b; }
    }
    __syncthreads();
    float mean = sh_s[0] * (1.0f / D_);
    float var  = sh_ss[0] * (1.0f / D_) - mean * mean;
    float inv  = rsqrtf(var + 1e-5f);
    float* y = out + (size_t)row * D_;
    y[tid]       = (v0 - mean) * inv * gam[tid]       + bet[tid];
    y[tid + 256] = (v1 - mean) * inv * gam[tid + 256] + bet[tid + 256];
}

// ---------------- HMMA fp16x2 GEMM: Ah·(Bh+Bl), fused LN on A -------------
// A rounded once to fp16 (activations); W kept split hi/lo (exact 2^-22).
// BM=128, BN=128, BK=32; 8 warps (2x4), warp tile 64x32.
// Stage = Ah(8KB) + Bh(8KB) + Bl(8KB) = 24KB; 3 stages, 2 CTAs/SM.
#define STAGE_BYTES 24576
#define NSTG 3
__global__ void __launch_bounds__(256, 2)
gemm_f32a(const float* __restrict__ A, const float2* __restrict__ stats,
          const float* __restrict__ gam, const float* __restrict__ bet,
          const __half* __restrict__ Bh, const __half* __restrict__ Bl,
          const float* __restrict__ bias, const float* __restrict__ res,
          float* __restrict__ outF, int N, int K, int relu) {
    extern __shared__ char smem[];
    uint32_t sb = s2u(smem);
    int tid = threadIdx.x, lane = tid & 31, wid = tid >> 5;
    int wm = wid >> 2, wn = wid & 3;
    int rowBase = blockIdx.y * 128, colBase = blockIdx.x * 128;
    int sub = lane & 7, grp = lane >> 3;

    float acc[4][4][4];
    #pragma unroll
    for (int i = 0; i < 4; i++)
        #pragma unroll
        for (int j = 0; j < 4; j++)
            #pragma unroll
            for (int c = 0; c < 4; c++) acc[i][j][c] = 0.0f;

    const int NC = K >> 5;

    float aR[2][8];
    float2 stR[2];
    #pragma unroll
    for (int i = 0; i < 2; i++) {
        int id = tid + (i << 8);
        int row = id >> 2;
        stR[i] = stats ? stats[rowBase + row] : make_float2(0.0f, 1.0f);
    }

    auto ldgA = [&](int c) {
        int k0 = c << 5;
        #pragma unroll
        for (int i = 0; i < 2; i++) {
            int id = tid + (i << 8);
            int row = id >> 2, ch = id & 3;
            const float* g = A + (size_t)(rowBase + row) * K + k0 + ch * 8;
            float4 u = *(const float4*)g;
            float4 v = *(const float4*)(g + 4);
            aR[i][0] = u.x; aR[i][1] = u.y; aR[i][2] = u.z; aR[i][3] = u.w;
            aR[i][4] = v.x; aR[i][5] = v.y; aR[i][6] = v.z; aR[i][7] = v.w;
        }
    };

    auto stsA = [&](int c, int buf) {
        int k0 = c << 5;
        #pragma unroll
        for (int i = 0; i < 2; i++) {
            int id = tid + (i << 8);
            int row = id >> 2, ch = id & 3;
            float y[8];
            if (gam) {
                float mean = stR[i].x, inv = stR[i].y;
                const float* gg = gam + k0 + ch * 8;
                const float* bb = bet + k0 + ch * 8;
                float4 g0 = *(const float4*)gg, g1 = *(const float4*)(gg + 4);
                float4 b0 = *(const float4*)bb, b1 = *(const float4*)(bb + 4);
                y[0] = (aR[i][0] - mean) * inv * g0.x + b0.x;
                y[1] = (aR[i][1] - mean) * inv * g0.y + b0.y;
                y[2] = (aR[i][2] - mean) * inv * g0.z + b0.z;
                y[3] = (aR[i][3] - mean) * inv * g0.w + b0.w;
                y[4] = (aR[i][4] - mean) * inv * g1.x + b1.x;
                y[5] = (aR[i][5] - mean) * inv * g1.y + b1.y;
                y[6] = (aR[i][6] - mean) * inv * g1.z + b1.z;
                y[7] = (aR[i][7] - mean) * inv * g1.w + b1.w;
            } else {
                #pragma unroll
                for (int j = 0; j < 8; j++) y[j] = aR[i][j];
            }
            int phys = ch ^ ((row >> 1) & 3);
            uint32_t rel = (uint32_t)(buf * STAGE_BYTES) + row * 64 + phys * 16;
            uint4 wh;
            wh.x = pack2(__float2half_rn(y[0]), __float2half_rn(y[1]));
            wh.y = pack2(__float2half_rn(y[2]), __float2half_rn(y[3]));
            wh.z = pack2(__float2half_rn(y[4]), __float2half_rn(y[5]));
            wh.w = pack2(__float2half_rn(y[6]), __float2half_rn(y[7]));
            *(uint4*)(smem + rel) = wh;
        }
    };

    auto loadB = [&](int c, int buf) {
        uint32_t sbase = sb + buf * STAGE_BYTES + 8192u;
        int k0 = c << 5;
        #pragma unroll
        for (int i = 0; i < 2; i++) {
            int id = tid + (i << 8);
            int row = id >> 2, ch = id & 3;
            int phys = ch ^ ((row >> 1) & 3);
            uint32_t so = sbase + row * 64 + phys * 16;
            CPA16(so,          Bh + (size_t)(colBase + row) * K + k0 + ch * 8);
            CPA16(so + 8192u,  Bl + (size_t)(colBase + row) * K + k0 + ch * 8);
        }
    };

    auto compute = [&](int buf) {
        uint32_t base = sb + buf * STAGE_BYTES;
        #pragma unroll
        for (int ks = 0; ks < 2; ks++) {
            uint32_t ahf[4][4], bhf[4][2], blf[4][2];
            #pragma unroll
            for (int mi = 0; mi < 4; mi++) {
                int row = wm * 64 + mi * 16 + sub + (grp & 1) * 8;
                int ci = 2 * ks + (grp >> 1);
                uint32_t ad = base + row * 64 + ((ci ^ ((row >> 1) & 3)) * 16);
                LDSM4(ahf[mi][0], ahf[mi][1], ahf[mi][2], ahf[mi][3], ad);
            }
            #pragma unroll
            for (int g = 0; g < 2; g++) {
                int row = wn * 32 + g * 16 + sub + (grp & 1) * 8;
                int ci = 2 * ks + (grp >> 1);
                uint32_t ad = base + 8192u + row * 64 + ((ci ^ ((row >> 1) & 3)) * 16);
                uint32_t r0, r1, r2, r3;
                LDSM4(r0, r1, r2, r3, ad);
                bhf[2*g][0] = r0; bhf[2*g+1][0] = r1; bhf[2*g][1] = r2; bhf[2*g+1][1] = r3;
                LDSM4(r0, r1, r2, r3, ad + 8192u);
                blf[2*g][0] = r0; blf[2*g+1][0] = r1; blf[2*g][1] = r2; blf[2*g+1][1] = r3;
            }
            #pragma unroll
            for (int mi = 0; mi < 4; mi++)
                #pragma unroll
                for (int nj = 0; nj < 4; nj++)
                    MMA16816(acc[mi][nj], ahf[mi], bhf[nj][0], bhf[nj][1]);
            #pragma unroll
            for (int mi = 0; mi < 4; mi++)
                #pragma unroll
                for (int nj = 0; nj < 4; nj++)
                    MMA16816(acc[mi][nj], ahf[mi], blf[nj][0], blf[nj][1]);
        }
    };

    // prologue: stages 0 and 1
    ldgA(0); stsA(0, 0); loadB(0, 0); CPCOMMIT();
    if (NC > 1) { ldgA(1); stsA(1, 1); loadB(1, 1); }
    CPCOMMIT();
    #pragma unroll 1
    for (int c = 0; c < NC; c++) {
        int nxt = c + 2;
        int nb = nxt % NSTG;
        if (nxt < NC) ldgA(nxt);           // LDG in flight over the wait
        CPWAIT(1);                          // stage c complete (c+1 may fly)
        __syncthreads();
        if (nxt < NC) loadB(nxt, nb);
        CPCOMMIT();
        if (nxt < NC) stsA(nxt, nb);
        compute(c % NSTG);
    }

    // --- epilogue (fp32 out) ---
    #pragma unroll
    for (int mi = 0; mi < 4; mi++) {
        #pragma unroll
        for (int nj = 0; nj < 4; nj++) {
            int r = rowBase + wm * 64 + mi * 16 + (lane >> 2);
            int c = colBase + wn * 32 + nj * 8 + ((lane & 3) << 1);
            #pragma unroll
            for (int half_ : {0, 1}) {
                int rr = r + half_ * 8;
                float v0 = acc[mi][nj][half_ * 2 + 0];
                float v1 = acc[mi][nj][half_ * 2 + 1];
                if (bias) { v0 += bias[c]; v1 += bias[c + 1]; }
                if (res) {
                    float2 rv = *(const float2*)(res + (size_t)rr * N + c);
                    v0 += rv.x; v1 += rv.y;
                }
                if (relu) { v0 = fmaxf(v0, 0.0f); v1 = fmaxf(v1, 0.0f); }
                *(float2*)(outF + (size_t)rr * N + c) = make_float2(v0, v1);
            }
        }
    }
}

// ---------------- Chunked local attention (fp16 scores path, fp32 out) -----
__global__ void attn_kernel(const float* __restrict__ qkv, const float* __restrict__ p,
                            const float* __restrict__ pbu, const float* __restrict__ pbv,
                            float* __restrict__ o) {
    int ci = blockIdx.x, h = blockIdx.y, b = blockIdx.z;
    int s0 = max((ci - LC_) * CS_, 0);
    int s1 = (ci + 1) * CS_;
    int W = s1 - s0;
    int t0 = ci * CS_;
    int tid = threadIdx.x;                    // 256 threads

    extern __shared__ char asmem[];
    __half* Ks = (__half*)asmem;              // WMAX*64 halves
    __half* Ps = Ks + WMAX_ * 64;
    __half* QU = Ps + WMAX_ * 64;             // 16*64
    __half* QV = QU + 16 * 64;
    float* Vs = (float*)(QV + 16 * 64);       // WMAX*64 floats
    float* SC = Vs + WMAX_ * 64;              // 16*WMAX

    for (int idx = tid; idx < W * 64; idx += 256) {
        int s = idx >> 6, d = idx & 63;
        size_t gi = (size_t)((b * T_) + s0 + s) * QKVN_ + h * DK_ + d;
        Ks[idx] = __float2half(qkv[gi + D_]);
        Vs[idx] = qkv[gi + 2 * D_];
        Ps[idx] = __float2half(p[(size_t)(s0 + s) * PALLN_ + h * DK_ + d]);
    }
    for (int idx = tid; idx < 16 * 64; idx += 256) {
        int qi = idx >> 6, d = idx & 63;
        float qv_ = qkv[(size_t)((b * T_) + t0 + qi) * QKVN_ + h * DK_ + d];
        QU[idx] = __float2half(qv_ + pbu[h * DK_ + d]);
        QV[idx] = __float2half(qv_ + pbv[h * DK_ + d]);
    }
    __syncthreads();

    const float scale = 0.125f;
    int Wh = W >> 1;
    for (int it = tid; it < 8 * Wh; it += 256) {
        int qi = (it / Wh) * 2, s = (it % Wh) * 2;
        float a00 = 0, a01 = 0, a10 = 0, a11 = 0;
        #pragma unroll 4
        for (int d = 0; d < 64; d += 4) {
            float4 qu0 = ld4h(&QU[qi * 64 + d]);
            float4 qu1 = ld4h(&QU[(qi + 1) * 64 + d]);
            float4 qv0 = ld4h(&QV[qi * 64 + d]);
            float4 qv1 = ld4h(&QV[(qi + 1) * 64 + d]);
            float4 k0 = ld4h(&Ks[s * 64 + d]);
            float4 k1 = ld4h(&Ks[(s + 1) * 64 + d]);
            float4 p0 = ld4h(&Ps[s * 64 + d]);
            float4 p1 = ld4h(&Ps[(s + 1) * 64 + d]);
            a00 += dot4(qu0, k0) + dot4(qv0, p0);
            a01 += dot4(qu0, k1) + dot4(qv0, p1);
            a10 += dot4(qu1, k0) + dot4(qv1, p0);
            a11 += dot4(qu1, k1) + dot4(qv1, p1);
        }
        SC[qi * WMAX_ + s]           = a00 * scale;
        SC[qi * WMAX_ + s + 1]       = a01 * scale;
        SC[(qi + 1) * WMAX_ + s]     = a10 * scale;
        SC[(qi + 1) * WMAX_ + s + 1] = a11 * scale;
    }
    __syncthreads();

    int warp = tid >> 5, lane = tid & 31;
    for (int qi = warp; qi < 16; qi += 8) {
        float m = -1e30f;
        for (int s = lane; s < W; s += 32) m = fmaxf(m, SC[qi * WMAX_ + s]);
        #pragma unroll
        for (int off = 16; off; off >>= 1) m = fmaxf(m, __shfl_xor_sync(0xffffffffu, m, off));
        float sum = 0.0f;
        for (int s = lane; s < W; s += 32) {
            float e = expf(SC[qi * WMAX_ + s] - m);
            SC[qi * WMAX_ + s] = e;
            sum += e;
        }
        #pragma unroll
        for (int off = 16; off; off >>= 1) sum += __shfl_xor_sync(0xffffffffu, sum, off);
        float inv = 1.0f / sum;
        for (int s = lane; s < W; s += 32) SC[qi * WMAX_ + s] *= inv;
    }
    __syncthreads();

    {
        int it = tid;                       // 8 * 32 = 256
        int qi = (it >> 5) * 2, d = (it & 31) * 2;
        float a00 = 0, a01 = 0, a10 = 0, a11 = 0;
        for (int s = 0; s < W; s++) {
            float2 vv = *(const float2*)&Vs[s * 64 + d];
            float c0 = SC[qi * WMAX_ + s];
            float c1 = SC[(qi + 1) * WMAX_ + s];
            a00 += c0 * vv.x; a01 += c0 * vv.y;
            a10 += c1 * vv.x; a11 += c1 * vv.y;
        }
        size_t o0 = (size_t)((b * T_) + t0 + qi) * D_ + h * DK_ + d;
        *(float2*)(o + o0)      = make_float2(a00, a01);
        *(float2*)(o + o0 + D_) = make_float2(a10, a11);
    }
}

static const int ATTN_SMEM = (WMAX_*64*2 + 16*64*2) * 2 + (WMAX_*64 + 16*WMAX_) * 4; // 50176
static const int GEMM_SMEM = NSTG * STAGE_BYTES;   // 73728

extern "C" void kernel_launch(void* const* d_in, const int* in_sizes, int n_in,
                              void* d_out, int out_size) {
    (void)in_sizes; (void)n_in; (void)out_size;
    const float* xs    = (const float*)d_in[0];
    const float* pos   = (const float*)d_in[1];
    // d_in[2] = mask: unused (window computed analytically)
    const float* Wq    = (const float*)d_in[3];
    const float* bq    = (const float*)d_in[4];
    const float* Wk    = (const float*)d_in[5];
    const float* bk    = (const float*)d_in[6];
    const float* Wv    = (const float*)d_in[7];
    const float* bv    = (const float*)d_in[8];
    const float* Wo    = (const float*)d_in[9];
    const float* bo    = (const float*)d_in[10];
    const float* Wp    = (const float*)d_in[11];
    const float* pbu   = (const float*)d_in[12];
    const float* pbv   = (const float*)d_in[13];
    const float* ln1s  = (const float*)d_in[14];
    const float* ln1b  = (const float*)d_in[15];
    const float* ln2s  = (const float*)d_in[16];
    const float* ln2b  = (const float*)d_in[17];
    const float* W1    = (const float*)d_in[18];
    const float* b1    = (const float*)d_in[19];
    const float* W2    = (const float*)d_in[20];
    const float* b2    = (const float*)d_in[21];
    const float* lnfs  = (const float*)d_in[22];
    const float* lnfb  = (const float*)d_in[23];

    cudaFuncSetAttribute(attn_kernel, cudaFuncAttributeMaxDynamicSharedMemorySize, ATTN_SMEM);
    cudaFuncSetAttribute(gemm_f32a,   cudaFuncAttributeMaxDynamicSharedMemorySize, GEMM_SMEM);

    void* a;
    #define SYM(p, s) cudaGetSymbolAddress(&a, s); auto* p = (decltype(&s[0]))a;
    SYM(px, g_x)  SYM(pqkv, g_qkv)  SYM(po, g_o)  SYM(pff, g_ff)
    SYM(ppall, g_pall)  SYM(pbqkv, g_bqkv)  SYM(pst, g_st)
    SYM(pwqkvh, g_wqkvh) SYM(pwqkvl, g_wqkvl)
    SYM(pwoh, g_woh) SYM(pwol, g_wol)
    SYM(pwph, g_wph) SYM(pwpl, g_wpl)
    SYM(pw1h, g_w1h) SYM(pw1l, g_w1l)
    SYM(pw2h, g_w2h) SYM(pw2l, g_w2l)
    #undef SYM

    const int M = B_ * T_;  // 4096
    const size_t DD = (size_t)D_ * D_;          // 262144
    const size_t QKVLS = (size_t)QKVN_ * D_;    // 786432
    dim3 wtb(32, 8);

    scale_kernel<<<(B_*T_*D_) / 256, 256>>>(xs, sqrtf((float)D_));
    bcat_kernel<<<(L_*QKVN_) / 256, 256>>>(bq, bk, bv);
    wtransqkv_kernel<<<dim3(16, 16, 3 * L_), wtb>>>(Wq, Wk, Wv, pwqkvh, pwqkvl);
    lnstats_kernel<<<M / 8, 256>>>(px, pst);
    wtrans_kernel<<<dim3(D_/32, D_/32, L_), wtb>>>(Wo, pwoh, pwol, D_, D_, DD, DD);
    // layer-0 fused QKV GEMM early (profiling target position)
    gemm_f32a<<<dim3(QKVN_/128, M/128), 256, GEMM_SMEM>>>(px, pst,
        ln1s, ln1b, pwqkvh, pwqkvl, pbqkv, nullptr, pqkv, QKVN_, D_, 0);
    // remaining prep
    wtrans_kernel<<<dim3(D_/32,  D_/32,  L_), wtb>>>(Wp, pwph, pwpl, D_,  D_,  DD, DD);
    wtrans_kernel<<<dim3(FF_/32, D_/32,  L_), wtb>>>(W1, pw1h, pw1l, D_,  FF_, (size_t)D_*FF_, (size_t)D_*FF_);
    wtrans_kernel<<<dim3(D_/32,  FF_/32, L_), wtb>>>(W2, pw2h, pw2l, FF_, D_,  (size_t)FF_*D_, (size_t)FF_*D_);
    gemm_f32a<<<dim3(PALLN_/128, T_/128), 256, GEMM_SMEM>>>(pos, nullptr, nullptr, nullptr,
        pwph, pwpl, nullptr, nullptr, ppall, PALLN_, D_, 0);

    for (int l = 0; l < L_; l++) {
        size_t wdf = (size_t)l * D_ * FF_;

        if (l > 0) {
            lnstats_kernel<<<M / 8, 256>>>(px, pst);
            gemm_f32a<<<dim3(QKVN_/128, M/128), 256, GEMM_SMEM>>>(px, pst,
                ln1s + l*D_, ln1b + l*D_,
                pwqkvh + l * QKVLS, pwqkvl + l * QKVLS,
                pbqkv + l * QKVN_, nullptr, pqkv, QKVN_, D_, 0);
        }

        // attention -> o fp32
        attn_kernel<<<dim3(NCHUNK_, H_, B_), 256, ATTN_SMEM>>>(
            pqkv, ppall + l * D_, pbu + l * H_ * DK_, pbv + l * H_ * DK_, po);

        // x = x + o @ Wo + bo
        gemm_f32a<<<dim3(D_/128, M/128), 256, GEMM_SMEM>>>(po, nullptr, nullptr, nullptr,
            pwoh + l * DD, pwol + l * DD,
            bo + l*D_, px, px, D_, D_, 0);

        // row stats for LN2
        lnstats_kernel<<<M / 8, 256>>>(px, pst);

        // ff = relu(LN2(x) @ W1 + b1)
        gemm_f32a<<<dim3(FF_/128, M/128), 256, GEMM_SMEM>>>(px, pst,
            ln2s + l*D_, ln2b + l*D_,
            pw1h + wdf, pw1l + wdf,
            b1 + l*FF_, nullptr, pff, FF_, D_, 1);

        // x = x + ff @ W2 + b2
        gemm_f32a<<<dim3(D_/128, M/128), 256, GEMM_SMEM>>>(pff, nullptr, nullptr, nullptr,
            pw2h + wdf, pw2l + wdf,
            b2 + l*D_, px, px, D_, FF_, 0);
    }

    // out = LNf(x)  (fp32)
    ln_kernel<<<M, 256>>>(px, (float*)d_out, lnfs, lnfb);
}

// round 10
// speedup vs baseline: 2.2354x; 1.2328x over previous
#include <cuda_runtime.h>
#include <cuda_fp16.h>
#include <math.h>
#include <stdint.h>

// Problem constants
#define B_  8
#define T_  512
#define D_  512
#define H_  8
#define FF_ 2048
#define L_  6
#define CS_ 16
#define LC_ 4
#define DK_ 64
#define NCHUNK_ (T_ / CS_)          // 32
#define WMAX_ ((LC_ + 1) * CS_)     // 80
#define QKVN_ (3 * D_)              // 1536
#define PALLN_ (L_ * D_)            // 3072

// ---------------- scratch (device globals; no allocation) ----------------
__device__ float  g_x   [B_*T_*D_];
__device__ float  g_qkv [B_*T_*QKVN_];
__device__ float  g_o   [B_*T_*D_];
__device__ float  g_ff  [B_*T_*FF_];
__device__ float  g_pall[T_*PALLN_];
__device__ float  g_bqkv[L_*QKVN_];
__device__ float2 g_st  [B_*T_];

// transposed fp16 weights: Wt[n][k] (round-to-nearest)
__device__ __half g_wqkvh[L_*QKVN_*D_];
__device__ __half g_woh[L_*D_*D_];
__device__ __half g_wph[L_*D_*D_];
__device__ __half g_w1h[L_*D_*FF_];
__device__ __half g_w2h[L_*FF_*D_];

// ---------------- PTX helpers (family-portable: sm_80+ ISA only) ----------
__device__ __forceinline__ uint32_t s2u(const void* p) {
    uint32_t a;
    asm("{ .reg .u64 t; cvta.to.shared.u64 t, %1; cvt.u32.u64 %0, t; }" : "=r"(a) : "l"(p));
    return a;
}

#define CPA16(sa, g) \
    asm volatile("cp.async.cg.shared.global [%0], [%1], 16;" :: "r"(sa), "l"(g) : "memory")
#define CPCOMMIT() asm volatile("cp.async.commit_group;" ::: "memory")
#define CPWAIT(n)  asm volatile("cp.async.wait_group %0;" :: "n"(n) : "memory")

#define LDSM4(d0, d1, d2, d3, a) \
    asm volatile("ldmatrix.sync.aligned.m8n8.x4.shared.b16 {%0,%1,%2,%3}, [%4];" \
        : "=r"(d0), "=r"(d1), "=r"(d2), "=r"(d3) : "r"(a))

#define MMA16816(c, a, b0, b1) \
    asm volatile("mma.sync.aligned.m16n8k16.row.col.f32.f16.f16.f32 " \
        "{%0,%1,%2,%3}, {%4,%5,%6,%7}, {%8,%9}, {%0,%1,%2,%3};" \
        : "+f"((c)[0]), "+f"((c)[1]), "+f"((c)[2]), "+f"((c)[3]) \
        : "r"((a)[0]), "r"((a)[1]), "r"((a)[2]), "r"((a)[3]), "r"(b0), "r"(b1))

__device__ __forceinline__ uint32_t pack2(__half a, __half b) {
    __half2 t = __halves2half2(a, b);
    return *reinterpret_cast<uint32_t*>(&t);
}
__device__ __forceinline__ float4 ld4h(const __half* p) {
    uint2 u = *(const uint2*)p;
    __half2 a = *reinterpret_cast<__half2*>(&u.x);
    __half2 b = *reinterpret_cast<__half2*>(&u.y);
    float2 fa = __half22float2(a), fb = __half22float2(b);
    return make_float4(fa.x, fa.y, fb.x, fb.y);
}
__device__ __forceinline__ float dot4(float4 a, float4 b) {
    return a.x * b.x + a.y * b.y + a.z * b.z + a.w * b.w;
}

// ---------------- elementwise scale: x = xs * sqrt(D) ----------------
__global__ void scale_kernel(const float* __restrict__ xs, float s) {
    int i = blockIdx.x * blockDim.x + threadIdx.x;
    g_x[i] = xs[i] * s;
}

// ---------------- bias concat for fused QKV ----------------
__global__ void bcat_kernel(const float* __restrict__ bq, const float* __restrict__ bk,
                            const float* __restrict__ bv) {
    int i = blockIdx.x * blockDim.x + threadIdx.x;   // L*1536
    int l = i / QKVN_, c = i % QKVN_;
    float v = (c < D_) ? bq[l * D_ + c]
            : (c < 2 * D_) ? bk[l * D_ + c - D_]
            : bv[l * D_ + c - 2 * D_];
    g_bqkv[i] = v;
}

// ---------------- merged QKV weight transpose (fp16 rn) ----------------
__global__ void wtransqkv_kernel(const float* __restrict__ Wq,
                                 const float* __restrict__ Wk,
                                 const float* __restrict__ Wv,
                                 __half* __restrict__ Th) {
    __shared__ float sm[32][33];
    int z = blockIdx.z;
    int which = z / L_, l = z % L_;
    const size_t DD = (size_t)D_ * D_;
    const float* Wl = (which == 0 ? Wq : which == 1 ? Wk : Wv) + (size_t)l * DD;
    __half* Thl = Th + (size_t)l * QKVN_ * D_ + (size_t)which * DD;
    int n0 = blockIdx.x * 32, k0 = blockIdx.y * 32;
    int tx = threadIdx.x, ty = threadIdx.y;
    #pragma unroll
    for (int j = 0; j < 4; j++)
        sm[ty + j * 8][tx] = Wl[(size_t)(k0 + ty + j * 8) * D_ + n0 + tx];
    __syncthreads();
    #pragma unroll
    for (int j = 0; j < 4; j++) {
        int n = ty + j * 8;
        Thl[(size_t)(n0 + n) * D_ + k0 + tx] = __float2half_rn(sm[tx][n]);
    }
}

// ---------------- generic weight transpose (fp16 rn) ----------------
__global__ void wtrans_kernel(const float* __restrict__ W, __half* __restrict__ Th,
                              int K, int N, size_t srcLS, size_t dstLS) {
    __shared__ float sm[32][33];
    const float* Wl = W + (size_t)blockIdx.z * srcLS;
    __half* Thl = Th + (size_t)blockIdx.z * dstLS;
    int n0 = blockIdx.x * 32, k0 = blockIdx.y * 32;
    int tx = threadIdx.x, ty = threadIdx.y;
    #pragma unroll
    for (int j = 0; j < 4; j++)
        sm[ty + j * 8][tx] = Wl[(size_t)(k0 + ty + j * 8) * N + n0 + tx];
    __syncthreads();
    #pragma unroll
    for (int j = 0; j < 4; j++) {
        int n = ty + j * 8;
        Thl[(size_t)(n0 + n) * K + k0 + tx] = __float2half_rn(sm[tx][n]);
    }
}

// ---------------- LN stats: one warp per row, float4 loads ----------------
__global__ void lnstats_kernel(const float* __restrict__ in, float2* __restrict__ st) {
    int warp = threadIdx.x >> 5, lane = threadIdx.x & 31;
    int row = blockIdx.x * 8 + warp;
    const float4* x = (const float4*)(in + (size_t)row * D_);
    float s = 0.0f, ss = 0.0f;
    #pragma unroll
    for (int j = 0; j < 4; j++) {
        float4 v = x[lane + j * 32];
        s  += v.x + v.y + v.z + v.w;
        ss += v.x * v.x + v.y * v.y + v.z * v.z + v.w * v.w;
    }
    #pragma unroll
    for (int off = 16; off; off >>= 1) {
        s  += __shfl_xor_sync(0xffffffffu, s,  off);
        ss += __shfl_xor_sync(0xffffffffu, ss, off);
    }
    if (lane == 0) {
        float mean = s * (1.0f / D_);
        float var  = ss * (1.0f / D_) - mean * mean;
        st[row] = make_float2(mean, rsqrtf(var + 1e-5f));
    }
}

// ---------------- final LN ----------------
__global__ void ln_kernel(const float* __restrict__ in, float* __restrict__ out,
                          const float* __restrict__ gam, const float* __restrict__ bet) {
    __shared__ float sh_s[8], sh_ss[8];
    int row = blockIdx.x, tid = threadIdx.x;
    const float* x = in + (size_t)row * D_;
    float v0 = x[tid], v1 = x[tid + 256];
    float s = v0 + v1, ss = v0 * v0 + v1 * v1;
    int lane = tid & 31, warp = tid >> 5;
    #pragma unroll
    for (int off = 16; off; off >>= 1) {
        s  += __shfl_xor_sync(0xffffffffu, s,  off);
        ss += __shfl_xor_sync(0xffffffffu, ss, off);
    }
    if (lane == 0) { sh_s[warp] = s; sh_ss[warp] = ss; }
    __syncthreads();
    if (warp == 0) {
        float a = (lane < 8) ? sh_s[lane]  : 0.0f;
        float b = (lane < 8) ? sh_ss[lane] : 0.0f;
        #pragma unroll
        for (int off = 4; off; off >>= 1) {
            a += __shfl_xor_sync(0xffffffffu, a, off);
            b += __shfl_xor_sync(0xffffffffu, b, off);
        }
        if (lane == 0) { sh_s[0] = a; sh_ss[0] = b; }
    }
    __syncthreads();
    float mean = sh_s[0] * (1.0f / D_);
    float var  = sh_ss[0] * (1.0f / D_) - mean * mean;
    float inv  = rsqrtf(var + 1e-5f);
    float* y = out + (size_t)row * D_;
    y[tid]       = (v0 - mean) * inv * gam[tid]       + bet[tid];
    y[tid + 256] = (v1 - mean) * inv * gam[tid + 256] + bet[tid + 256];
}

// ---------------- HMMA fp16 GEMM (1 pass), fp32-A with fused LN ------------
// BM=128, BN=128, BK=32; 8 warps (2x4), warp tile 64x32.
// Stage = Ah(8KB) + Bh(8KB) = 16KB; 3 stages, 2 CTAs/SM.
#define STAGE_BYTES 16384
#define NSTG 3
__global__ void __launch_bounds__(256, 2)
gemm_f32a(const float* __restrict__ A, const float2* __restrict__ stats,
          const float* __restrict__ gam, const float* __restrict__ bet,
          const __half* __restrict__ Bh,
          const float* __restrict__ bias, const float* __restrict__ res,
          float* __restrict__ outF, int N, int K, int relu) {
    extern __shared__ char smem[];
    uint32_t sb = s2u(smem);
    int tid = threadIdx.x, lane = tid & 31, wid = tid >> 5;
    int wm = wid >> 2, wn = wid & 3;
    int rowBase = blockIdx.y * 128, colBase = blockIdx.x * 128;
    int sub = lane & 7, grp = lane >> 3;

    float acc[4][4][4];
    #pragma unroll
    for (int i = 0; i < 4; i++)
        #pragma unroll
        for (int j = 0; j < 4; j++)
            #pragma unroll
            for (int c = 0; c < 4; c++) acc[i][j][c] = 0.0f;

    const int NC = K >> 5;

    float aR[2][8];
    float2 stR[2];
    #pragma unroll
    for (int i = 0; i < 2; i++) {
        int id = tid + (i << 8);
        int row = id >> 2;
        stR[i] = stats ? stats[rowBase + row] : make_float2(0.0f, 1.0f);
    }

    auto ldgA = [&](int c) {
        int k0 = c << 5;
        #pragma unroll
        for (int i = 0; i < 2; i++) {
            int id = tid + (i << 8);
            int row = id >> 2, ch = id & 3;
            const float* g = A + (size_t)(rowBase + row) * K + k0 + ch * 8;
            float4 u = *(const float4*)g;
            float4 v = *(const float4*)(g + 4);
            aR[i][0] = u.x; aR[i][1] = u.y; aR[i][2] = u.z; aR[i][3] = u.w;
            aR[i][4] = v.x; aR[i][5] = v.y; aR[i][6] = v.z; aR[i][7] = v.w;
        }
    };

    auto stsA = [&](int c, int buf) {
        int k0 = c << 5;
        #pragma unroll
        for (int i = 0; i < 2; i++) {
            int id = tid + (i << 8);
            int row = id >> 2, ch = id & 3;
            float y[8];
            if (gam) {
                float mean = stR[i].x, inv = stR[i].y;
                const float* gg = gam + k0 + ch * 8;
                const float* bb = bet + k0 + ch * 8;
                float4 g0 = *(const float4*)gg, g1 = *(const float4*)(gg + 4);
                float4 b0 = *(const float4*)bb, b1 = *(const float4*)(bb + 4);
                y[0] = (aR[i][0] - mean) * inv * g0.x + b0.x;
                y[1] = (aR[i][1] - mean) * inv * g0.y + b0.y;
                y[2] = (aR[i][2] - mean) * inv * g0.z + b0.z;
                y[3] = (aR[i][3] - mean) * inv * g0.w + b0.w;
                y[4] = (aR[i][4] - mean) * inv * g1.x + b1.x;
                y[5] = (aR[i][5] - mean) * inv * g1.y + b1.y;
                y[6] = (aR[i][6] - mean) * inv * g1.z + b1.z;
                y[7] = (aR[i][7] - mean) * inv * g1.w + b1.w;
            } else {
                #pragma unroll
                for (int j = 0; j < 8; j++) y[j] = aR[i][j];
            }
            int phys = ch ^ ((row >> 1) & 3);
            uint32_t rel = (uint32_t)(buf * STAGE_BYTES) + row * 64 + phys * 16;
            uint4 wh;
            wh.x = pack2(__float2half_rn(y[0]), __float2half_rn(y[1]));
            wh.y = pack2(__float2half_rn(y[2]), __float2half_rn(y[3]));
            wh.z = pack2(__float2half_rn(y[4]), __float2half_rn(y[5]));
            wh.w = pack2(__float2half_rn(y[6]), __float2half_rn(y[7]));
            *(uint4*)(smem + rel) = wh;
        }
    };

    auto loadB = [&](int c, int buf) {
        uint32_t sbase = sb + buf * STAGE_BYTES + 8192u;
        int k0 = c << 5;
        #pragma unroll
        for (int i = 0; i < 2; i++) {
            int id = tid + (i << 8);
            int row = id >> 2, ch = id & 3;
            int phys = ch ^ ((row >> 1) & 3);
            uint32_t so = sbase + row * 64 + phys * 16;
            CPA16(so, Bh + (size_t)(colBase + row) * K + k0 + ch * 8);
        }
    };

    auto compute = [&](int buf) {
        uint32_t base = sb + buf * STAGE_BYTES;
        #pragma unroll
        for (int ks = 0; ks < 2; ks++) {
            uint32_t ahf[4][4], bhf[4][2];
            #pragma unroll
            for (int mi = 0; mi < 4; mi++) {
                int row = wm * 64 + mi * 16 + sub + (grp & 1) * 8;
                int ci = 2 * ks + (grp >> 1);
                uint32_t ad = base + row * 64 + ((ci ^ ((row >> 1) & 3)) * 16);
                LDSM4(ahf[mi][0], ahf[mi][1], ahf[mi][2], ahf[mi][3], ad);
            }
            #pragma unroll
            for (int g = 0; g < 2; g++) {
                int row = wn * 32 + g * 16 + sub + (grp & 1) * 8;
                int ci = 2 * ks + (grp >> 1);
                uint32_t ad = base + 8192u + row * 64 + ((ci ^ ((row >> 1) & 3)) * 16);
                uint32_t r0, r1, r2, r3;
                LDSM4(r0, r1, r2, r3, ad);
                bhf[2*g][0] = r0; bhf[2*g+1][0] = r1; bhf[2*g][1] = r2; bhf[2*g+1][1] = r3;
            }
            #pragma unroll
            for (int mi = 0; mi < 4; mi++)
                #pragma unroll
                for (int nj = 0; nj < 4; nj++)
                    MMA16816(acc[mi][nj], ahf[mi], bhf[nj][0], bhf[nj][1]);
        }
    };

    // prologue: stages 0 and 1
    ldgA(0); stsA(0, 0); loadB(0, 0); CPCOMMIT();
    if (NC > 1) { ldgA(1); stsA(1, 1); loadB(1, 1); }
    CPCOMMIT();
    #pragma unroll 1
    for (int c = 0; c < NC; c++) {
        int nxt = c + 2;
        int nb = nxt % NSTG;
        if (nxt < NC) ldgA(nxt);           // LDG in flight over the wait
        CPWAIT(1);                          // stage c complete (c+1 may fly)
        __syncthreads();
        if (nxt < NC) loadB(nxt, nb);
        CPCOMMIT();
        if (nxt < NC) stsA(nxt, nb);
        compute(c % NSTG);
    }

    // --- epilogue (fp32 out) ---
    #pragma unroll
    for (int mi = 0; mi < 4; mi++) {
        #pragma unroll
        for (int nj = 0; nj < 4; nj++) {
            int r = rowBase + wm * 64 + mi * 16 + (lane >> 2);
            int c = colBase + wn * 32 + nj * 8 + ((lane & 3) << 1);
            #pragma unroll
            for (int half_ : {0, 1}) {
                int rr = r + half_ * 8;
                float v0 = acc[mi][nj][half_ * 2 + 0];
                float v1 = acc[mi][nj][half_ * 2 + 1];
                if (bias) { v0 += bias[c]; v1 += bias[c + 1]; }
                if (res) {
                    float2 rv = *(const float2*)(res + (size_t)rr * N + c);
                    v0 += rv.x; v1 += rv.y;
                }
                if (relu) { v0 = fmaxf(v0, 0.0f); v1 = fmaxf(v1, 0.0f); }
                *(float2*)(outF + (size_t)rr * N + c) = make_float2(v0, v1);
            }
        }
    }
}

// ---------------- Chunked local attention (fp16 scores path, fp32 out) -----
__global__ void attn_kernel(const float* __restrict__ qkv, const float* __restrict__ p,
                            const float* __restrict__ pbu, const float* __restrict__ pbv,
                            float* __restrict__ o) {
    int ci = blockIdx.x, h = blockIdx.y, b = blockIdx.z;
    int s0 = max((ci - LC_) * CS_, 0);
    int s1 = (ci + 1) * CS_;
    int W = s1 - s0;
    int t0 = ci * CS_;
    int tid = threadIdx.x;                    // 256 threads

    extern __shared__ char asmem[];
    __half* Ks = (__half*)asmem;              // WMAX*64 halves
    __half* Ps = Ks + WMAX_ * 64;
    __half* QU = Ps + WMAX_ * 64;             // 16*64
    __half* QV = QU + 16 * 64;
    float* Vs = (float*)(QV + 16 * 64);       // WMAX*64 floats
    float* SC = Vs + WMAX_ * 64;              // 16*WMAX

    for (int idx = tid; idx < W * 64; idx += 256) {
        int s = idx >> 6, d = idx & 63;
        size_t gi = (size_t)((b * T_) + s0 + s) * QKVN_ + h * DK_ + d;
        Ks[idx] = __float2half(qkv[gi + D_]);
        Vs[idx] = qkv[gi + 2 * D_];
        Ps[idx] = __float2half(p[(size_t)(s0 + s) * PALLN_ + h * DK_ + d]);
    }
    for (int idx = tid; idx < 16 * 64; idx += 256) {
        int qi = idx >> 6, d = idx & 63;
        float qv_ = qkv[(size_t)((b * T_) + t0 + qi) * QKVN_ + h * DK_ + d];
        QU[idx] = __float2half(qv_ + pbu[h * DK_ + d]);
        QV[idx] = __float2half(qv_ + pbv[h * DK_ + d]);
    }
    __syncthreads();

    const float scale = 0.125f;
    int Wh = W >> 1;
    for (int it = tid; it < 8 * Wh; it += 256) {
        int qi = (it / Wh) * 2, s = (it % Wh) * 2;
        float a00 = 0, a01 = 0, a10 = 0, a11 = 0;
        #pragma unroll 4
        for (int d = 0; d < 64; d += 4) {
            float4 qu0 = ld4h(&QU[qi * 64 + d]);
            float4 qu1 = ld4h(&QU[(qi + 1) * 64 + d]);
            float4 qv0 = ld4h(&QV[qi * 64 + d]);
            float4 qv1 = ld4h(&QV[(qi + 1) * 64 + d]);
            float4 k0 = ld4h(&Ks[s * 64 + d]);
            float4 k1 = ld4h(&Ks[(s + 1) * 64 + d]);
            float4 p0 = ld4h(&Ps[s * 64 + d]);
            float4 p1 = ld4h(&Ps[(s + 1) * 64 + d]);
            a00 += dot4(qu0, k0) + dot4(qv0, p0);
            a01 += dot4(qu0, k1) + dot4(qv0, p1);
            a10 += dot4(qu1, k0) + dot4(qv1, p0);
            a11 += dot4(qu1, k1) + dot4(qv1, p1);
        }
        SC[qi * WMAX_ + s]           = a00 * scale;
        SC[qi * WMAX_ + s + 1]       = a01 * scale;
        SC[(qi + 1) * WMAX_ + s]     = a10 * scale;
        SC[(qi + 1) * WMAX_ + s + 1] = a11 * scale;
    }
    __syncthreads();

    int warp = tid >> 5, lane = tid & 31;
    for (int qi = warp; qi < 16; qi += 8) {
        float m = -1e30f;
        for (int s = lane; s < W; s += 32) m = fmaxf(m, SC[qi * WMAX_ + s]);
        #pragma unroll
        for (int off = 16; off; off >>= 1) m = fmaxf(m, __shfl_xor_sync(0xffffffffu, m, off));
        float sum = 0.0f;
        for (int s = lane; s < W; s += 32) {
            float e = expf(SC[qi * WMAX_ + s] - m);
            SC[qi * WMAX_ + s] = e;
            sum += e;
        }
        #pragma unroll
        for (int off = 16; off; off >>= 1) sum += __shfl_xor_sync(0xffffffffu, sum, off);
        float inv = 1.0f / sum;
        for (int s = lane; s < W; s += 32) SC[qi * WMAX_ + s] *= inv;
    }
    __syncthreads();

    {
        int it = tid;                       // 8 * 32 = 256
        int qi = (it >> 5) * 2, d = (it & 31) * 2;
        float a00 = 0, a01 = 0, a10 = 0, a11 = 0;
        for (int s = 0; s < W; s++) {
            float2 vv = *(const float2*)&Vs[s * 64 + d];
            float c0 = SC[qi * WMAX_ + s];
            float c1 = SC[(qi + 1) * WMAX_ + s];
            a00 += c0 * vv.x; a01 += c0 * vv.y;
            a10 += c1 * vv.x; a11 += c1 * vv.y;
        }
        size_t o0 = (size_t)((b * T_) + t0 + qi) * D_ + h * DK_ + d;
        *(float2*)(o + o0)      = make_float2(a00, a01);
        *(float2*)(o + o0 + D_) = make_float2(a10, a11);
    }
}

static const int ATTN_SMEM = (WMAX_*64*2 + 16*64*2) * 2 + (WMAX_*64 + 16*WMAX_) * 4; // 50176
static const int GEMM_SMEM = NSTG * STAGE_BYTES;   // 49152

extern "C" void kernel_launch(void* const* d_in, const int* in_sizes, int n_in,
                              void* d_out, int out_size) {
    (void)in_sizes; (void)n_in; (void)out_size;
    const float* xs    = (const float*)d_in[0];
    const float* pos   = (const float*)d_in[1];
    // d_in[2] = mask: unused (window computed analytically)
    const float* Wq    = (const float*)d_in[3];
    const float* bq    = (const float*)d_in[4];
    const float* Wk    = (const float*)d_in[5];
    const float* bk    = (const float*)d_in[6];
    const float* Wv    = (const float*)d_in[7];
    const float* bv    = (const float*)d_in[8];
    const float* Wo    = (const float*)d_in[9];
    const float* bo    = (const float*)d_in[10];
    const float* Wp    = (const float*)d_in[11];
    const float* pbu   = (const float*)d_in[12];
    const float* pbv   = (const float*)d_in[13];
    const float* ln1s  = (const float*)d_in[14];
    const float* ln1b  = (const float*)d_in[15];
    const float* ln2s  = (const float*)d_in[16];
    const float* ln2b  = (const float*)d_in[17];
    const float* W1    = (const float*)d_in[18];
    const float* b1    = (const float*)d_in[19];
    const float* W2    = (const float*)d_in[20];
    const float* b2    = (const float*)d_in[21];
    const float* lnfs  = (const float*)d_in[22];
    const float* lnfb  = (const float*)d_in[23];

    cudaFuncSetAttribute(attn_kernel, cudaFuncAttributeMaxDynamicSharedMemorySize, ATTN_SMEM);
    cudaFuncSetAttribute(gemm_f32a,   cudaFuncAttributeMaxDynamicSharedMemorySize, GEMM_SMEM);

    void* a;
    #define SYM(p, s) cudaGetSymbolAddress(&a, s); auto* p = (decltype(&s[0]))a;
    SYM(px, g_x)  SYM(pqkv, g_qkv)  SYM(po, g_o)  SYM(pff, g_ff)
    SYM(ppall, g_pall)  SYM(pbqkv, g_bqkv)  SYM(pst, g_st)
    SYM(pwqkvh, g_wqkvh)
    SYM(pwoh, g_woh)
    SYM(pwph, g_wph)
    SYM(pw1h, g_w1h)
    SYM(pw2h, g_w2h)
    #undef SYM

    const int M = B_ * T_;  // 4096
    const size_t DD = (size_t)D_ * D_;          // 262144
    const size_t QKVLS = (size_t)QKVN_ * D_;    // 786432
    dim3 wtb(32, 8);

    scale_kernel<<<(B_*T_*D_) / 256, 256>>>(xs, sqrtf((float)D_));
    bcat_kernel<<<(L_*QKVN_) / 256, 256>>>(bq, bk, bv);
    wtransqkv_kernel<<<dim3(16, 16, 3 * L_), wtb>>>(Wq, Wk, Wv, pwqkvh);
    lnstats_kernel<<<M / 8, 256>>>(px, pst);
    wtrans_kernel<<<dim3(D_/32, D_/32, L_), wtb>>>(Wo, pwoh, D_, D_, DD, DD);
    // layer-0 fused QKV GEMM early (profiling target position)
    gemm_f32a<<<dim3(QKVN_/128, M/128), 256, GEMM_SMEM>>>(px, pst,
        ln1s, ln1b, pwqkvh, pbqkv, nullptr, pqkv, QKVN_, D_, 0);
    // remaining prep
    wtrans_kernel<<<dim3(D_/32,  D_/32,  L_), wtb>>>(Wp, pwph, D_,  D_,  DD, DD);
    wtrans_kernel<<<dim3(FF_/32, D_/32,  L_), wtb>>>(W1, pw1h, D_,  FF_, (size_t)D_*FF_, (size_t)D_*FF_);
    wtrans_kernel<<<dim3(D_/32,  FF_/32, L_), wtb>>>(W2, pw2h, FF_, D_,  (size_t)FF_*D_, (size_t)FF_*D_);
    gemm_f32a<<<dim3(PALLN_/128, T_/128), 256, GEMM_SMEM>>>(pos, nullptr, nullptr, nullptr,
        pwph, nullptr, nullptr, ppall, PALLN_, D_, 0);

    for (int l = 0; l < L_; l++) {
        size_t wdf = (size_t)l * D_ * FF_;

        if (l > 0) {
            lnstats_kernel<<<M / 8, 256>>>(px, pst);
            gemm_f32a<<<dim3(QKVN_/128, M/128), 256, GEMM_SMEM>>>(px, pst,
                ln1s + l*D_, ln1b + l*D_,
                pwqkvh + l * QKVLS,
                pbqkv + l * QKVN_, nullptr, pqkv, QKVN_, D_, 0);
        }

        // attention -> o fp32
        attn_kernel<<<dim3(NCHUNK_, H_, B_), 256, ATTN_SMEM>>>(
            pqkv, ppall + l * D_, pbu + l * H_ * DK_, pbv + l * H_ * DK_, po);

        // x = x + o @ Wo + bo
        gemm_f32a<<<dim3(D_/128, M/128), 256, GEMM_SMEM>>>(po, nullptr, nullptr, nullptr,
            pwoh + l * DD,
            bo + l*D_, px, px, D_, D_, 0);

        // row stats for LN2
        lnstats_kernel<<<M / 8, 256>>>(px, pst);

        // ff = relu(LN2(x) @ W1 + b1)
        gemm_f32a<<<dim3(FF_/128, M/128), 256, GEMM_SMEM>>>(px, pst,
            ln2s + l*D_, ln2b + l*D_,
            pw1h + wdf,
            b1 + l*FF_, nullptr, pff, FF_, D_, 1);

        // x = x + ff @ W2 + b2
        gemm_f32a<<<dim3(D_/128, M/128), 256, GEMM_SMEM>>>(pff, nullptr, nullptr, nullptr,
            pw2h + wdf,
            b2 + l*D_, px, px, D_, FF_, 0);
    }

    // out = LNf(x)  (fp32)
    ln_kernel<<<M, 256>>>(px, (float*)d_out, lnfs, lnfb);
}

// round 11
// speedup vs baseline: 2.5980x; 1.1622x over previous
#include <cuda_runtime.h>
#include <cuda_fp16.h>
#include <math.h>
#include <stdint.h>

// Problem constants
#define B_  8
#define T_  512
#define D_  512
#define H_  8
#define FF_ 2048
#define L_  6
#define CS_ 16
#define LC_ 4
#define DK_ 64
#define NCHUNK_ (T_ / CS_)          // 32
#define WMAX_ ((LC_ + 1) * CS_)     // 80
#define QKVN_ (3 * D_)              // 1536
#define PALLN_ (L_ * D_)            // 3072

// ---------------- scratch (device globals; no allocation) ----------------
__device__ float  g_x   [B_*T_*D_];
__device__ __half g_qkvh[B_*T_*QKVN_];
__device__ __half g_oh  [B_*T_*D_];
__device__ __half g_ffh [B_*T_*FF_];
__device__ __half g_pall[T_*PALLN_];
__device__ float  g_bqkv[L_*QKVN_];
__device__ float2 g_st  [B_*T_];

// transposed fp16 weights: Wt[n][k] (round-to-nearest)
__device__ __half g_wqkvh[L_*QKVN_*D_];
__device__ __half g_woh[L_*D_*D_];
__device__ __half g_wph[L_*D_*D_];
__device__ __half g_w1h[L_*D_*FF_];
__device__ __half g_w2h[L_*FF_*D_];

// ---------------- PTX helpers (family-portable: sm_80+ ISA only) ----------
__device__ __forceinline__ uint32_t s2u(const void* p) {
    uint32_t a;
    asm("{ .reg .u64 t; cvta.to.shared.u64 t, %1; cvt.u32.u64 %0, t; }" : "=r"(a) : "l"(p));
    return a;
}

#define CPA16(sa, g) \
    asm volatile("cp.async.cg.shared.global [%0], [%1], 16;" :: "r"(sa), "l"(g) : "memory")
#define CPCOMMIT() asm volatile("cp.async.commit_group;" ::: "memory")
#define CPWAIT(n)  asm volatile("cp.async.wait_group %0;" :: "n"(n) : "memory")

#define LDSM4(d0, d1, d2, d3, a) \
    asm volatile("ldmatrix.sync.aligned.m8n8.x4.shared.b16 {%0,%1,%2,%3}, [%4];" \
        : "=r"(d0), "=r"(d1), "=r"(d2), "=r"(d3) : "r"(a))

#define MMA16816(c, a, b0, b1) \
    asm volatile("mma.sync.aligned.m16n8k16.row.col.f32.f16.f16.f32 " \
        "{%0,%1,%2,%3}, {%4,%5,%6,%7}, {%8,%9}, {%0,%1,%2,%3};" \
        : "+f"((c)[0]), "+f"((c)[1]), "+f"((c)[2]), "+f"((c)[3]) \
        : "r"((a)[0]), "r"((a)[1]), "r"((a)[2]), "r"((a)[3]), "r"(b0), "r"(b1))

__device__ __forceinline__ uint32_t pack2(__half a, __half b) {
    __half2 t = __halves2half2(a, b);
    return *reinterpret_cast<uint32_t*>(&t);
}
__device__ __forceinline__ float4 ld4h(const __half* p) {
    uint2 u = *(const uint2*)p;
    __half2 a = *reinterpret_cast<__half2*>(&u.x);
    __half2 b = *reinterpret_cast<__half2*>(&u.y);
    float2 fa = __half22float2(a), fb = __half22float2(b);
    return make_float4(fa.x, fa.y, fb.x, fb.y);
}
__device__ __forceinline__ float dot4(float4 a, float4 b) {
    return a.x * b.x + a.y * b.y + a.z * b.z + a.w * b.w;
}

// ---------------- elementwise scale: x = xs * sqrt(D) ----------------
__global__ void scale_kernel(const float* __restrict__ xs, float s) {
    int i = blockIdx.x * blockDim.x + threadIdx.x;
    g_x[i] = xs[i] * s;
}

// ---------------- bias concat for fused QKV ----------------
__global__ void bcat_kernel(const float* __restrict__ bq, const float* __restrict__ bk,
                            const float* __restrict__ bv) {
    int i = blockIdx.x * blockDim.x + threadIdx.x;   // L*1536
    int l = i / QKVN_, c = i % QKVN_;
    float v = (c < D_) ? bq[l * D_ + c]
            : (c < 2 * D_) ? bk[l * D_ + c - D_]
            : bv[l * D_ + c - 2 * D_];
    g_bqkv[i] = v;
}

// ---------------- merged QKV weight transpose (fp16 rn) ----------------
__global__ void wtransqkv_kernel(const float* __restrict__ Wq,
                                 const float* __restrict__ Wk,
                                 const float* __restrict__ Wv,
                                 __half* __restrict__ Th) {
    __shared__ float sm[32][33];
    int z = blockIdx.z;
    int which = z / L_, l = z % L_;
    const size_t DD = (size_t)D_ * D_;
    const float* Wl = (which == 0 ? Wq : which == 1 ? Wk : Wv) + (size_t)l * DD;
    __half* Thl = Th + (size_t)l * QKVN_ * D_ + (size_t)which * DD;
    int n0 = blockIdx.x * 32, k0 = blockIdx.y * 32;
    int tx = threadIdx.x, ty = threadIdx.y;
    #pragma unroll
    for (int j = 0; j < 4; j++)
        sm[ty + j * 8][tx] = Wl[(size_t)(k0 + ty + j * 8) * D_ + n0 + tx];
    __syncthreads();
    #pragma unroll
    for (int j = 0; j < 4; j++) {
        int n = ty + j * 8;
        Thl[(size_t)(n0 + n) * D_ + k0 + tx] = __float2half_rn(sm[tx][n]);
    }
}

// ---------------- generic weight transpose (fp16 rn) ----------------
__global__ void wtrans_kernel(const float* __restrict__ W, __half* __restrict__ Th,
                              int K, int N, size_t srcLS, size_t dstLS) {
    __shared__ float sm[32][33];
    const float* Wl = W + (size_t)blockIdx.z * srcLS;
    __half* Thl = Th + (size_t)blockIdx.z * dstLS;
    int n0 = blockIdx.x * 32, k0 = blockIdx.y * 32;
    int tx = threadIdx.x, ty = threadIdx.y;
    #pragma unroll
    for (int j = 0; j < 4; j++)
        sm[ty + j * 8][tx] = Wl[(size_t)(k0 + ty + j * 8) * N + n0 + tx];
    __syncthreads();
    #pragma unroll
    for (int j = 0; j < 4; j++) {
        int n = ty + j * 8;
        Thl[(size_t)(n0 + n) * K + k0 + tx] = __float2half_rn(sm[tx][n]);
    }
}

// ---------------- LN stats: one warp per row, float4 loads ----------------
__global__ void lnstats_kernel(const float* __restrict__ in, float2* __restrict__ st) {
    int warp = threadIdx.x >> 5, lane = threadIdx.x & 31;
    int row = blockIdx.x * 8 + warp;
    const float4* x = (const float4*)(in + (size_t)row * D_);
    float s = 0.0f, ss = 0.0f;
    #pragma unroll
    for (int j = 0; j < 4; j++) {
        float4 v = x[lane + j * 32];
        s  += v.x + v.y + v.z + v.w;
        ss += v.x * v.x + v.y * v.y + v.z * v.z + v.w * v.w;
    }
    #pragma unroll
    for (int off = 16; off; off >>= 1) {
        s  += __shfl_xor_sync(0xffffffffu, s,  off);
        ss += __shfl_xor_sync(0xffffffffu, ss, off);
    }
    if (lane == 0) {
        float mean = s * (1.0f / D_);
        float var  = ss * (1.0f / D_) - mean * mean;
        st[row] = make_float2(mean, rsqrtf(var + 1e-5f));
    }
}

// ---------------- final LN ----------------
__global__ void ln_kernel(const float* __restrict__ in, float* __restrict__ out,
                          const float* __restrict__ gam, const float* __restrict__ bet) {
    __shared__ float sh_s[8], sh_ss[8];
    int row = blockIdx.x, tid = threadIdx.x;
    const float* x = in + (size_t)row * D_;
    float v0 = x[tid], v1 = x[tid + 256];
    float s = v0 + v1, ss = v0 * v0 + v1 * v1;
    int lane = tid & 31, warp = tid >> 5;
    #pragma unroll
    for (int off = 16; off; off >>= 1) {
        s  += __shfl_xor_sync(0xffffffffu, s,  off);
        ss += __shfl_xor_sync(0xffffffffu, ss, off);
    }
    if (lane == 0) { sh_s[warp] = s; sh_ss[warp] = ss; }
    __syncthreads();
    if (warp == 0) {
        float a = (lane < 8) ? sh_s[lane]  : 0.0f;
        float b = (lane < 8) ? sh_ss[lane] : 0.0f;
        #pragma unroll
        for (int off = 4; off; off >>= 1) {
            a += __shfl_xor_sync(0xffffffffu, a, off);
            b += __shfl_xor_sync(0xffffffffu, b, off);
        }
        if (lane == 0) { sh_s[0] = a; sh_ss[0] = b; }
    }
    __syncthreads();
    float mean = sh_s[0] * (1.0f / D_);
    float var  = sh_ss[0] * (1.0f / D_) - mean * mean;
    float inv  = rsqrtf(var + 1e-5f);
    float* y = out + (size_t)row * D_;
    y[tid]       = (v0 - mean) * inv * gam[tid]       + bet[tid];
    y[tid + 256] = (v1 - mean) * inv * gam[tid + 256] + bet[tid + 256];
}

// ---------------- shared epilogue ----------------
#define GEMM_EPILOGUE(acc, N, bias, res, outF, outH, relu) \
    _Pragma("unroll") \
    for (int mi = 0; mi < 4; mi++) { \
        _Pragma("unroll") \
        for (int nj = 0; nj < 4; nj++) { \
            int r = rowBase + wm * 64 + mi * 16 + (lane >> 2); \
            int c = colBase + wn * 32 + nj * 8 + ((lane & 3) << 1); \
            _Pragma("unroll") \
            for (int half_ = 0; half_ < 2; half_++) { \
                int rr = r + half_ * 8; \
                float v0 = acc[mi][nj][half_ * 2 + 0]; \
                float v1 = acc[mi][nj][half_ * 2 + 1]; \
                if (bias) { v0 += bias[c]; v1 += bias[c + 1]; } \
                if (res) { \
                    float2 rv = *(const float2*)(res + (size_t)rr * N + c); \
                    v0 += rv.x; v1 += rv.y; \
                } \
                if (relu) { v0 = fmaxf(v0, 0.0f); v1 = fmaxf(v1, 0.0f); } \
                if (outF) \
                    *(float2*)(outF + (size_t)rr * N + c) = make_float2(v0, v1); \
                else \
                    *(__half2*)(outH + (size_t)rr * N + c) = \
                        __halves2half2(__float2half_rn(v0), __float2half_rn(v1)); \
            } \
        } \
    }

// ---------------- HMMA fp16 GEMM, fp32-A with fused LN --------------------
// BM=128, BN=128, BK=32; 8 warps (2x4), warp tile 64x32.
// Stage = Ah(8KB) + Bh(8KB) = 16KB; 3 stages, 2 CTAs/SM.
#define STAGE_BYTES 16384
#define NSTG 3
__global__ void __launch_bounds__(256, 2)
gemm_f32a(const float* __restrict__ A, const float2* __restrict__ stats,
          const float* __restrict__ gam, const float* __restrict__ bet,
          const __half* __restrict__ Bh,
          const float* __restrict__ bias, const float* __restrict__ res,
          float* __restrict__ outF, __half* __restrict__ outH,
          int N, int K, int relu) {
    extern __shared__ char smem[];
    uint32_t sb = s2u(smem);
    int tid = threadIdx.x, lane = tid & 31, wid = tid >> 5;
    int wm = wid >> 2, wn = wid & 3;
    int rowBase = blockIdx.y * 128, colBase = blockIdx.x * 128;
    int sub = lane & 7, grp = lane >> 3;

    float acc[4][4][4];
    #pragma unroll
    for (int i = 0; i < 4; i++)
        #pragma unroll
        for (int j = 0; j < 4; j++)
            #pragma unroll
            for (int c = 0; c < 4; c++) acc[i][j][c] = 0.0f;

    const int NC = K >> 5;

    float aR[2][8];
    float2 stR[2];
    #pragma unroll
    for (int i = 0; i < 2; i++) {
        int id = tid + (i << 8);
        int row = id >> 2;
        stR[i] = stats ? stats[rowBase + row] : make_float2(0.0f, 1.0f);
    }

    auto ldgA = [&](int c) {
        int k0 = c << 5;
        #pragma unroll
        for (int i = 0; i < 2; i++) {
            int id = tid + (i << 8);
            int row = id >> 2, ch = id & 3;
            const float* g = A + (size_t)(rowBase + row) * K + k0 + ch * 8;
            float4 u = *(const float4*)g;
            float4 v = *(const float4*)(g + 4);
            aR[i][0] = u.x; aR[i][1] = u.y; aR[i][2] = u.z; aR[i][3] = u.w;
            aR[i][4] = v.x; aR[i][5] = v.y; aR[i][6] = v.z; aR[i][7] = v.w;
        }
    };

    auto stsA = [&](int c, int buf) {
        int k0 = c << 5;
        #pragma unroll
        for (int i = 0; i < 2; i++) {
            int id = tid + (i << 8);
            int row = id >> 2, ch = id & 3;
            float y[8];
            if (gam) {
                float mean = stR[i].x, inv = stR[i].y;
                const float* gg = gam + k0 + ch * 8;
                const float* bb = bet + k0 + ch * 8;
                float4 g0 = *(const float4*)gg, g1 = *(const float4*)(gg + 4);
                float4 b0 = *(const float4*)bb, b1 = *(const float4*)(bb + 4);
                y[0] = (aR[i][0] - mean) * inv * g0.x + b0.x;
                y[1] = (aR[i][1] - mean) * inv * g0.y + b0.y;
                y[2] = (aR[i][2] - mean) * inv * g0.z + b0.z;
                y[3] = (aR[i][3] - mean) * inv * g0.w + b0.w;
                y[4] = (aR[i][4] - mean) * inv * g1.x + b1.x;
                y[5] = (aR[i][5] - mean) * inv * g1.y + b1.y;
                y[6] = (aR[i][6] - mean) * inv * g1.z + b1.z;
                y[7] = (aR[i][7] - mean) * inv * g1.w + b1.w;
            } else {
                #pragma unroll
                for (int j = 0; j < 8; j++) y[j] = aR[i][j];
            }
            int phys = ch ^ ((row >> 1) & 3);
            uint32_t rel = (uint32_t)(buf * STAGE_BYTES) + row * 64 + phys * 16;
            uint4 wh;
            wh.x = pack2(__float2half_rn(y[0]), __float2half_rn(y[1]));
            wh.y = pack2(__float2half_rn(y[2]), __float2half_rn(y[3]));
            wh.z = pack2(__float2half_rn(y[4]), __float2half_rn(y[5]));
            wh.w = pack2(__float2half_rn(y[6]), __float2half_rn(y[7]));
            *(uint4*)(smem + rel) = wh;
        }
    };

    auto loadB = [&](int c, int buf) {
        uint32_t sbase = sb + buf * STAGE_BYTES + 8192u;
        int k0 = c << 5;
        #pragma unroll
        for (int i = 0; i < 2; i++) {
            int id = tid + (i << 8);
            int row = id >> 2, ch = id & 3;
            int phys = ch ^ ((row >> 1) & 3);
            CPA16(sbase + row * 64 + phys * 16,
                  Bh + (size_t)(colBase + row) * K + k0 + ch * 8);
        }
    };

    auto compute = [&](int buf) {
        uint32_t base = sb + buf * STAGE_BYTES;
        #pragma unroll
        for (int ks = 0; ks < 2; ks++) {
            uint32_t ahf[4][4], bhf[4][2];
            #pragma unroll
            for (int mi = 0; mi < 4; mi++) {
                int row = wm * 64 + mi * 16 + sub + (grp & 1) * 8;
                int ci = 2 * ks + (grp >> 1);
                uint32_t ad = base + row * 64 + ((ci ^ ((row >> 1) & 3)) * 16);
                LDSM4(ahf[mi][0], ahf[mi][1], ahf[mi][2], ahf[mi][3], ad);
            }
            #pragma unroll
            for (int g = 0; g < 2; g++) {
                int row = wn * 32 + g * 16 + sub + (grp & 1) * 8;
                int ci = 2 * ks + (grp >> 1);
                uint32_t ad = base + 8192u + row * 64 + ((ci ^ ((row >> 1) & 3)) * 16);
                uint32_t r0, r1, r2, r3;
                LDSM4(r0, r1, r2, r3, ad);
                bhf[2*g][0] = r0; bhf[2*g+1][0] = r1; bhf[2*g][1] = r2; bhf[2*g+1][1] = r3;
            }
            #pragma unroll
            for (int mi = 0; mi < 4; mi++)
                #pragma unroll
                for (int nj = 0; nj < 4; nj++)
                    MMA16816(acc[mi][nj], ahf[mi], bhf[nj][0], bhf[nj][1]);
        }
    };

    ldgA(0); stsA(0, 0); loadB(0, 0); CPCOMMIT();
    if (NC > 1) { ldgA(1); stsA(1, 1); loadB(1, 1); }
    CPCOMMIT();
    #pragma unroll 1
    for (int c = 0; c < NC; c++) {
        int nxt = c + 2;
        int nb = nxt % NSTG;
        if (nxt < NC) ldgA(nxt);
        CPWAIT(1);
        __syncthreads();
        if (nxt < NC) loadB(nxt, nb);
        CPCOMMIT();
        if (nxt < NC) stsA(nxt, nb);
        compute(c % NSTG);
    }

    GEMM_EPILOGUE(acc, N, bias, res, outF, outH, relu)
}

// ---------------- HMMA fp16 GEMM, fp16-A via cp.async ---------------------
__global__ void __launch_bounds__(256, 2)
gemm_f16a(const __half* __restrict__ Ah, const __half* __restrict__ Bh,
          const float* __restrict__ bias, const float* __restrict__ res,
          float* __restrict__ outF, __half* __restrict__ outH,
          int N, int K, int relu) {
    extern __shared__ char smem[];
    uint32_t sb = s2u(smem);
    int tid = threadIdx.x, lane = tid & 31, wid = tid >> 5;
    int wm = wid >> 2, wn = wid & 3;
    int rowBase = blockIdx.y * 128, colBase = blockIdx.x * 128;
    int sub = lane & 7, grp = lane >> 3;

    float acc[4][4][4];
    #pragma unroll
    for (int i = 0; i < 4; i++)
        #pragma unroll
        for (int j = 0; j < 4; j++)
            #pragma unroll
            for (int c = 0; c < 4; c++) acc[i][j][c] = 0.0f;

    const int NC = K >> 5;

    auto loadAB = [&](int c, int buf) {
        uint32_t sbase = sb + buf * STAGE_BYTES;
        int k0 = c << 5;
        #pragma unroll
        for (int i = 0; i < 2; i++) {
            int id = tid + (i << 8);
            int row = id >> 2, ch = id & 3;
            int phys = ch ^ ((row >> 1) & 3);
            uint32_t so = sbase + row * 64 + phys * 16;
            CPA16(so,          Ah + (size_t)(rowBase + row) * K + k0 + ch * 8);
            CPA16(so + 8192u,  Bh + (size_t)(colBase + row) * K + k0 + ch * 8);
        }
    };

    auto compute = [&](int buf) {
        uint32_t base = sb + buf * STAGE_BYTES;
        #pragma unroll
        for (int ks = 0; ks < 2; ks++) {
            uint32_t ahf[4][4], bhf[4][2];
            #pragma unroll
            for (int mi = 0; mi < 4; mi++) {
                int row = wm * 64 + mi * 16 + sub + (grp & 1) * 8;
                int ci = 2 * ks + (grp >> 1);
                uint32_t ad = base + row * 64 + ((ci ^ ((row >> 1) & 3)) * 16);
                LDSM4(ahf[mi][0], ahf[mi][1], ahf[mi][2], ahf[mi][3], ad);
            }
            #pragma unroll
            for (int g = 0; g < 2; g++) {
                int row = wn * 32 + g * 16 + sub + (grp & 1) * 8;
                int ci = 2 * ks + (grp >> 1);
                uint32_t ad = base + 8192u + row * 64 + ((ci ^ ((row >> 1) & 3)) * 16);
                uint32_t r0, r1, r2, r3;
                LDSM4(r0, r1, r2, r3, ad);
                bhf[2*g][0] = r0; bhf[2*g+1][0] = r1; bhf[2*g][1] = r2; bhf[2*g+1][1] = r3;
            }
            #pragma unroll
            for (int mi = 0; mi < 4; mi++)
                #pragma unroll
                for (int nj = 0; nj < 4; nj++)
                    MMA16816(acc[mi][nj], ahf[mi], bhf[nj][0], bhf[nj][1]);
        }
    };

    loadAB(0, 0); CPCOMMIT();
    if (NC > 1) loadAB(1, 1);
    CPCOMMIT();
    #pragma unroll 1
    for (int c = 0; c < NC; c++) {
        int nxt = c + 2;
        CPWAIT(1);
        __syncthreads();
        if (nxt < NC) loadAB(nxt, nxt % NSTG);
        CPCOMMIT();
        compute(c % NSTG);
    }

    GEMM_EPILOGUE(acc, N, bias, res, outF, outH, relu)
}

// ---------------- Chunked local attention (fp16 in, fp16 out) --------------
__global__ void attn_kernel(const __half* __restrict__ qkv, const __half* __restrict__ p,
                            const float* __restrict__ pbu, const float* __restrict__ pbv,
                            __half* __restrict__ o) {
    int ci = blockIdx.x, h = blockIdx.y, b = blockIdx.z;
    int s0 = max((ci - LC_) * CS_, 0);
    int s1 = (ci + 1) * CS_;
    int W = s1 - s0;
    int t0 = ci * CS_;
    int tid = threadIdx.x;                    // 256 threads

    extern __shared__ char asmem[];
    __half* Ks = (__half*)asmem;              // WMAX*64 halves
    __half* Ps = Ks + WMAX_ * 64;
    __half* QU = Ps + WMAX_ * 64;             // 16*64
    __half* QV = QU + 16 * 64;
    float* Vs = (float*)(QV + 16 * 64);       // WMAX*64 floats
    float* SC = Vs + WMAX_ * 64;              // 16*WMAX

    for (int idx = tid; idx < W * 64; idx += 256) {
        int s = idx >> 6, d = idx & 63;
        size_t gi = (size_t)((b * T_) + s0 + s) * QKVN_ + h * DK_ + d;
        Ks[idx] = qkv[gi + D_];
        Vs[idx] = __half2float(qkv[gi + 2 * D_]);
        Ps[idx] = p[(size_t)(s0 + s) * PALLN_ + h * DK_ + d];
    }
    for (int idx = tid; idx < 16 * 64; idx += 256) {
        int qi = idx >> 6, d = idx & 63;
        float qv_ = __half2float(qkv[(size_t)((b * T_) + t0 + qi) * QKVN_ + h * DK_ + d]);
        QU[idx] = __float2half(qv_ + pbu[h * DK_ + d]);
        QV[idx] = __float2half(qv_ + pbv[h * DK_ + d]);
    }
    __syncthreads();

    const float scale = 0.125f;
    int Wh = W >> 1;
    for (int it = tid; it < 8 * Wh; it += 256) {
        int qi = (it / Wh) * 2, s = (it % Wh) * 2;
        float a00 = 0, a01 = 0, a10 = 0, a11 = 0;
        #pragma unroll 4
        for (int d = 0; d < 64; d += 4) {
            float4 qu0 = ld4h(&QU[qi * 64 + d]);
            float4 qu1 = ld4h(&QU[(qi + 1) * 64 + d]);
            float4 qv0 = ld4h(&QV[qi * 64 + d]);
            float4 qv1 = ld4h(&QV[(qi + 1) * 64 + d]);
            float4 k0 = ld4h(&Ks[s * 64 + d]);
            float4 k1 = ld4h(&Ks[(s + 1) * 64 + d]);
            float4 p0 = ld4h(&Ps[s * 64 + d]);
            float4 p1 = ld4h(&Ps[(s + 1) * 64 + d]);
            a00 += dot4(qu0, k0) + dot4(qv0, p0);
            a01 += dot4(qu0, k1) + dot4(qv0, p1);
            a10 += dot4(qu1, k0) + dot4(qv1, p0);
            a11 += dot4(qu1, k1) + dot4(qv1, p1);
        }
        SC[qi * WMAX_ + s]           = a00 * scale;
        SC[qi * WMAX_ + s + 1]       = a01 * scale;
        SC[(qi + 1) * WMAX_ + s]     = a10 * scale;
        SC[(qi + 1) * WMAX_ + s + 1] = a11 * scale;
    }
    __syncthreads();

    int warp = tid >> 5, lane = tid & 31;
    for (int qi = warp; qi < 16; qi += 8) {
        float m = -1e30f;
        for (int s = lane; s < W; s += 32) m = fmaxf(m, SC[qi * WMAX_ + s]);
        #pragma unroll
        for (int off = 16; off; off >>= 1) m = fmaxf(m, __shfl_xor_sync(0xffffffffu, m, off));
        float sum = 0.0f;
        for (int s = lane; s < W; s += 32) {
            float e = expf(SC[qi * WMAX_ + s] - m);
            SC[qi * WMAX_ + s] = e;
            sum += e;
        }
        #pragma unroll
        for (int off = 16; off; off >>= 1) sum += __shfl_xor_sync(0xffffffffu, sum, off);
        float inv = 1.0f / sum;
        for (int s = lane; s < W; s += 32) SC[qi * WMAX_ + s] *= inv;
    }
    __syncthreads();

    {
        int it = tid;                       // 8 * 32 = 256
        int qi = (it >> 5) * 2, d = (it & 31) * 2;
        float a00 = 0, a01 = 0, a10 = 0, a11 = 0;
        for (int s = 0; s < W; s++) {
            float2 vv = *(const float2*)&Vs[s * 64 + d];
            float c0 = SC[qi * WMAX_ + s];
            float c1 = SC[(qi + 1) * WMAX_ + s];
            a00 += c0 * vv.x; a01 += c0 * vv.y;
            a10 += c1 * vv.x; a11 += c1 * vv.y;
        }
        size_t o0 = (size_t)((b * T_) + t0 + qi) * D_ + h * DK_ + d;
        *(__half2*)(o + o0)      = __halves2half2(__float2half_rn(a00), __float2half_rn(a01));
        *(__half2*)(o + o0 + D_) = __halves2half2(__float2half_rn(a10), __float2half_rn(a11));
    }
}

static const int ATTN_SMEM = (WMAX_*64*2 + 16*64*2) * 2 + (WMAX_*64 + 16*WMAX_) * 4; // 50176
static const int GEMM_SMEM = NSTG * STAGE_BYTES;   // 49152

extern "C" void kernel_launch(void* const* d_in, const int* in_sizes, int n_in,
                              void* d_out, int out_size) {
    (void)in_sizes; (void)n_in; (void)out_size;
    const float* xs    = (const float*)d_in[0];
    const float* pos   = (const float*)d_in[1];
    // d_in[2] = mask: unused (window computed analytically)
    const float* Wq    = (const float*)d_in[3];
    const float* bq    = (const float*)d_in[4];
    const float* Wk    = (const float*)d_in[5];
    const float* bk    = (const float*)d_in[6];
    const float* Wv    = (const float*)d_in[7];
    const float* bv    = (const float*)d_in[8];
    const float* Wo    = (const float*)d_in[9];
    const float* bo    = (const float*)d_in[10];
    const float* Wp    = (const float*)d_in[11];
    const float* pbu   = (const float*)d_in[12];
    const float* pbv   = (const float*)d_in[13];
    const float* ln1s  = (const float*)d_in[14];
    const float* ln1b  = (const float*)d_in[15];
    const float* ln2s  = (const float*)d_in[16];
    const float* ln2b  = (const float*)d_in[17];
    const float* W1    = (const float*)d_in[18];
    const float* b1    = (const float*)d_in[19];
    const float* W2    = (const float*)d_in[20];
    const float* b2    = (const float*)d_in[21];
    const float* lnfs  = (const float*)d_in[22];
    const float* lnfb  = (const float*)d_in[23];

    cudaFuncSetAttribute(attn_kernel, cudaFuncAttributeMaxDynamicSharedMemorySize, ATTN_SMEM);
    cudaFuncSetAttribute(gemm_f32a,   cudaFuncAttributeMaxDynamicSharedMemorySize, GEMM_SMEM);
    cudaFuncSetAttribute(gemm_f16a,   cudaFuncAttributeMaxDynamicSharedMemorySize, GEMM_SMEM);

    void* a;
    #define SYM(p, s) cudaGetSymbolAddress(&a, s); auto* p = (decltype(&s[0]))a;
    SYM(px, g_x)  SYM(pqkvh, g_qkvh)  SYM(poh, g_oh)  SYM(pffh, g_ffh)
    SYM(ppall, g_pall)  SYM(pbqkv, g_bqkv)  SYM(pst, g_st)
    SYM(pwqkvh, g_wqkvh)
    SYM(pwoh, g_woh)
    SYM(pwph, g_wph)
    SYM(pw1h, g_w1h)
    SYM(pw2h, g_w2h)
    #undef SYM

    const int M = B_ * T_;  // 4096
    const size_t DD = (size_t)D_ * D_;          // 262144
    const size_t QKVLS = (size_t)QKVN_ * D_;    // 786432
    dim3 wtb(32, 8);

    scale_kernel<<<(B_*T_*D_) / 256, 256>>>(xs, sqrtf((float)D_));
    bcat_kernel<<<(L_*QKVN_) / 256, 256>>>(bq, bk, bv);
    wtransqkv_kernel<<<dim3(16, 16, 3 * L_), wtb>>>(Wq, Wk, Wv, pwqkvh);
    lnstats_kernel<<<M / 8, 256>>>(px, pst);
    wtrans_kernel<<<dim3(D_/32, D_/32, L_), wtb>>>(Wo, pwoh, D_, D_, DD, DD);
    // layer-0 fused QKV GEMM early (profiling target position)
    gemm_f32a<<<dim3(QKVN_/128, M/128), 256, GEMM_SMEM>>>(px, pst,
        ln1s, ln1b, pwqkvh, pbqkv, nullptr, nullptr, pqkvh, QKVN_, D_, 0);
    // remaining prep
    wtrans_kernel<<<dim3(D_/32,  D_/32,  L_), wtb>>>(Wp, pwph, D_,  D_,  DD, DD);
    wtrans_kernel<<<dim3(FF_/32, D_/32,  L_), wtb>>>(W1, pw1h, D_,  FF_, (size_t)D_*FF_, (size_t)D_*FF_);
    wtrans_kernel<<<dim3(D_/32,  FF_/32, L_), wtb>>>(W2, pw2h, FF_, D_,  (size_t)FF_*D_, (size_t)FF_*D_);
    gemm_f32a<<<dim3(PALLN_/128, T_/128), 256, GEMM_SMEM>>>(pos, nullptr, nullptr, nullptr,
        pwph, nullptr, nullptr, nullptr, ppall, PALLN_, D_, 0);

    for (int l = 0; l < L_; l++) {
        size_t wdf = (size_t)l * D_ * FF_;

        if (l > 0) {
            lnstats_kernel<<<M / 8, 256>>>(px, pst);
            gemm_f32a<<<dim3(QKVN_/128, M/128), 256, GEMM_SMEM>>>(px, pst,
                ln1s + l*D_, ln1b + l*D_,
                pwqkvh + l * QKVLS,
                pbqkv + l * QKVN_, nullptr, nullptr, pqkvh, QKVN_, D_, 0);
        }

        // attention -> o fp16
        attn_kernel<<<dim3(NCHUNK_, H_, B_), 256, ATTN_SMEM>>>(
            pqkvh, ppall + l * D_, pbu + l * H_ * DK_, pbv + l * H_ * DK_, poh);

        // x = x + o @ Wo + bo   (A fp16 via cp.async)
        gemm_f16a<<<dim3(D_/128, M/128), 256, GEMM_SMEM>>>(poh,
            pwoh + l * DD, bo + l*D_, px, px, nullptr, D_, D_, 0);

        // row stats for LN2
        lnstats_kernel<<<M / 8, 256>>>(px, pst);

        // ff = relu(LN2(x) @ W1 + b1) -> fp16
        gemm_f32a<<<dim3(FF_/128, M/128), 256, GEMM_SMEM>>>(px, pst,
            ln2s + l*D_, ln2b + l*D_,
            pw1h + wdf,
            b1 + l*FF_, nullptr, nullptr, pffh, FF_, D_, 1);

        // x = x + ff @ W2 + b2  (A fp16 via cp.async)
        gemm_f16a<<<dim3(D_/128, M/128), 256, GEMM_SMEM>>>(pffh,
            pw2h + wdf, b2 + l*D_, px, px, nullptr, D_, FF_, 0);
    }

    // out = LNf(x)  (fp32)
    ln_kernel<<<M, 256>>>(px, (float*)d_out, lnfs, lnfb);
}

// round 12
// speedup vs baseline: 2.9609x; 1.1397x over previous
#include <cuda_runtime.h>
#include <cuda_fp16.h>
#include <math.h>
#include <stdint.h>

// Problem constants
#define B_  8
#define T_  512
#define D_  512
#define H_  8
#define FF_ 2048
#define L_  6
#define CS_ 16
#define LC_ 4
#define DK_ 64
#define NCHUNK_ (T_ / CS_)          // 32
#define WMAX_ ((LC_ + 1) * CS_)     // 80
#define QKVN_ (3 * D_)              // 1536
#define PALLN_ (L_ * D_)            // 3072

// ---------------- scratch (device globals; no allocation) ----------------
__device__ float  g_x   [B_*T_*D_];
__device__ __half g_hh  [B_*T_*D_];     // LN output fp16
__device__ __half g_qkvh[B_*T_*QKVN_];
__device__ __half g_oh  [B_*T_*D_];
__device__ __half g_ffh [B_*T_*FF_];
__device__ __half g_pall[T_*PALLN_];
__device__ __half g_posh[T_*D_];
__device__ float  g_bqkv[L_*QKVN_];

// transposed fp16 weights: Wt[n][k] (round-to-nearest)
__device__ __half g_wqkvh[L_*QKVN_*D_];
__device__ __half g_woh[L_*D_*D_];
__device__ __half g_wph[L_*D_*D_];
__device__ __half g_w1h[L_*D_*FF_];
__device__ __half g_w2h[L_*FF_*D_];

// ---------------- PTX helpers (family-portable: sm_80+ ISA only) ----------
__device__ __forceinline__ uint32_t s2u(const void* p) {
    uint32_t a;
    asm("{ .reg .u64 t; cvta.to.shared.u64 t, %1; cvt.u32.u64 %0, t; }" : "=r"(a) : "l"(p));
    return a;
}

#define CPA16(sa, g) \
    asm volatile("cp.async.cg.shared.global [%0], [%1], 16;" :: "r"(sa), "l"(g) : "memory")
#define CPCOMMIT() asm volatile("cp.async.commit_group;" ::: "memory")
#define CPWAIT(n)  asm volatile("cp.async.wait_group %0;" :: "n"(n) : "memory")

#define LDSM4(d0, d1, d2, d3, a) \
    asm volatile("ldmatrix.sync.aligned.m8n8.x4.shared.b16 {%0,%1,%2,%3}, [%4];" \
        : "=r"(d0), "=r"(d1), "=r"(d2), "=r"(d3) : "r"(a))

#define MMA16816(c, a, b0, b1) \
    asm volatile("mma.sync.aligned.m16n8k16.row.col.f32.f16.f16.f32 " \
        "{%0,%1,%2,%3}, {%4,%5,%6,%7}, {%8,%9}, {%0,%1,%2,%3};" \
        : "+f"((c)[0]), "+f"((c)[1]), "+f"((c)[2]), "+f"((c)[3]) \
        : "r"((a)[0]), "r"((a)[1]), "r"((a)[2]), "r"((a)[3]), "r"(b0), "r"(b1))

__device__ __forceinline__ float4 ld4h(const __half* p) {
    uint2 u = *(const uint2*)p;
    __half2 a = *reinterpret_cast<__half2*>(&u.x);
    __half2 b = *reinterpret_cast<__half2*>(&u.y);
    float2 fa = __half22float2(a), fb = __half22float2(b);
    return make_float4(fa.x, fa.y, fb.x, fb.y);
}
__device__ __forceinline__ float dot4(float4 a, float4 b) {
    return a.x * b.x + a.y * b.y + a.z * b.z + a.w * b.w;
}

// ---------------- elementwise scale: x = xs * sqrt(D) ----------------
__global__ void scale_kernel(const float* __restrict__ xs, float s) {
    int i = blockIdx.x * blockDim.x + threadIdx.x;
    g_x[i] = xs[i] * s;
}

// ---------------- pos_emb -> fp16 ----------------
__global__ void posconv_kernel(const float* __restrict__ pos) {
    int i = blockIdx.x * blockDim.x + threadIdx.x;
    g_posh[i] = __float2half_rn(pos[i]);
}

// ---------------- bias concat for fused QKV ----------------
__global__ void bcat_kernel(const float* __restrict__ bq, const float* __restrict__ bk,
                            const float* __restrict__ bv) {
    int i = blockIdx.x * blockDim.x + threadIdx.x;   // L*1536
    int l = i / QKVN_, c = i % QKVN_;
    float v = (c < D_) ? bq[l * D_ + c]
            : (c < 2 * D_) ? bk[l * D_ + c - D_]
            : bv[l * D_ + c - 2 * D_];
    g_bqkv[i] = v;
}

// ---------------- merged QKV weight transpose (fp16 rn) ----------------
__global__ void wtransqkv_kernel(const float* __restrict__ Wq,
                                 const float* __restrict__ Wk,
                                 const float* __restrict__ Wv,
                                 __half* __restrict__ Th) {
    __shared__ float sm[32][33];
    int z = blockIdx.z;
    int which = z / L_, l = z % L_;
    const size_t DD = (size_t)D_ * D_;
    const float* Wl = (which == 0 ? Wq : which == 1 ? Wk : Wv) + (size_t)l * DD;
    __half* Thl = Th + (size_t)l * QKVN_ * D_ + (size_t)which * DD;
    int n0 = blockIdx.x * 32, k0 = blockIdx.y * 32;
    int tx = threadIdx.x, ty = threadIdx.y;
    #pragma unroll
    for (int j = 0; j < 4; j++)
        sm[ty + j * 8][tx] = Wl[(size_t)(k0 + ty + j * 8) * D_ + n0 + tx];
    __syncthreads();
    #pragma unroll
    for (int j = 0; j < 4; j++) {
        int n = ty + j * 8;
        Thl[(size_t)(n0 + n) * D_ + k0 + tx] = __float2half_rn(sm[tx][n]);
    }
}

// ---------------- generic weight transpose (fp16 rn) ----------------
__global__ void wtrans_kernel(const float* __restrict__ W, __half* __restrict__ Th,
                              int K, int N, size_t srcLS, size_t dstLS) {
    __shared__ float sm[32][33];
    const float* Wl = W + (size_t)blockIdx.z * srcLS;
    __half* Thl = Th + (size_t)blockIdx.z * dstLS;
    int n0 = blockIdx.x * 32, k0 = blockIdx.y * 32;
    int tx = threadIdx.x, ty = threadIdx.y;
    #pragma unroll
    for (int j = 0; j < 4; j++)
        sm[ty + j * 8][tx] = Wl[(size_t)(k0 + ty + j * 8) * N + n0 + tx];
    __syncthreads();
    #pragma unroll
    for (int j = 0; j < 4; j++) {
        int n = ty + j * 8;
        Thl[(size_t)(n0 + n) * K + k0 + tx] = __float2half_rn(sm[tx][n]);
    }
}

// ---------------- LN -> fp16: one warp per row ----------------
__global__ void ln_h16_kernel(const float* __restrict__ in, __half* __restrict__ out,
                              const float* __restrict__ gam, const float* __restrict__ bet) {
    int warp = threadIdx.x >> 5, lane = threadIdx.x & 31;
    int row = blockIdx.x * 8 + warp;
    const float4* x = (const float4*)(in + (size_t)row * D_);
    float4 v[4];
    float s = 0.0f, ss = 0.0f;
    #pragma unroll
    for (int j = 0; j < 4; j++) {
        v[j] = x[lane + j * 32];
        s  += v[j].x + v[j].y + v[j].z + v[j].w;
        ss += v[j].x * v[j].x + v[j].y * v[j].y + v[j].z * v[j].z + v[j].w * v[j].w;
    }
    #pragma unroll
    for (int off = 16; off; off >>= 1) {
        s  += __shfl_xor_sync(0xffffffffu, s,  off);
        ss += __shfl_xor_sync(0xffffffffu, ss, off);
    }
    float mean = s * (1.0f / D_);
    float var  = ss * (1.0f / D_) - mean * mean;
    float inv  = rsqrtf(var + 1e-5f);
    __half* y = out + (size_t)row * D_;
    #pragma unroll
    for (int j = 0; j < 4; j++) {
        int e = (lane + j * 32) * 4;
        float4 g = *(const float4*)(gam + e);
        float4 b = *(const float4*)(bet + e);
        __half2 h0 = __halves2half2(__float2half_rn((v[j].x - mean) * inv * g.x + b.x),
                                    __float2half_rn((v[j].y - mean) * inv * g.y + b.y));
        __half2 h1 = __halves2half2(__float2half_rn((v[j].z - mean) * inv * g.z + b.z),
                                    __float2half_rn((v[j].w - mean) * inv * g.w + b.w));
        *(__half2*)(y + e)     = h0;
        *(__half2*)(y + e + 2) = h1;
    }
}

// ---------------- final LN ----------------
__global__ void ln_kernel(const float* __restrict__ in, float* __restrict__ out,
                          const float* __restrict__ gam, const float* __restrict__ bet) {
    __shared__ float sh_s[8], sh_ss[8];
    int row = blockIdx.x, tid = threadIdx.x;
    const float* x = in + (size_t)row * D_;
    float v0 = x[tid], v1 = x[tid + 256];
    float s = v0 + v1, ss = v0 * v0 + v1 * v1;
    int lane = tid & 31, warp = tid >> 5;
    #pragma unroll
    for (int off = 16; off; off >>= 1) {
        s  += __shfl_xor_sync(0xffffffffu, s,  off);
        ss += __shfl_xor_sync(0xffffffffu, ss, off);
    }
    if (lane == 0) { sh_s[warp] = s; sh_ss[warp] = ss; }
    __syncthreads();
    if (warp == 0) {
        float a = (lane < 8) ? sh_s[lane]  : 0.0f;
        float b = (lane < 8) ? sh_ss[lane] : 0.0f;
        #pragma unroll
        for (int off = 4; off; off >>= 1) {
            a += __shfl_xor_sync(0xffffffffu, a, off);
            b += __shfl_xor_sync(0xffffffffu, b, off);
        }
        if (lane == 0) { sh_s[0] = a; sh_ss[0] = b; }
    }
    __syncthreads();
    float mean = sh_s[0] * (1.0f / D_);
    float var  = sh_ss[0] * (1.0f / D_) - mean * mean;
    float inv  = rsqrtf(var + 1e-5f);
    float* y = out + (size_t)row * D_;
    y[tid]       = (v0 - mean) * inv * gam[tid]       + bet[tid];
    y[tid + 256] = (v1 - mean) * inv * gam[tid + 256] + bet[tid + 256];
}

// ---------------- HMMA fp16 GEMM, fp16 A/B via cp.async, BK=64 ------------
// BM=128, BN=128, BK=64; 8 warps (2x4), warp tile 64x32.
// Stage = A(16KB) + B(16KB) = 32KB; 3 stages, 2 CTAs/SM.
#define STAGE_BYTES 32768
#define NSTG 3
__global__ void __launch_bounds__(256, 2)
gemm_f16a(const __half* __restrict__ Ah, const __half* __restrict__ Bh,
          const float* __restrict__ bias, const float* __restrict__ res,
          float* __restrict__ outF, __half* __restrict__ outH,
          int N, int K, int relu) {
    extern __shared__ char smem[];
    uint32_t sb = s2u(smem);
    int tid = threadIdx.x, lane = tid & 31, wid = tid >> 5;
    int wm = wid >> 2, wn = wid & 3;
    int rowBase = blockIdx.y * 128, colBase = blockIdx.x * 128;
    int sub = lane & 7, grp = lane >> 3;

    float acc[4][4][4];
    #pragma unroll
    for (int i = 0; i < 4; i++)
        #pragma unroll
        for (int j = 0; j < 4; j++)
            #pragma unroll
            for (int c = 0; c < 4; c++) acc[i][j][c] = 0.0f;

    const int NC = K >> 6;

    auto loadAB = [&](int c, int buf) {
        uint32_t sbase = sb + buf * STAGE_BYTES;
        int k0 = c << 6;
        #pragma unroll
        for (int i = 0; i < 4; i++) {
            int id = tid + (i << 8);
            int row = id >> 3, ch = id & 7;
            int phys = ch ^ (row & 7);
            uint32_t so = sbase + row * 128 + phys * 16;
            CPA16(so,           Ah + (size_t)(rowBase + row) * K + k0 + ch * 8);
            CPA16(so + 16384u,  Bh + (size_t)(colBase + row) * K + k0 + ch * 8);
        }
    };

    auto compute = [&](int buf) {
        uint32_t base = sb + buf * STAGE_BYTES;
        #pragma unroll
        for (int ks = 0; ks < 4; ks++) {
            uint32_t ahf[4][4], bhf[4][2];
            int ci = 2 * ks + (grp >> 1);
            #pragma unroll
            for (int mi = 0; mi < 4; mi++) {
                int row = wm * 64 + mi * 16 + sub + (grp & 1) * 8;
                uint32_t ad = base + row * 128 + ((ci ^ (row & 7)) * 16);
                LDSM4(ahf[mi][0], ahf[mi][1], ahf[mi][2], ahf[mi][3], ad);
            }
            #pragma unroll
            for (int g = 0; g < 2; g++) {
                int row = wn * 32 + g * 16 + sub + (grp & 1) * 8;
                uint32_t ad = base + 16384u + row * 128 + ((ci ^ (row & 7)) * 16);
                uint32_t r0, r1, r2, r3;
                LDSM4(r0, r1, r2, r3, ad);
                bhf[2*g][0] = r0; bhf[2*g+1][0] = r1; bhf[2*g][1] = r2; bhf[2*g+1][1] = r3;
            }
            #pragma unroll
            for (int mi = 0; mi < 4; mi++)
                #pragma unroll
                for (int nj = 0; nj < 4; nj++)
                    MMA16816(acc[mi][nj], ahf[mi], bhf[nj][0], bhf[nj][1]);
        }
    };

    loadAB(0, 0); CPCOMMIT();
    if (NC > 1) loadAB(1, 1);
    CPCOMMIT();
    #pragma unroll 1
    for (int c = 0; c < NC; c++) {
        int nxt = c + 2;
        CPWAIT(1);
        __syncthreads();
        if (nxt < NC) loadAB(nxt, nxt % NSTG);
        CPCOMMIT();
        compute(c % NSTG);
    }

    // --- epilogue ---
    #pragma unroll
    for (int mi = 0; mi < 4; mi++) {
        #pragma unroll
        for (int nj = 0; nj < 4; nj++) {
            int r = rowBase + wm * 64 + mi * 16 + (lane >> 2);
            int c = colBase + wn * 32 + nj * 8 + ((lane & 3) << 1);
            #pragma unroll
            for (int half_ = 0; half_ < 2; half_++) {
                int rr = r + half_ * 8;
                float v0 = acc[mi][nj][half_ * 2 + 0];
                float v1 = acc[mi][nj][half_ * 2 + 1];
                if (bias) { v0 += bias[c]; v1 += bias[c + 1]; }
                if (res) {
                    float2 rv = *(const float2*)(res + (size_t)rr * N + c);
                    v0 += rv.x; v1 += rv.y;
                }
                if (relu) { v0 = fmaxf(v0, 0.0f); v1 = fmaxf(v1, 0.0f); }
                if (outF)
                    *(float2*)(outF + (size_t)rr * N + c) = make_float2(v0, v1);
                else
                    *(__half2*)(outH + (size_t)rr * N + c) =
                        __halves2half2(__float2half_rn(v0), __float2half_rn(v1));
            }
        }
    }
}

// ---------------- Chunked local attention (fp16 in, fp16 out) --------------
__global__ void attn_kernel(const __half* __restrict__ qkv, const __half* __restrict__ p,
                            const float* __restrict__ pbu, const float* __restrict__ pbv,
                            __half* __restrict__ o) {
    int ci = blockIdx.x, h = blockIdx.y, b = blockIdx.z;
    int s0 = max((ci - LC_) * CS_, 0);
    int s1 = (ci + 1) * CS_;
    int W = s1 - s0;
    int t0 = ci * CS_;
    int tid = threadIdx.x;                    // 256 threads

    extern __shared__ char asmem[];
    __half* Ks = (__half*)asmem;              // WMAX*64 halves
    __half* Ps = Ks + WMAX_ * 64;
    __half* QU = Ps + WMAX_ * 64;             // 16*64
    __half* QV = QU + 16 * 64;
    float* Vs = (float*)(QV + 16 * 64);       // WMAX*64 floats
    float* SC = Vs + WMAX_ * 64;              // 16*WMAX

    for (int idx = tid; idx < W * 64; idx += 256) {
        int s = idx >> 6, d = idx & 63;
        size_t gi = (size_t)((b * T_) + s0 + s) * QKVN_ + h * DK_ + d;
        Ks[idx] = qkv[gi + D_];
        Vs[idx] = __half2float(qkv[gi + 2 * D_]);
        Ps[idx] = p[(size_t)(s0 + s) * PALLN_ + h * DK_ + d];
    }
    for (int idx = tid; idx < 16 * 64; idx += 256) {
        int qi = idx >> 6, d = idx & 63;
        float qv_ = __half2float(qkv[(size_t)((b * T_) + t0 + qi) * QKVN_ + h * DK_ + d]);
        QU[idx] = __float2half(qv_ + pbu[h * DK_ + d]);
        QV[idx] = __float2half(qv_ + pbv[h * DK_ + d]);
    }
    __syncthreads();

    const float scale = 0.125f;
    int Wh = W >> 1;
    for (int it = tid; it < 8 * Wh; it += 256) {
        int qi = (it / Wh) * 2, s = (it % Wh) * 2;
        float a00 = 0, a01 = 0, a10 = 0, a11 = 0;
        #pragma unroll 4
        for (int d = 0; d < 64; d += 4) {
            float4 qu0 = ld4h(&QU[qi * 64 + d]);
            float4 qu1 = ld4h(&QU[(qi + 1) * 64 + d]);
            float4 qv0 = ld4h(&QV[qi * 64 + d]);
            float4 qv1 = ld4h(&QV[(qi + 1) * 64 + d]);
            float4 k0 = ld4h(&Ks[s * 64 + d]);
            float4 k1 = ld4h(&Ks[(s + 1) * 64 + d]);
            float4 p0 = ld4h(&Ps[s * 64 + d]);
            float4 p1 = ld4h(&Ps[(s + 1) * 64 + d]);
            a00 += dot4(qu0, k0) + dot4(qv0, p0);
            a01 += dot4(qu0, k1) + dot4(qv0, p1);
            a10 += dot4(qu1, k0) + dot4(qv1, p0);
            a11 += dot4(qu1, k1) + dot4(qv1, p1);
        }
        SC[qi * WMAX_ + s]           = a00 * scale;
        SC[qi * WMAX_ + s + 1]       = a01 * scale;
        SC[(qi + 1) * WMAX_ + s]     = a10 * scale;
        SC[(qi + 1) * WMAX_ + s + 1] = a11 * scale;
    }
    __syncthreads();

    int warp = tid >> 5, lane = tid & 31;
    for (int qi = warp; qi < 16; qi += 8) {
        float m = -1e30f;
        for (int s = lane; s < W; s += 32) m = fmaxf(m, SC[qi * WMAX_ + s]);
        #pragma unroll
        for (int off = 16; off; off >>= 1) m = fmaxf(m, __shfl_xor_sync(0xffffffffu, m, off));
        float sum = 0.0f;
        for (int s = lane; s < W; s += 32) {
            float e = expf(SC[qi * WMAX_ + s] - m);
            SC[qi * WMAX_ + s] = e;
            sum += e;
        }
        #pragma unroll
        for (int off = 16; off; off >>= 1) sum += __shfl_xor_sync(0xffffffffu, sum, off);
        float inv = 1.0f / sum;
        for (int s = lane; s < W; s += 32) SC[qi * WMAX_ + s] *= inv;
    }
    __syncthreads();

    {
        int it = tid;                       // 8 * 32 = 256
        int qi = (it >> 5) * 2, d = (it & 31) * 2;
        float a00 = 0, a01 = 0, a10 = 0, a11 = 0;
        for (int s = 0; s < W; s++) {
            float2 vv = *(const float2*)&Vs[s * 64 + d];
            float c0 = SC[qi * WMAX_ + s];
            float c1 = SC[(qi + 1) * WMAX_ + s];
            a00 += c0 * vv.x; a01 += c0 * vv.y;
            a10 += c1 * vv.x; a11 += c1 * vv.y;
        }
        size_t o0 = (size_t)((b * T_) + t0 + qi) * D_ + h * DK_ + d;
        *(__half2*)(o + o0)      = __halves2half2(__float2half_rn(a00), __float2half_rn(a01));
        *(__half2*)(o + o0 + D_) = __halves2half2(__float2half_rn(a10), __float2half_rn(a11));
    }
}

static const int ATTN_SMEM = (WMAX_*64*2 + 16*64*2) * 2 + (WMAX_*64 + 16*WMAX_) * 4; // 50176
static const int GEMM_SMEM = NSTG * STAGE_BYTES;   // 98304

extern "C" void kernel_launch(void* const* d_in, const int* in_sizes, int n_in,
                              void* d_out, int out_size) {
    (void)in_sizes; (void)n_in; (void)out_size;
    const float* xs    = (const float*)d_in[0];
    const float* pos   = (const float*)d_in[1];
    // d_in[2] = mask: unused (window computed analytically)
    const float* Wq    = (const float*)d_in[3];
    const float* bq    = (const float*)d_in[4];
    const float* Wk    = (const float*)d_in[5];
    const float* bk    = (const float*)d_in[6];
    const float* Wv    = (const float*)d_in[7];
    const float* bv    = (const float*)d_in[8];
    const float* Wo    = (const float*)d_in[9];
    const float* bo    = (const float*)d_in[10];
    const float* Wp    = (const float*)d_in[11];
    const float* pbu   = (const float*)d_in[12];
    const float* pbv   = (const float*)d_in[13];
    const float* ln1s  = (const float*)d_in[14];
    const float* ln1b  = (const float*)d_in[15];
    const float* ln2s  = (const float*)d_in[16];
    const float* ln2b  = (const float*)d_in[17];
    const float* W1    = (const float*)d_in[18];
    const float* b1    = (const float*)d_in[19];
    const float* W2    = (const float*)d_in[20];
    const float* b2    = (const float*)d_in[21];
    const float* lnfs  = (const float*)d_in[22];
    const float* lnfb  = (const float*)d_in[23];

    cudaFuncSetAttribute(attn_kernel, cudaFuncAttributeMaxDynamicSharedMemorySize, ATTN_SMEM);
    cudaFuncSetAttribute(gemm_f16a,   cudaFuncAttributeMaxDynamicSharedMemorySize, GEMM_SMEM);

    void* a;
    #define SYM(p, s) cudaGetSymbolAddress(&a, s); auto* p = (decltype(&s[0]))a;
    SYM(px, g_x)  SYM(phh, g_hh)  SYM(pqkvh, g_qkvh)  SYM(poh, g_oh)  SYM(pffh, g_ffh)
    SYM(ppall, g_pall)  SYM(pposh, g_posh)  SYM(pbqkv, g_bqkv)
    SYM(pwqkvh, g_wqkvh)
    SYM(pwoh, g_woh)
    SYM(pwph, g_wph)
    SYM(pw1h, g_w1h)
    SYM(pw2h, g_w2h)
    #undef SYM

    const int M = B_ * T_;  // 4096
    const size_t DD = (size_t)D_ * D_;          // 262144
    const size_t QKVLS = (size_t)QKVN_ * D_;    // 786432
    dim3 wtb(32, 8);

    scale_kernel<<<(B_*T_*D_) / 256, 256>>>(xs, sqrtf((float)D_));
    posconv_kernel<<<(T_*D_) / 256, 256>>>(pos);
    bcat_kernel<<<(L_*QKVN_) / 256, 256>>>(bq, bk, bv);
    wtransqkv_kernel<<<dim3(16, 16, 3 * L_), wtb>>>(Wq, Wk, Wv, pwqkvh);
    wtrans_kernel<<<dim3(D_/32, D_/32, L_), wtb>>>(Wo, pwoh, D_, D_, DD, DD);
    wtrans_kernel<<<dim3(D_/32,  D_/32,  L_), wtb>>>(Wp, pwph, D_,  D_,  DD, DD);
    wtrans_kernel<<<dim3(FF_/32, D_/32,  L_), wtb>>>(W1, pw1h, D_,  FF_, (size_t)D_*FF_, (size_t)D_*FF_);
    wtrans_kernel<<<dim3(D_/32,  FF_/32, L_), wtb>>>(W2, pw2h, FF_, D_,  (size_t)FF_*D_, (size_t)FF_*D_);
    // p_all = pos_emb @ Wp (all layers, fp16 out)
    gemm_f16a<<<dim3(PALLN_/128, T_/128), 256, GEMM_SMEM>>>(pposh, pwph,
        nullptr, nullptr, nullptr, ppall, PALLN_, D_, 0);

    for (int l = 0; l < L_; l++) {
        size_t wdf = (size_t)l * D_ * FF_;

        // h = LN1(x) -> fp16
        ln_h16_kernel<<<M / 8, 256>>>(px, phh, ln1s + l*D_, ln1b + l*D_);

        // qkv = h @ [Wq|Wk|Wv] + b -> fp16
        gemm_f16a<<<dim3(QKVN_/128, M/128), 256, GEMM_SMEM>>>(phh,
            pwqkvh + l * QKVLS, pbqkv + l * QKVN_, nullptr, nullptr, pqkvh, QKVN_, D_, 0);

        // attention -> o fp16
        attn_kernel<<<dim3(NCHUNK_, H_, B_), 256, ATTN_SMEM>>>(
            pqkvh, ppall + l * D_, pbu + l * H_ * DK_, pbv + l * H_ * DK_, poh);

        // x = x + o @ Wo + bo
        gemm_f16a<<<dim3(D_/128, M/128), 256, GEMM_SMEM>>>(poh,
            pwoh + l * DD, bo + l*D_, px, px, nullptr, D_, D_, 0);

        // h2 = LN2(x) -> fp16
        ln_h16_kernel<<<M / 8, 256>>>(px, phh, ln2s + l*D_, ln2b + l*D_);

        // ff = relu(h2 @ W1 + b1) -> fp16
        gemm_f16a<<<dim3(FF_/128, M/128), 256, GEMM_SMEM>>>(phh,
            pw1h + wdf, b1 + l*FF_, nullptr, nullptr, pffh, FF_, D_, 1);

        // x = x + ff @ W2 + b2
        gemm_f16a<<<dim3(D_/128, M/128), 256, GEMM_SMEM>>>(pffh,
            pw2h + wdf, b2 + l*D_, px, px, nullptr, D_, FF_, 0);
    }

    // out = LNf(x)  (fp32)
    ln_kernel<<<M, 256>>>(px, (float*)d_out, lnfs, lnfb);
}

// round 13
// speedup vs baseline: 4.1895x; 1.4149x over previous
#include <cuda_runtime.h>
#include <cuda_fp16.h>
#include <math.h>
#include <stdint.h>

// Problem constants
#define B_  8
#define T_  512
#define D_  512
#define H_  8
#define FF_ 2048
#define L_  6
#define CS_ 16
#define LC_ 4
#define DK_ 64
#define NCHUNK_ (T_ / CS_)          // 32
#define WMAX_ ((LC_ + 1) * CS_)     // 80
#define QKVN_ (3 * D_)              // 1536
#define PALLN_ (L_ * D_)            // 3072
#define AP_ 66                      // padded attention row pitch (halves)

// ---------------- scratch (device globals; no allocation) ----------------
__device__ float  g_x   [B_*T_*D_];
__device__ __half g_hh  [B_*T_*D_];     // LN output fp16
__device__ __half g_qkvh[B_*T_*QKVN_];
__device__ __half g_oh  [B_*T_*D_];
__device__ __half g_ffh [B_*T_*FF_];
__device__ __half g_pall[T_*PALLN_];
__device__ __half g_posh[T_*D_];
__device__ float  g_bqkv[L_*QKVN_];

// transposed fp16 weights: Wt[n][k] (round-to-nearest)
__device__ __half g_wqkvh[L_*QKVN_*D_];
__device__ __half g_woh[L_*D_*D_];
__device__ __half g_wph[L_*D_*D_];
__device__ __half g_w1h[L_*D_*FF_];
__device__ __half g_w2h[L_*FF_*D_];

// ---------------- PTX helpers (family-portable: sm_80+ ISA only) ----------
__device__ __forceinline__ uint32_t s2u(const void* p) {
    uint32_t a;
    asm("{ .reg .u64 t; cvta.to.shared.u64 t, %1; cvt.u32.u64 %0, t; }" : "=r"(a) : "l"(p));
    return a;
}

#define CPA16(sa, g) \
    asm volatile("cp.async.cg.shared.global [%0], [%1], 16;" :: "r"(sa), "l"(g) : "memory")
#define CPCOMMIT() asm volatile("cp.async.commit_group;" ::: "memory")
#define CPWAIT(n)  asm volatile("cp.async.wait_group %0;" :: "n"(n) : "memory")

#define LDSM4(d0, d1, d2, d3, a) \
    asm volatile("ldmatrix.sync.aligned.m8n8.x4.shared.b16 {%0,%1,%2,%3}, [%4];" \
        : "=r"(d0), "=r"(d1), "=r"(d2), "=r"(d3) : "r"(a))

#define MMA16816(c, a, b0, b1) \
    asm volatile("mma.sync.aligned.m16n8k16.row.col.f32.f16.f16.f32 " \
        "{%0,%1,%2,%3}, {%4,%5,%6,%7}, {%8,%9}, {%0,%1,%2,%3};" \
        : "+f"((c)[0]), "+f"((c)[1]), "+f"((c)[2]), "+f"((c)[3]) \
        : "r"((a)[0]), "r"((a)[1]), "r"((a)[2]), "r"((a)[3]), "r"(b0), "r"(b1))

// ---------------- elementwise scale: x = xs * sqrt(D) ----------------
__global__ void scale_kernel(const float* __restrict__ xs, float s) {
    int i = blockIdx.x * blockDim.x + threadIdx.x;
    g_x[i] = xs[i] * s;
}

// ---------------- pos_emb -> fp16 ----------------
__global__ void posconv_kernel(const float* __restrict__ pos) {
    int i = blockIdx.x * blockDim.x + threadIdx.x;
    g_posh[i] = __float2half_rn(pos[i]);
}

// ---------------- bias concat for fused QKV ----------------
__global__ void bcat_kernel(const float* __restrict__ bq, const float* __restrict__ bk,
                            const float* __restrict__ bv) {
    int i = blockIdx.x * blockDim.x + threadIdx.x;   // L*1536
    int l = i / QKVN_, c = i % QKVN_;
    float v = (c < D_) ? bq[l * D_ + c]
            : (c < 2 * D_) ? bk[l * D_ + c - D_]
            : bv[l * D_ + c - 2 * D_];
    g_bqkv[i] = v;
}

// ---------------- merged QKV weight transpose (fp16 rn) ----------------
__global__ void wtransqkv_kernel(const float* __restrict__ Wq,
                                 const float* __restrict__ Wk,
                                 const float* __restrict__ Wv,
                                 __half* __restrict__ Th) {
    __shared__ float sm[32][33];
    int z = blockIdx.z;
    int which = z / L_, l = z % L_;
    const size_t DD = (size_t)D_ * D_;
    const float* Wl = (which == 0 ? Wq : which == 1 ? Wk : Wv) + (size_t)l * DD;
    __half* Thl = Th + (size_t)l * QKVN_ * D_ + (size_t)which * DD;
    int n0 = blockIdx.x * 32, k0 = blockIdx.y * 32;
    int tx = threadIdx.x, ty = threadIdx.y;
    #pragma unroll
    for (int j = 0; j < 4; j++)
        sm[ty + j * 8][tx] = Wl[(size_t)(k0 + ty + j * 8) * D_ + n0 + tx];
    __syncthreads();
    #pragma unroll
    for (int j = 0; j < 4; j++) {
        int n = ty + j * 8;
        Thl[(size_t)(n0 + n) * D_ + k0 + tx] = __float2half_rn(sm[tx][n]);
    }
}

// ---------------- generic weight transpose (fp16 rn) ----------------
__global__ void wtrans_kernel(const float* __restrict__ W, __half* __restrict__ Th,
                              int K, int N, size_t srcLS, size_t dstLS) {
    __shared__ float sm[32][33];
    const float* Wl = W + (size_t)blockIdx.z * srcLS;
    __half* Thl = Th + (size_t)blockIdx.z * dstLS;
    int n0 = blockIdx.x * 32, k0 = blockIdx.y * 32;
    int tx = threadIdx.x, ty = threadIdx.y;
    #pragma unroll
    for (int j = 0; j < 4; j++)
        sm[ty + j * 8][tx] = Wl[(size_t)(k0 + ty + j * 8) * N + n0 + tx];
    __syncthreads();
    #pragma unroll
    for (int j = 0; j < 4; j++) {
        int n = ty + j * 8;
        Thl[(size_t)(n0 + n) * K + k0 + tx] = __float2half_rn(sm[tx][n]);
    }
}

// ---------------- LN -> fp16: one warp per row ----------------
__global__ void ln_h16_kernel(const float* __restrict__ in, __half* __restrict__ out,
                              const float* __restrict__ gam, const float* __restrict__ bet) {
    int warp = threadIdx.x >> 5, lane = threadIdx.x & 31;
    int row = blockIdx.x * 8 + warp;
    const float4* x = (const float4*)(in + (size_t)row * D_);
    float4 v[4];
    float s = 0.0f, ss = 0.0f;
    #pragma unroll
    for (int j = 0; j < 4; j++) {
        v[j] = x[lane + j * 32];
        s  += v[j].x + v[j].y + v[j].z + v[j].w;
        ss += v[j].x * v[j].x + v[j].y * v[j].y + v[j].z * v[j].z + v[j].w * v[j].w;
    }
    #pragma unroll
    for (int off = 16; off; off >>= 1) {
        s  += __shfl_xor_sync(0xffffffffu, s,  off);
        ss += __shfl_xor_sync(0xffffffffu, ss, off);
    }
    float mean = s * (1.0f / D_);
    float var  = ss * (1.0f / D_) - mean * mean;
    float inv  = rsqrtf(var + 1e-5f);
    __half* y = out + (size_t)row * D_;
    #pragma unroll
    for (int j = 0; j < 4; j++) {
        int e = (lane + j * 32) * 4;
        float4 g = *(const float4*)(gam + e);
        float4 b = *(const float4*)(bet + e);
        __half2 h0 = __halves2half2(__float2half_rn((v[j].x - mean) * inv * g.x + b.x),
                                    __float2half_rn((v[j].y - mean) * inv * g.y + b.y));
        __half2 h1 = __halves2half2(__float2half_rn((v[j].z - mean) * inv * g.z + b.z),
                                    __float2half_rn((v[j].w - mean) * inv * g.w + b.w));
        *(__half2*)(y + e)     = h0;
        *(__half2*)(y + e + 2) = h1;
    }
}

// ---------------- final LN (fp32 out): one warp per row ----------------
__global__ void ln_f32_kernel(const float* __restrict__ in, float* __restrict__ out,
                              const float* __restrict__ gam, const float* __restrict__ bet) {
    int warp = threadIdx.x >> 5, lane = threadIdx.x & 31;
    int row = blockIdx.x * 8 + warp;
    const float4* x = (const float4*)(in + (size_t)row * D_);
    float4 v[4];
    float s = 0.0f, ss = 0.0f;
    #pragma unroll
    for (int j = 0; j < 4; j++) {
        v[j] = x[lane + j * 32];
        s  += v[j].x + v[j].y + v[j].z + v[j].w;
        ss += v[j].x * v[j].x + v[j].y * v[j].y + v[j].z * v[j].z + v[j].w * v[j].w;
    }
    #pragma unroll
    for (int off = 16; off; off >>= 1) {
        s  += __shfl_xor_sync(0xffffffffu, s,  off);
        ss += __shfl_xor_sync(0xffffffffu, ss, off);
    }
    float mean = s * (1.0f / D_);
    float var  = ss * (1.0f / D_) - mean * mean;
    float inv  = rsqrtf(var + 1e-5f);
    float* y = out + (size_t)row * D_;
    #pragma unroll
    for (int j = 0; j < 4; j++) {
        int e = (lane + j * 32) * 4;
        float4 g = *(const float4*)(gam + e);
        float4 b = *(const float4*)(bet + e);
        float4 o;
        o.x = (v[j].x - mean) * inv * g.x + b.x;
        o.y = (v[j].y - mean) * inv * g.y + b.y;
        o.z = (v[j].z - mean) * inv * g.z + b.z;
        o.w = (v[j].w - mean) * inv * g.w + b.w;
        *(float4*)(y + e) = o;
    }
}

// ---------------- HMMA fp16 GEMM, fp16 A/B via cp.async, BK=64 ------------
#define STAGE_BYTES 32768
#define NSTG 3
__global__ void __launch_bounds__(256, 2)
gemm_f16a(const __half* __restrict__ Ah, const __half* __restrict__ Bh,
          const float* __restrict__ bias, const float* __restrict__ res,
          float* __restrict__ outF, __half* __restrict__ outH,
          int N, int K, int relu) {
    extern __shared__ char smem[];
    uint32_t sb = s2u(smem);
    int tid = threadIdx.x, lane = tid & 31, wid = tid >> 5;
    int wm = wid >> 2, wn = wid & 3;
    int rowBase = blockIdx.y * 128, colBase = blockIdx.x * 128;
    int sub = lane & 7, grp = lane >> 3;

    float acc[4][4][4];
    #pragma unroll
    for (int i = 0; i < 4; i++)
        #pragma unroll
        for (int j = 0; j < 4; j++)
            #pragma unroll
            for (int c = 0; c < 4; c++) acc[i][j][c] = 0.0f;

    const int NC = K >> 6;

    auto loadAB = [&](int c, int buf) {
        uint32_t sbase = sb + buf * STAGE_BYTES;
        int k0 = c << 6;
        #pragma unroll
        for (int i = 0; i < 4; i++) {
            int id = tid + (i << 8);
            int row = id >> 3, ch = id & 7;
            int phys = ch ^ (row & 7);
            uint32_t so = sbase + row * 128 + phys * 16;
            CPA16(so,           Ah + (size_t)(rowBase + row) * K + k0 + ch * 8);
            CPA16(so + 16384u,  Bh + (size_t)(colBase + row) * K + k0 + ch * 8);
        }
    };

    auto compute = [&](int buf) {
        uint32_t base = sb + buf * STAGE_BYTES;
        #pragma unroll
        for (int ks = 0; ks < 4; ks++) {
            uint32_t ahf[4][4], bhf[4][2];
            int ci = 2 * ks + (grp >> 1);
            #pragma unroll
            for (int mi = 0; mi < 4; mi++) {
                int row = wm * 64 + mi * 16 + sub + (grp & 1) * 8;
                uint32_t ad = base + row * 128 + ((ci ^ (row & 7)) * 16);
                LDSM4(ahf[mi][0], ahf[mi][1], ahf[mi][2], ahf[mi][3], ad);
            }
            #pragma unroll
            for (int g = 0; g < 2; g++) {
                int row = wn * 32 + g * 16 + sub + (grp & 1) * 8;
                uint32_t ad = base + 16384u + row * 128 + ((ci ^ (row & 7)) * 16);
                uint32_t r0, r1, r2, r3;
                LDSM4(r0, r1, r2, r3, ad);
                bhf[2*g][0] = r0; bhf[2*g+1][0] = r1; bhf[2*g][1] = r2; bhf[2*g+1][1] = r3;
            }
            #pragma unroll
            for (int mi = 0; mi < 4; mi++)
                #pragma unroll
                for (int nj = 0; nj < 4; nj++)
                    MMA16816(acc[mi][nj], ahf[mi], bhf[nj][0], bhf[nj][1]);
        }
    };

    loadAB(0, 0); CPCOMMIT();
    if (NC > 1) loadAB(1, 1);
    CPCOMMIT();
    #pragma unroll 1
    for (int c = 0; c < NC; c++) {
        int nxt = c + 2;
        CPWAIT(1);
        __syncthreads();
        if (nxt < NC) loadAB(nxt, nxt % NSTG);
        CPCOMMIT();
        compute(c % NSTG);
    }

    // --- epilogue ---
    #pragma unroll
    for (int mi = 0; mi < 4; mi++) {
        #pragma unroll
        for (int nj = 0; nj < 4; nj++) {
            int r = rowBase + wm * 64 + mi * 16 + (lane >> 2);
            int c = colBase + wn * 32 + nj * 8 + ((lane & 3) << 1);
            #pragma unroll
            for (int half_ = 0; half_ < 2; half_++) {
                int rr = r + half_ * 8;
                float v0 = acc[mi][nj][half_ * 2 + 0];
                float v1 = acc[mi][nj][half_ * 2 + 1];
                if (bias) { v0 += bias[c]; v1 += bias[c + 1]; }
                if (res) {
                    float2 rv = *(const float2*)(res + (size_t)rr * N + c);
                    v0 += rv.x; v1 += rv.y;
                }
                if (relu) { v0 = fmaxf(v0, 0.0f); v1 = fmaxf(v1, 0.0f); }
                if (outF)
                    *(float2*)(outF + (size_t)rr * N + c) = make_float2(v0, v1);
                else
                    *(__half2*)(outH + (size_t)rr * N + c) =
                        __halves2half2(__float2half_rn(v0), __float2half_rn(v1));
            }
        }
    }
}

// ---------------- Chunked local attention (half2 math, padded rows) --------
__global__ void attn_kernel(const __half* __restrict__ qkv, const __half* __restrict__ p,
                            const float* __restrict__ pbu, const float* __restrict__ pbv,
                            __half* __restrict__ o) {
    int ci = blockIdx.x, h = blockIdx.y, b = blockIdx.z;
    int s0 = max((ci - LC_) * CS_, 0);
    int s1 = (ci + 1) * CS_;
    int W = s1 - s0;
    int t0 = ci * CS_;
    int tid = threadIdx.x;                    // 256 threads

    extern __shared__ char asmem[];
    __half* Ks = (__half*)asmem;              // WMAX_*AP_
    __half* Ps = Ks + WMAX_ * AP_;
    __half* QU = Ps + WMAX_ * AP_;            // 16*AP_
    __half* QV = QU + 16 * AP_;
    __half* Vs = QV + 16 * AP_;               // WMAX_*AP_ halves
    float*  SC = (float*)(Vs + WMAX_ * AP_);  // 16*WMAX_

    for (int idx = tid; idx < W * 64; idx += 256) {
        int s = idx >> 6, d = idx & 63;
        size_t gi = (size_t)((b * T_) + s0 + s) * QKVN_ + h * DK_ + d;
        Ks[s * AP_ + d] = qkv[gi + D_];
        Vs[s * AP_ + d] = qkv[gi + 2 * D_];
        Ps[s * AP_ + d] = p[(size_t)(s0 + s) * PALLN_ + h * DK_ + d];
    }
    for (int idx = tid; idx < 16 * 64; idx += 256) {
        int qi = idx >> 6, d = idx & 63;
        float qv_ = __half2float(qkv[(size_t)((b * T_) + t0 + qi) * QKVN_ + h * DK_ + d]);
        QU[qi * AP_ + d] = __float2half(qv_ + pbu[h * DK_ + d]);
        QV[qi * AP_ + d] = __float2half(qv_ + pbv[h * DK_ + d]);
    }
    __syncthreads();

    const float scale = 0.125f;
    int Wh = W >> 1;
    for (int it = tid; it < 8 * Wh; it += 256) {
        int qi = (it / Wh) * 2, s = (it % Wh) * 2;
        const __half2* qu0 = (const __half2*)(QU + qi * AP_);
        const __half2* qu1 = (const __half2*)(QU + (qi + 1) * AP_);
        const __half2* qv0 = (const __half2*)(QV + qi * AP_);
        const __half2* qv1 = (const __half2*)(QV + (qi + 1) * AP_);
        const __half2* k0p = (const __half2*)(Ks + s * AP_);
        const __half2* k1p = (const __half2*)(Ks + (s + 1) * AP_);
        const __half2* p0p = (const __half2*)(Ps + s * AP_);
        const __half2* p1p = (const __half2*)(Ps + (s + 1) * AP_);
        float a00 = 0, a01 = 0, a10 = 0, a11 = 0;
        #pragma unroll
        for (int blk = 0; blk < 8; blk++) {
            __half2 h00 = __float2half2_rn(0.0f), h01 = h00, h10 = h00, h11 = h00;
            #pragma unroll
            for (int j = 0; j < 4; j++) {
                int d2 = blk * 4 + j;
                __half2 u0 = qu0[d2], u1 = qu1[d2], w0 = qv0[d2], w1 = qv1[d2];
                __half2 kk0 = k0p[d2], kk1 = k1p[d2], pp0 = p0p[d2], pp1 = p1p[d2];
                h00 = __hfma2(u0, kk0, h00); h00 = __hfma2(w0, pp0, h00);
                h01 = __hfma2(u0, kk1, h01); h01 = __hfma2(w0, pp1, h01);
                h10 = __hfma2(u1, kk0, h10); h10 = __hfma2(w1, pp0, h10);
                h11 = __hfma2(u1, kk1, h11); h11 = __hfma2(w1, pp1, h11);
            }
            float2 f;
            f = __half22float2(h00); a00 += f.x + f.y;
            f = __half22float2(h01); a01 += f.x + f.y;
            f = __half22float2(h10); a10 += f.x + f.y;
            f = __half22float2(h11); a11 += f.x + f.y;
        }
        SC[qi * WMAX_ + s]           = a00 * scale;
        SC[qi * WMAX_ + s + 1]       = a01 * scale;
        SC[(qi + 1) * WMAX_ + s]     = a10 * scale;
        SC[(qi + 1) * WMAX_ + s + 1] = a11 * scale;
    }
    __syncthreads();

    int warp = tid >> 5, lane = tid & 31;
    for (int qi = warp; qi < 16; qi += 8) {
        float m = -1e30f;
        for (int s = lane; s < W; s += 32) m = fmaxf(m, SC[qi * WMAX_ + s]);
        #pragma unroll
        for (int off = 16; off; off >>= 1) m = fmaxf(m, __shfl_xor_sync(0xffffffffu, m, off));
        float sum = 0.0f;
        for (int s = lane; s < W; s += 32) {
            float e = expf(SC[qi * WMAX_ + s] - m);
            SC[qi * WMAX_ + s] = e;
            sum += e;
        }
        #pragma unroll
        for (int off = 16; off; off >>= 1) sum += __shfl_xor_sync(0xffffffffu, sum, off);
        float inv = 1.0f / sum;
        for (int s = lane; s < W; s += 32) SC[qi * WMAX_ + s] *= inv;
    }
    __syncthreads();

    {
        int it = tid;                       // 8 warps x 32 lanes
        int qi = (it >> 5) * 2, d2 = it & 31;
        float a00 = 0, a01 = 0, a10 = 0, a11 = 0;
        const __half2* V2 = (const __half2*)Vs;
        for (int s = 0; s < W; s++) {
            float2 fv = __half22float2(V2[s * (AP_ / 2) + d2]);
            float c0 = SC[qi * WMAX_ + s];
            float c1 = SC[(qi + 1) * WMAX_ + s];
            a00 += c0 * fv.x; a01 += c0 * fv.y;
            a10 += c1 * fv.x; a11 += c1 * fv.y;
        }
        int d = d2 * 2;
        size_t o0 = (size_t)((b * T_) + t0 + qi) * D_ + h * DK_ + d;
        *(__half2*)(o + o0)      = __halves2half2(__float2half_rn(a00), __float2half_rn(a01));
        *(__half2*)(o + o0 + D_) = __halves2half2(__float2half_rn(a10), __float2half_rn(a11));
    }
}

static const int ATTN_SMEM = (WMAX_*3 + 32) * AP_ * 2 + 16 * WMAX_ * 4;  // 41024
static const int GEMM_SMEM = NSTG * STAGE_BYTES;   // 98304

extern "C" void kernel_launch(void* const* d_in, const int* in_sizes, int n_in,
                              void* d_out, int out_size) {
    (void)in_sizes; (void)n_in; (void)out_size;
    const float* xs    = (const float*)d_in[0];
    const float* pos   = (const float*)d_in[1];
    // d_in[2] = mask: unused (window computed analytically)
    const float* Wq    = (const float*)d_in[3];
    const float* bq    = (const float*)d_in[4];
    const float* Wk    = (const float*)d_in[5];
    const float* bk    = (const float*)d_in[6];
    const float* Wv    = (const float*)d_in[7];
    const float* bv    = (const float*)d_in[8];
    const float* Wo    = (const float*)d_in[9];
    const float* bo    = (const float*)d_in[10];
    const float* Wp    = (const float*)d_in[11];
    const float* pbu   = (const float*)d_in[12];
    const float* pbv   = (const float*)d_in[13];
    const float* ln1s  = (const float*)d_in[14];
    const float* ln1b  = (const float*)d_in[15];
    const float* ln2s  = (const float*)d_in[16];
    const float* ln2b  = (const float*)d_in[17];
    const float* W1    = (const float*)d_in[18];
    const float* b1    = (const float*)d_in[19];
    const float* W2    = (const float*)d_in[20];
    const float* b2    = (const float*)d_in[21];
    const float* lnfs  = (const float*)d_in[22];
    const float* lnfb  = (const float*)d_in[23];

    cudaFuncSetAttribute(attn_kernel, cudaFuncAttributeMaxDynamicSharedMemorySize, ATTN_SMEM);
    cudaFuncSetAttribute(gemm_f16a,   cudaFuncAttributeMaxDynamicSharedMemorySize, GEMM_SMEM);

    void* a;
    #define SYM(p, s) cudaGetSymbolAddress(&a, s); auto* p = (decltype(&s[0]))a;
    SYM(px, g_x)  SYM(phh, g_hh)  SYM(pqkvh, g_qkvh)  SYM(poh, g_oh)  SYM(pffh, g_ffh)
    SYM(ppall, g_pall)  SYM(pposh, g_posh)  SYM(pbqkv, g_bqkv)
    SYM(pwqkvh, g_wqkvh)
    SYM(pwoh, g_woh)
    SYM(pwph, g_wph)
    SYM(pw1h, g_w1h)
    SYM(pw2h, g_w2h)
    #undef SYM

    const int M = B_ * T_;  // 4096
    const size_t DD = (size_t)D_ * D_;          // 262144
    const size_t QKVLS = (size_t)QKVN_ * D_;    // 786432
    dim3 wtb(32, 8);

    scale_kernel<<<(B_*T_*D_) / 256, 256>>>(xs, sqrtf((float)D_));
    posconv_kernel<<<(T_*D_) / 256, 256>>>(pos);
    bcat_kernel<<<(L_*QKVN_) / 256, 256>>>(bq, bk, bv);
    wtransqkv_kernel<<<dim3(16, 16, 3 * L_), wtb>>>(Wq, Wk, Wv, pwqkvh);
    wtrans_kernel<<<dim3(D_/32, D_/32, L_), wtb>>>(Wo, pwoh, D_, D_, DD, DD);
    wtrans_kernel<<<dim3(D_/32,  D_/32,  L_), wtb>>>(Wp, pwph, D_,  D_,  DD, DD);
    wtrans_kernel<<<dim3(FF_/32, D_/32,  L_), wtb>>>(W1, pw1h, D_,  FF_, (size_t)D_*FF_, (size_t)D_*FF_);
    wtrans_kernel<<<dim3(D_/32,  FF_/32, L_), wtb>>>(W2, pw2h, FF_, D_,  (size_t)FF_*D_, (size_t)FF_*D_);
    // p_all = pos_emb @ Wp (all layers, fp16 out)
    gemm_f16a<<<dim3(PALLN_/128, T_/128), 256, GEMM_SMEM>>>(pposh, pwph,
        nullptr, nullptr, nullptr, ppall, PALLN_, D_, 0);

    for (int l = 0; l < L_; l++) {
        size_t wdf = (size_t)l * D_ * FF_;

        // h = LN1(x) -> fp16
        ln_h16_kernel<<<M / 8, 256>>>(px, phh, ln1s + l*D_, ln1b + l*D_);

        // qkv = h @ [Wq|Wk|Wv] + b -> fp16
        gemm_f16a<<<dim3(QKVN_/128, M/128), 256, GEMM_SMEM>>>(phh,
            pwqkvh + l * QKVLS, pbqkv + l * QKVN_, nullptr, nullptr, pqkvh, QKVN_, D_, 0);

        // attention -> o fp16
        attn_kernel<<<dim3(NCHUNK_, H_, B_), 256, ATTN_SMEM>>>(
            pqkvh, ppall + l * D_, pbu + l * H_ * DK_, pbv + l * H_ * DK_, poh);

        // x = x + o @ Wo + bo
        gemm_f16a<<<dim3(D_/128, M/128), 256, GEMM_SMEM>>>(poh,
            pwoh + l * DD, bo + l*D_, px, px, nullptr, D_, D_, 0);

        // h2 = LN2(x) -> fp16
        ln_h16_kernel<<<M / 8, 256>>>(px, phh, ln2s + l*D_, ln2b + l*D_);

        // ff = relu(h2 @ W1 + b1) -> fp16
        gemm_f16a<<<dim3(FF_/128, M/128), 256, GEMM_SMEM>>>(phh,
            pw1h + wdf, b1 + l*FF_, nullptr, nullptr, pffh, FF_, D_, 1);

        // x = x + ff @ W2 + b2
        gemm_f16a<<<dim3(D_/128, M/128), 256, GEMM_SMEM>>>(pffh,
            pw2h + wdf, b2 + l*D_, px, px, nullptr, D_, FF_, 0);
    }

    // out = LNf(x)  (fp32)
    ln_f32_kernel<<<M / 8, 256>>>(px, (float*)d_out, lnfs, lnfb);
}